// round 8
// baseline (speedup 1.0000x reference)
#include <cuda_runtime.h>
#include <math.h>
#include <stdint.h>

#define N_NODES 20000
#define NTOT    40000
#define MPAD2   40192
#define MT2     314
#define N_EDGES 640000
#define FIN_DIM 256
#define HDIM 512
#define TOPK 1000
#define SELN 4096

// ---------------- scratch (static device memory; no allocations) ----------------
__device__ float g_agg[(size_t)MPAD2 * HDIM];
__device__ float g_tmp[(size_t)MPAD2 * HDIM];
__device__ float g_act[(size_t)MPAD2 * HDIM];
__device__ float g_o[NTOT * 2];
__device__ float g_dist[N_NODES];
__device__ float g_sel[SELN];
__device__ float g_top[TOPK];
__device__ int   g_selcnt;
__device__ int   g_thrbin;
__device__ int   g_cnt[NTOT];
__device__ int   g_rowptr[2 * (N_NODES + 1)];
__device__ int   g_cursor[NTOT];
__device__ int   g_esrc[2 * N_EDGES];

// ---------------- helpers ----------------
__device__ __forceinline__ uint32_t packbf(float lo_e, float hi_o) {
    uint32_t r;
    asm("cvt.rn.bf16x2.f32 %0, %1, %2;" : "=r"(r) : "f"(hi_o), "f"(lo_e));
    return r;
}
__device__ __forceinline__ void split2(float v0, float v1, uint32_t& h, uint32_t& l) {
    h = packbf(v0, v1);
    float h0 = __uint_as_float(h << 16);
    float h1 = __uint_as_float(h & 0xffff0000u);
    l = packbf(v0 - h0, v1 - h1);
}
__device__ __forceinline__ void mma_bf16(float* c, const uint32_t* a, const uint32_t* b) {
    asm volatile(
        "mma.sync.aligned.m16n8k16.row.col.f32.bf16.bf16.f32 "
        "{%0,%1,%2,%3}, {%4,%5,%6,%7}, {%8,%9}, {%0,%1,%2,%3};"
        : "+f"(c[0]), "+f"(c[1]), "+f"(c[2]), "+f"(c[3])
        : "r"(a[0]), "r"(a[1]), "r"(a[2]), "r"(a[3]), "r"(b[0]), "r"(b[1]));
}

// ---------------- CSR build (both graphs, batched) ----------------
__global__ void k_zero_cnt() {
    int i = blockIdx.x * blockDim.x + threadIdx.x;
    if (i < NTOT) g_cnt[i] = 0;
}
__global__ void k_hist2(const int* __restrict__ dst1, const int* __restrict__ dst2) {
    int e = blockIdx.x * blockDim.x + threadIdx.x;
    if (e >= 2 * N_EDGES) return;
    int gph = e >= N_EDGES;
    int le = e - gph * N_EDGES;
    int d = (gph ? dst2 : dst1)[le];
    atomicAdd(&g_cnt[gph * N_NODES + d], 1);
}
__global__ void k_scan2() {
    __shared__ int s[1024];
    __shared__ int carry;
    int t = threadIdx.x;
    int gph = blockIdx.x;
    const int cbase = gph * N_NODES;
    const int rbase = gph * (N_NODES + 1);
    if (t == 0) carry = 0;
    __syncthreads();
    for (int base = 0; base < N_NODES; base += 1024) {
        int v = (base + t < N_NODES) ? g_cnt[cbase + base + t] : 0;
        s[t] = v;
        __syncthreads();
        for (int off = 1; off < 1024; off <<= 1) {
            int a = (t >= off) ? s[t - off] : 0;
            __syncthreads();
            s[t] += a;
            __syncthreads();
        }
        int exc = s[t] - v + carry;
        if (base + t < N_NODES) {
            g_rowptr[rbase + base + t] = exc;
            g_cursor[cbase + base + t] = exc;
        }
        __syncthreads();
        if (t == 0) carry = carry + s[1023];
        __syncthreads();
    }
    if (t == 0) g_rowptr[rbase + N_NODES] = carry;
}
__global__ void k_fill2(const int* __restrict__ src1, const int* __restrict__ dst1,
                        const int* __restrict__ src2, const int* __restrict__ dst2) {
    int e = blockIdx.x * blockDim.x + threadIdx.x;
    if (e >= 2 * N_EDGES) return;
    int gph = e >= N_EDGES;
    int le = e - gph * N_EDGES;
    int d = (gph ? dst2 : dst1)[le];
    int sv = (gph ? src2 : src1)[le];
    int pos = atomicAdd(&g_cursor[gph * N_NODES + d], 1);
    g_esrc[gph * N_EDGES + pos] = sv;
}

// ---------------- aggregation: out[node] = x[node] + sum_j x[j] -------------
template <int F>
__global__ void k_agg2(const float* __restrict__ xa, const float* __restrict__ xb,
                       float* __restrict__ out) {
    const int FV = F / 4;
    const int NPB = 512 / FV;
    int t = threadIdx.x;
    int node = blockIdx.x * NPB + t / FV;
    int tf = t % FV;
    if (node >= NTOT) return;
    int gph = node >= N_NODES;
    int local = node - gph * N_NODES;
    const float4* x4 = (const float4*)(gph ? xb : xa);
    float4 acc = x4[(size_t)local * FV + tf];
    int beg = g_rowptr[gph * (N_NODES + 1) + local];
    int end = g_rowptr[gph * (N_NODES + 1) + local + 1];
    const int* ep = g_esrc + gph * N_EDGES;
    int e = beg;
    for (; e + 1 < end; e += 2) {
        int i0 = __ldg(&ep[e]);
        int i1 = __ldg(&ep[e + 1]);
        float4 v0 = x4[(size_t)i0 * FV + tf];
        float4 v1 = x4[(size_t)i1 * FV + tf];
        acc.x += v0.x + v1.x; acc.y += v0.y + v1.y;
        acc.z += v0.z + v1.z; acc.w += v0.w + v1.w;
    }
    if (e < end) {
        int i0 = __ldg(&ep[e]);
        float4 v0 = x4[(size_t)i0 * FV + tf];
        acc.x += v0.x; acc.y += v0.y; acc.z += v0.z; acc.w += v0.w;
    }
    ((float4*)out)[(size_t)node * FV + tf] = acc;
}

// ---------------- 3x-bf16 mma.sync GEMM: C[MPAD2,512] = relu(A @ W + b) ------
// Block 128x128x16, 256 thr, 8 warps (4x2), warp tile 32x64.
// smem A: [qm 0..3][m 0..127][4 words: h(q), l(q), h(q+4), l(q+4)], stride 130 rows
// smem B: [k2 0..7][n 0..139][2 words: h, l]
#define AQS  130                    // A row-stride per qm (in 4-word units)
#define ABUF (4 * AQS * 4)          // 2080 words
#define BSS  140                    // B n-stride
#define BBUF (8 * BSS * 2)          // 2240 words
#define STGW (ABUF + BBUF)          // 4320 words per stage

__global__ void __launch_bounds__(256)
k_gemm_mma(const float* __restrict__ A, const float* __restrict__ W,
           const float* __restrict__ bias, float* __restrict__ C, int K) {
    __shared__ uint32_t S[2][STGW];
    int t = threadIdx.x, lane = t & 31, wid = t >> 5;
    int warp_m = wid >> 1, warp_n = wid & 1;
    int rowBase = blockIdx.y * 128;
    int colBase = blockIdx.x * 128;

    float acc[2][8][4];
#pragma unroll
    for (int i = 0; i < 2; i++)
#pragma unroll
        for (int j = 0; j < 8; j++)
#pragma unroll
            for (int q = 0; q < 4; q++) acc[i][j][q] = 0.f;

    int a_row = t >> 1;
    int a_half = t & 1;
    int b_k2 = t >> 5;
    int b_n0 = lane * 4;

    const float* Ap = A + (size_t)(rowBase + a_row) * K + a_half * 8;
    const float* Bp0 = W + (size_t)(2 * b_k2) * HDIM + colBase + b_n0;
    const float* Bp1 = Bp0 + HDIM;

    const int nk = K >> 4;
    float4 ra0, ra1, rb0, rb1;

    ra0 = *(const float4*)(Ap);
    ra1 = *(const float4*)(Ap + 4);
    rb0 = *(const float4*)(Bp0);
    rb1 = *(const float4*)(Bp1);

    for (int s = 0; s < nk; s++) {
        int buf = s & 1;
        uint32_t* Aw = S[buf];
        uint32_t* Bw = S[buf] + ABUF;
        // convert + store
        {
            float av[8] = {ra0.x, ra0.y, ra0.z, ra0.w, ra1.x, ra1.y, ra1.z, ra1.w};
#pragma unroll
            for (int i = 0; i < 4; i++) {
                uint32_t h, l;
                split2(av[2 * i], av[2 * i + 1], h, l);
                int idx = ((i * AQS + a_row) << 2) + (a_half << 1);
                *(uint2*)&Aw[idx] = make_uint2(h, l);
            }
            uint4 hh, ll;
            split2(rb0.x, rb1.x, hh.x, ll.x);
            split2(rb0.y, rb1.y, hh.y, ll.y);
            split2(rb0.z, rb1.z, hh.z, ll.z);
            split2(rb0.w, rb1.w, hh.w, ll.w);
            int base = (b_k2 * BSS + b_n0) * 2;
            *(uint4*)&Bw[base]     = make_uint4(hh.x, ll.x, hh.y, ll.y);
            *(uint4*)&Bw[base + 4] = make_uint4(hh.z, ll.z, hh.w, ll.w);
        }
        __syncthreads();
        // prefetch next stage
        if (s + 1 < nk) {
            const float* Ap2 = Ap + (s + 1) * 16;
            const float* Bp2 = Bp0 + (size_t)(s + 1) * 16 * HDIM;
            ra0 = *(const float4*)(Ap2);
            ra1 = *(const float4*)(Ap2 + 4);
            rb0 = *(const float4*)(Bp2);
            rb1 = *(const float4*)(Bp2 + HDIM);
        }
        // compute one k16 step
        {
            int g = lane >> 2, q = lane & 3;
            uint32_t bhf[8][2], blf[8][2];
#pragma unroll
            for (int nt = 0; nt < 8; nt++) {
                int n = warp_n * 64 + nt * 8 + g;
                uint2 p0 = *(const uint2*)&Bw[(q * BSS + n) * 2];
                uint2 p1 = *(const uint2*)&Bw[((q + 4) * BSS + n) * 2];
                bhf[nt][0] = p0.x; blf[nt][0] = p0.y;
                bhf[nt][1] = p1.x; blf[nt][1] = p1.y;
            }
#pragma unroll
            for (int mt = 0; mt < 2; mt++) {
                int m = warp_m * 32 + mt * 16 + g;
                uint4 v0 = *(const uint4*)&Aw[(q * AQS + m) << 2];
                uint4 v1 = *(const uint4*)&Aw[(q * AQS + m + 8) << 2];
                uint32_t ahf[4] = {v0.x, v1.x, v0.z, v1.z};
                uint32_t alf[4] = {v0.y, v1.y, v0.w, v1.w};
#pragma unroll
                for (int nt = 0; nt < 8; nt++) {
                    mma_bf16(acc[mt][nt], ahf, bhf[nt]);
                    mma_bf16(acc[mt][nt], alf, bhf[nt]);
                    mma_bf16(acc[mt][nt], ahf, blf[nt]);
                }
            }
        }
        __syncthreads();
    }

    int g = lane >> 2;
    int cq = (lane & 3) * 2;
#pragma unroll
    for (int mt = 0; mt < 2; mt++) {
        int row = rowBase + warp_m * 32 + mt * 16 + g;
#pragma unroll
        for (int nt = 0; nt < 8; nt++) {
            int col = colBase + warp_n * 64 + nt * 8 + cq;
            float b0 = bias[col], b1 = bias[col + 1];
            float2 o0, o1;
            o0.x = fmaxf(acc[mt][nt][0] + b0, 0.f);
            o0.y = fmaxf(acc[mt][nt][1] + b1, 0.f);
            o1.x = fmaxf(acc[mt][nt][2] + b0, 0.f);
            o1.y = fmaxf(acc[mt][nt][3] + b1, 0.f);
            *(float2*)&C[(size_t)row * HDIM + col] = o0;
            *(float2*)&C[(size_t)(row + 8) * HDIM + col] = o1;
        }
    }
}

// ---------------- final linear [NTOT,512] @ [512,2] ----------------
__global__ void k_lin(const float* __restrict__ act, const float* __restrict__ w,
                      const float* __restrict__ b, float* __restrict__ o) {
    int warp = (blockIdx.x * blockDim.x + threadIdx.x) >> 5;
    int lane = threadIdx.x & 31;
    if (warp >= NTOT) return;
    float a0 = 0.f, a1 = 0.f;
    for (int k = lane; k < HDIM; k += 32) {
        float v = act[(size_t)warp * HDIM + k];
        a0 += v * w[k * 2];
        a1 += v * w[k * 2 + 1];
    }
#pragma unroll
    for (int off = 16; off; off >>= 1) {
        a0 += __shfl_down_sync(0xffffffffu, a0, off);
        a1 += __shfl_down_sync(0xffffffffu, a1, off);
    }
    if (lane == 0) {
        o[warp * 2]     = a0 + b[0];
        o[warp * 2 + 1] = a1 + b[1];
    }
}

// ---------------- pairwise distance ----------------
__global__ void k_dist() {
    int i = blockIdx.x * blockDim.x + threadIdx.x;
    if (i >= N_NODES) return;
    float dx = g_o[i * 2]     - g_o[(i + N_NODES) * 2]     + 1e-6f;
    float dy = g_o[i * 2 + 1] - g_o[(i + N_NODES) * 2 + 1] + 1e-6f;
    g_dist[i] = sqrtf(dx * dx + dy * dy);
}

// ---------------- top-k select: histogram threshold ----------------
__global__ void k_selhist() {
    __shared__ int hist[2048];
    int t = threadIdx.x;
    hist[t] = 0; hist[t + 1024] = 0;
    for (int i = t; i < SELN; i += 1024) g_sel[i] = -INFINITY;
    if (t == 0) g_selcnt = 0;
    __syncthreads();
    for (int i = t; i < N_NODES; i += 1024) {
        uint32_t bits = __float_as_uint(g_dist[i]);
        atomicAdd(&hist[bits >> 21], 1);
    }
    __syncthreads();
    if (t == 0) {
        int cum = 0, thr = 0;
        for (int b = 2047; b >= 0; b--) {
            cum += hist[b];
            if (cum >= TOPK) { thr = b; break; }
        }
        g_thrbin = thr;
    }
}
__global__ void k_compact() {
    int i = blockIdx.x * blockDim.x + threadIdx.x;
    if (i >= N_NODES) return;
    float d = g_dist[i];
    if ((int)(__float_as_uint(d) >> 21) >= g_thrbin) {
        int pos = atomicAdd(&g_selcnt, 1);
        if (pos < SELN) g_sel[pos] = d;
    }
}
__global__ void k_sortsel() {
    __shared__ float s[SELN];
    int t = threadIdx.x;
    for (int i = t; i < SELN; i += 1024) s[i] = g_sel[i];
    __syncthreads();
    for (int k = 2; k <= SELN; k <<= 1) {
        for (int j = k >> 1; j > 0; j >>= 1) {
            for (int i = t; i < SELN; i += 1024) {
                int ixj = i ^ j;
                if (ixj > i) {
                    bool dsc = (i & k) == 0;
                    float a = s[i], c = s[ixj];
                    bool sw = dsc ? (a < c) : (a > c);
                    if (sw) { s[i] = c; s[ixj] = a; }
                }
            }
            __syncthreads();
        }
    }
    for (int i = t; i < TOPK; i += 1024) g_top[i] = s[i];
}

// ---------------- head MLP ----------------
__global__ void k_mlp(const float* __restrict__ fc1w, const float* __restrict__ fc1b,
                      const float* __restrict__ ln1g, const float* __restrict__ ln1b,
                      const float* __restrict__ fc2w, const float* __restrict__ fc2b,
                      const float* __restrict__ ln2g, const float* __restrict__ ln2b,
                      const float* __restrict__ fc3w, const float* __restrict__ fc3b,
                      float* __restrict__ out) {
    __shared__ float vals[TOPK];
    __shared__ float h1[128];
    __shared__ float part[4][128];
    __shared__ float h2[512];
    __shared__ float red[512];
    int t = threadIdx.x;
    for (int i = t; i < TOPK; i += 512) vals[i] = g_top[i];
    __syncthreads();
    {
        int j = t & 127, c = t >> 7;
        float acc = 0.f;
        for (int i = c * 250; i < (c + 1) * 250; i++) acc += vals[i] * fc1w[i * 128 + j];
        part[c][j] = acc;
    }
    __syncthreads();
    if (t < 128) h1[t] = part[0][t] + part[1][t] + part[2][t] + part[3][t] + fc1b[t];
    __syncthreads();
    red[t] = (t < 128) ? h1[t] : 0.f;
    __syncthreads();
    for (int off = 256; off; off >>= 1) { if (t < off) red[t] += red[t + off]; __syncthreads(); }
    float mean1 = red[0] / 128.f;
    __syncthreads();
    red[t] = (t < 128) ? (h1[t] - mean1) * (h1[t] - mean1) : 0.f;
    __syncthreads();
    for (int off = 256; off; off >>= 1) { if (t < off) red[t] += red[t + off]; __syncthreads(); }
    float var1 = red[0] / 128.f;
    __syncthreads();
    if (t < 128) {
        float v = (h1[t] - mean1) * rsqrtf(var1 + 1e-5f) * ln1g[t] + ln1b[t];
        h1[t] = fmaxf(v, 0.f);
    }
    __syncthreads();
    {
        float acc = fc2b[t];
        for (int i = 0; i < 128; i++) acc += h1[i] * fc2w[i * 512 + t];
        h2[t] = acc;
    }
    __syncthreads();
    red[t] = h2[t];
    __syncthreads();
    for (int off = 256; off; off >>= 1) { if (t < off) red[t] += red[t + off]; __syncthreads(); }
    float mean2 = red[0] / 512.f;
    __syncthreads();
    red[t] = (h2[t] - mean2) * (h2[t] - mean2);
    __syncthreads();
    for (int off = 256; off; off >>= 1) { if (t < off) red[t] += red[t + off]; __syncthreads(); }
    float var2 = red[0] / 512.f;
    __syncthreads();
    float hr = fmaxf((h2[t] - mean2) * rsqrtf(var2 + 1e-5f) * ln2g[t] + ln2b[t], 0.f);
    red[t] = hr * fc3w[t];
    __syncthreads();
    for (int off = 256; off; off >>= 1) { if (t < off) red[t] += red[t + off]; __syncthreads(); }
    if (t == 0) out[0] = 1.f / (1.f + expf(-(red[0] + fc3b[0])));
}

// ---------------- launch ----------------
extern "C" void kernel_launch(void* const* d_in, const int* in_sizes, int n_in,
                              void* d_out, int out_size) {
    const float* x1   = (const float*)d_in[0];
    const int*   ei1  = (const int*)d_in[1];
    const float* x2   = (const float*)d_in[2];
    const int*   ei2  = (const int*)d_in[3];
    const float* w11  = (const float*)d_in[4];
    const float* b11  = (const float*)d_in[5];
    const float* w12  = (const float*)d_in[6];
    const float* b12  = (const float*)d_in[7];
    const float* w21  = (const float*)d_in[8];
    const float* b21  = (const float*)d_in[9];
    const float* w22  = (const float*)d_in[10];
    const float* b22  = (const float*)d_in[11];
    const float* w31  = (const float*)d_in[12];
    const float* b31  = (const float*)d_in[13];
    const float* w32  = (const float*)d_in[14];
    const float* b32  = (const float*)d_in[15];
    const float* linw = (const float*)d_in[16];
    const float* linb = (const float*)d_in[17];
    const float* fc1w = (const float*)d_in[18];
    const float* fc1b = (const float*)d_in[19];
    const float* ln1g = (const float*)d_in[20];
    const float* ln1b = (const float*)d_in[21];
    const float* fc2w = (const float*)d_in[22];
    const float* fc2b = (const float*)d_in[23];
    const float* ln2g = (const float*)d_in[24];
    const float* ln2b = (const float*)d_in[25];
    const float* fc3w = (const float*)d_in[26];
    const float* fc3b = (const float*)d_in[27];
    float* out = (float*)d_out;

    const int* src1 = ei1;
    const int* dst1 = ei1 + N_EDGES;
    const int* src2 = ei2;
    const int* dst2 = ei2 + N_EDGES;

    float *p_agg, *p_tmp, *p_act, *p_o;
    cudaGetSymbolAddress((void**)&p_agg, g_agg);
    cudaGetSymbolAddress((void**)&p_tmp, g_tmp);
    cudaGetSymbolAddress((void**)&p_act, g_act);
    cudaGetSymbolAddress((void**)&p_o, g_o);

    dim3 ggrid(HDIM / 128, MT2);
    const int E2B = (2 * N_EDGES + 255) / 256;
    const int N2B = (NTOT + 255) / 256;
    const int NB = (N_NODES + 255) / 256;

    // batched CSR for both graphs
    k_zero_cnt<<<N2B, 256>>>();
    k_hist2<<<E2B, 256>>>(dst1, dst2);
    k_scan2<<<2, 1024>>>();
    k_fill2<<<E2B, 256>>>(src1, dst1, src2, dst2);

    // layer 1 (FIN=256 -> H)
    k_agg2<FIN_DIM><<<(NTOT + 7) / 8, 512>>>(x1, x2, p_agg);
    k_gemm_mma<<<ggrid, 256>>>(p_agg, w11, b11, p_tmp, FIN_DIM);
    k_gemm_mma<<<ggrid, 256>>>(p_tmp, w12, b12, p_act, HDIM);
    // layer 2
    k_agg2<HDIM><<<(NTOT + 3) / 4, 512>>>(p_act, p_act + (size_t)N_NODES * HDIM, p_agg);
    k_gemm_mma<<<ggrid, 256>>>(p_agg, w21, b21, p_tmp, HDIM);
    k_gemm_mma<<<ggrid, 256>>>(p_tmp, w22, b22, p_act, HDIM);
    // layer 3
    k_agg2<HDIM><<<(NTOT + 3) / 4, 512>>>(p_act, p_act + (size_t)N_NODES * HDIM, p_agg);
    k_gemm_mma<<<ggrid, 256>>>(p_agg, w31, b31, p_tmp, HDIM);
    k_gemm_mma<<<ggrid, 256>>>(p_tmp, w32, b32, p_act, HDIM);
    // lin head -> [NTOT,2]
    k_lin<<<(NTOT * 32 + 255) / 256, 256>>>(p_act, linw, linb, p_o);

    k_dist<<<NB, 256>>>();
    k_selhist<<<1, 1024>>>();
    k_compact<<<NB, 256>>>();
    k_sortsel<<<1, 1024>>>();
    k_mlp<<<1, 512>>>(fc1w, fc1b, ln1g, ln1b, fc2w, fc2b, ln2g, ln2b, fc3w, fc3b, out);
}

// round 9
// speedup vs baseline: 1.3128x; 1.3128x over previous
#include <cuda_runtime.h>
#include <math.h>
#include <stdint.h>

#define N_NODES 20000
#define NTOT    40000
#define MPAD2   40192
#define MT2     314
#define N_EDGES 640000
#define FIN_DIM 256
#define HDIM 512
#define TOPK 1000
#define SELN 4096

// ---------------- scratch (static device memory; no allocations) ----------------
__device__ float g_agg[(size_t)MPAD2 * HDIM];
__device__ float g_tmp[(size_t)MPAD2 * HDIM];
__device__ float g_act[(size_t)MPAD2 * HDIM];
__device__ float g_o[NTOT * 2];
__device__ float g_dist[N_NODES];
__device__ float g_sel[SELN];
__device__ float g_top[TOPK];
__device__ int   g_selcnt;
__device__ int   g_thrbin;
__device__ int   g_cnt[NTOT];
__device__ int   g_rowptr[2 * (N_NODES + 1)];
__device__ int   g_cursor[NTOT];
__device__ int   g_esrc[2 * N_EDGES];

// ---------------- helpers ----------------
__device__ __forceinline__ uint32_t packbf(float lo_e, float hi_o) {
    uint32_t r;
    asm("cvt.rn.bf16x2.f32 %0, %1, %2;" : "=r"(r) : "f"(hi_o), "f"(lo_e));
    return r;
}
__device__ __forceinline__ void split2(float v0, float v1, uint32_t& h, uint32_t& l) {
    h = packbf(v0, v1);
    float h0 = __uint_as_float(h << 16);
    float h1 = __uint_as_float(h & 0xffff0000u);
    l = packbf(v0 - h0, v1 - h1);
}
__device__ __forceinline__ void mma_bf16(float* c, const uint32_t* a, const uint32_t* b) {
    asm volatile(
        "mma.sync.aligned.m16n8k16.row.col.f32.bf16.bf16.f32 "
        "{%0,%1,%2,%3}, {%4,%5,%6,%7}, {%8,%9}, {%0,%1,%2,%3};"
        : "+f"(c[0]), "+f"(c[1]), "+f"(c[2]), "+f"(c[3])
        : "r"(a[0]), "r"(a[1]), "r"(a[2]), "r"(a[3]), "r"(b[0]), "r"(b[1]));
}

// ---------------- CSR build (both graphs, batched) ----------------
__global__ void k_zero_cnt() {
    int i = blockIdx.x * blockDim.x + threadIdx.x;
    if (i < NTOT) g_cnt[i] = 0;
}
__global__ void k_hist2(const int* __restrict__ dst1, const int* __restrict__ dst2) {
    int e = blockIdx.x * blockDim.x + threadIdx.x;
    if (e >= 2 * N_EDGES) return;
    int gph = e >= N_EDGES;
    int le = e - gph * N_EDGES;
    int d = (gph ? dst2 : dst1)[le];
    atomicAdd(&g_cnt[gph * N_NODES + d], 1);
}
__global__ void k_scan2() {
    __shared__ int s[1024];
    __shared__ int carry;
    int t = threadIdx.x;
    int gph = blockIdx.x;
    const int cbase = gph * N_NODES;
    const int rbase = gph * (N_NODES + 1);
    if (t == 0) carry = 0;
    __syncthreads();
    for (int base = 0; base < N_NODES; base += 1024) {
        int v = (base + t < N_NODES) ? g_cnt[cbase + base + t] : 0;
        s[t] = v;
        __syncthreads();
        for (int off = 1; off < 1024; off <<= 1) {
            int a = (t >= off) ? s[t - off] : 0;
            __syncthreads();
            s[t] += a;
            __syncthreads();
        }
        int exc = s[t] - v + carry;
        if (base + t < N_NODES) {
            g_rowptr[rbase + base + t] = exc;
            g_cursor[cbase + base + t] = exc;
        }
        __syncthreads();
        if (t == 0) carry = carry + s[1023];
        __syncthreads();
    }
    if (t == 0) g_rowptr[rbase + N_NODES] = carry;
}
__global__ void k_fill2(const int* __restrict__ src1, const int* __restrict__ dst1,
                        const int* __restrict__ src2, const int* __restrict__ dst2) {
    int e = blockIdx.x * blockDim.x + threadIdx.x;
    if (e >= 2 * N_EDGES) return;
    int gph = e >= N_EDGES;
    int le = e - gph * N_EDGES;
    int d = (gph ? dst2 : dst1)[le];
    int sv = (gph ? src2 : src1)[le];
    int pos = atomicAdd(&g_cursor[gph * N_NODES + d], 1);
    g_esrc[gph * N_EDGES + pos] = sv;
}

// ---------------- aggregation: out[node] = x[node] + sum_j x[j] -------------
template <int F>
__global__ void k_agg2(const float* __restrict__ xa, const float* __restrict__ xb,
                       float* __restrict__ out) {
    const int FV = F / 4;
    const int NPB = 512 / FV;
    int t = threadIdx.x;
    int node = blockIdx.x * NPB + t / FV;
    int tf = t % FV;
    if (node >= NTOT) return;
    int gph = node >= N_NODES;
    int local = node - gph * N_NODES;
    const float4* x4 = (const float4*)(gph ? xb : xa);
    float4 acc = x4[(size_t)local * FV + tf];
    int beg = g_rowptr[gph * (N_NODES + 1) + local];
    int end = g_rowptr[gph * (N_NODES + 1) + local + 1];
    const int* ep = g_esrc + gph * N_EDGES;
    int e = beg;
    for (; e + 1 < end; e += 2) {
        int i0 = __ldg(&ep[e]);
        int i1 = __ldg(&ep[e + 1]);
        float4 v0 = x4[(size_t)i0 * FV + tf];
        float4 v1 = x4[(size_t)i1 * FV + tf];
        acc.x += v0.x + v1.x; acc.y += v0.y + v1.y;
        acc.z += v0.z + v1.z; acc.w += v0.w + v1.w;
    }
    if (e < end) {
        int i0 = __ldg(&ep[e]);
        float4 v0 = x4[(size_t)i0 * FV + tf];
        acc.x += v0.x; acc.y += v0.y; acc.z += v0.z; acc.w += v0.w;
    }
    ((float4*)out)[(size_t)node * FV + tf] = acc;
}

// ---------------- 3x-bf16 mma.sync GEMM: C[MPAD2,512] = relu(A @ W + b) ------
// (R5 layout; double-buffered with ONE barrier per stage)
#define GSTRIDE 140
#define GMATW   (8 * GSTRIDE)

__global__ void __launch_bounds__(256)
k_gemm_mma(const float* __restrict__ A, const float* __restrict__ W,
           const float* __restrict__ bias, float* __restrict__ C, int K) {
    __shared__ uint32_t S[2][4][GMATW];
    int t = threadIdx.x, lane = t & 31, wid = t >> 5;
    int warp_m = wid >> 1, warp_n = wid & 1;
    int rowBase = blockIdx.y * 128;
    int colBase = blockIdx.x * 128;

    float acc[2][8][4];
#pragma unroll
    for (int i = 0; i < 2; i++)
#pragma unroll
        for (int j = 0; j < 8; j++)
#pragma unroll
            for (int q = 0; q < 4; q++) acc[i][j][q] = 0.f;

    int a_row = t >> 1;
    int a_half = t & 1;
    int b_k2 = t >> 5;
    int b_n0 = lane * 4;

    const float* Ap = A + (size_t)(rowBase + a_row) * K + a_half * 8;
    const float* Bp0 = W + (size_t)(2 * b_k2) * HDIM + colBase + b_n0;
    const float* Bp1 = Bp0 + HDIM;

    const int nk = K >> 4;
    float4 ra0, ra1, rb0, rb1;

    ra0 = *(const float4*)(Ap);
    ra1 = *(const float4*)(Ap + 4);
    rb0 = *(const float4*)(Bp0);
    rb1 = *(const float4*)(Bp1);

    for (int s = 0; s < nk; s++) {
        int buf = s & 1;
        uint32_t* Ah = S[buf][0];
        uint32_t* Al = S[buf][1];
        uint32_t* Bh = S[buf][2];
        uint32_t* Bl = S[buf][3];
        // convert + store into buf(s&1). Safe vs stage s-1 compute (other buffer);
        // safe vs stage s-2 compute (same buffer) because every thread passed the
        // stage s-1 barrier, which is after its stage s-2 compute.
        {
            float av[8] = {ra0.x, ra0.y, ra0.z, ra0.w, ra1.x, ra1.y, ra1.z, ra1.w};
#pragma unroll
            for (int i = 0; i < 4; i++) {
                uint32_t h, l;
                split2(av[2 * i], av[2 * i + 1], h, l);
                int idx = (a_half * 4 + i) * GSTRIDE + a_row;
                Ah[idx] = h; Al[idx] = l;
            }
            uint4 hh, ll;
            split2(rb0.x, rb1.x, hh.x, ll.x);
            split2(rb0.y, rb1.y, hh.y, ll.y);
            split2(rb0.z, rb1.z, hh.z, ll.z);
            split2(rb0.w, rb1.w, hh.w, ll.w);
            *(uint4*)&Bh[b_k2 * GSTRIDE + b_n0] = hh;
            *(uint4*)&Bl[b_k2 * GSTRIDE + b_n0] = ll;
        }
        __syncthreads();   // the ONLY barrier per stage
        // prefetch next stage
        if (s + 1 < nk) {
            const float* Ap2 = Ap + (s + 1) * 16;
            const float* Bp2 = Bp0 + (size_t)(s + 1) * 16 * HDIM;
            ra0 = *(const float4*)(Ap2);
            ra1 = *(const float4*)(Ap2 + 4);
            rb0 = *(const float4*)(Bp2);
            rb1 = *(const float4*)(Bp2 + HDIM);
        }
        // compute one k16 step
        {
            int g = lane >> 2, q = lane & 3;
            uint32_t bhf[8][2], blf[8][2];
#pragma unroll
            for (int nt = 0; nt < 8; nt++) {
                int n = warp_n * 64 + nt * 8 + g;
                bhf[nt][0] = Bh[q * GSTRIDE + n];
                bhf[nt][1] = Bh[(q + 4) * GSTRIDE + n];
                blf[nt][0] = Bl[q * GSTRIDE + n];
                blf[nt][1] = Bl[(q + 4) * GSTRIDE + n];
            }
#pragma unroll
            for (int mt = 0; mt < 2; mt++) {
                int m = warp_m * 32 + mt * 16 + g;
                uint32_t ahf[4], alf[4];
                ahf[0] = Ah[q * GSTRIDE + m];
                ahf[1] = Ah[q * GSTRIDE + m + 8];
                ahf[2] = Ah[(q + 4) * GSTRIDE + m];
                ahf[3] = Ah[(q + 4) * GSTRIDE + m + 8];
                alf[0] = Al[q * GSTRIDE + m];
                alf[1] = Al[q * GSTRIDE + m + 8];
                alf[2] = Al[(q + 4) * GSTRIDE + m];
                alf[3] = Al[(q + 4) * GSTRIDE + m + 8];
#pragma unroll
                for (int nt = 0; nt < 8; nt++) {
                    mma_bf16(acc[mt][nt], ahf, bhf[nt]);
                    mma_bf16(acc[mt][nt], alf, bhf[nt]);
                    mma_bf16(acc[mt][nt], ahf, blf[nt]);
                }
            }
        }
        // no trailing barrier (double buffering makes it redundant)
    }

    int g = lane >> 2;
    int cq = (lane & 3) * 2;
#pragma unroll
    for (int mt = 0; mt < 2; mt++) {
        int row = rowBase + warp_m * 32 + mt * 16 + g;
#pragma unroll
        for (int nt = 0; nt < 8; nt++) {
            int col = colBase + warp_n * 64 + nt * 8 + cq;
            float b0 = bias[col], b1 = bias[col + 1];
            float2 o0, o1;
            o0.x = fmaxf(acc[mt][nt][0] + b0, 0.f);
            o0.y = fmaxf(acc[mt][nt][1] + b1, 0.f);
            o1.x = fmaxf(acc[mt][nt][2] + b0, 0.f);
            o1.y = fmaxf(acc[mt][nt][3] + b1, 0.f);
            *(float2*)&C[(size_t)row * HDIM + col] = o0;
            *(float2*)&C[(size_t)(row + 8) * HDIM + col] = o1;
        }
    }
}

// ---------------- final linear [NTOT,512] @ [512,2] ----------------
__global__ void k_lin(const float* __restrict__ act, const float* __restrict__ w,
                      const float* __restrict__ b, float* __restrict__ o) {
    int warp = (blockIdx.x * blockDim.x + threadIdx.x) >> 5;
    int lane = threadIdx.x & 31;
    if (warp >= NTOT) return;
    float a0 = 0.f, a1 = 0.f;
    for (int k = lane; k < HDIM; k += 32) {
        float v = act[(size_t)warp * HDIM + k];
        a0 += v * w[k * 2];
        a1 += v * w[k * 2 + 1];
    }
#pragma unroll
    for (int off = 16; off; off >>= 1) {
        a0 += __shfl_down_sync(0xffffffffu, a0, off);
        a1 += __shfl_down_sync(0xffffffffu, a1, off);
    }
    if (lane == 0) {
        o[warp * 2]     = a0 + b[0];
        o[warp * 2 + 1] = a1 + b[1];
    }
}

// ---------------- pairwise distance ----------------
__global__ void k_dist() {
    int i = blockIdx.x * blockDim.x + threadIdx.x;
    if (i >= N_NODES) return;
    float dx = g_o[i * 2]     - g_o[(i + N_NODES) * 2]     + 1e-6f;
    float dy = g_o[i * 2 + 1] - g_o[(i + N_NODES) * 2 + 1] + 1e-6f;
    g_dist[i] = sqrtf(dx * dx + dy * dy);
}

// ---------------- top-k select: histogram threshold ----------------
__global__ void k_selhist() {
    __shared__ int hist[2048];
    int t = threadIdx.x;
    hist[t] = 0; hist[t + 1024] = 0;
    for (int i = t; i < SELN; i += 1024) g_sel[i] = -INFINITY;
    if (t == 0) g_selcnt = 0;
    __syncthreads();
    for (int i = t; i < N_NODES; i += 1024) {
        uint32_t bits = __float_as_uint(g_dist[i]);
        atomicAdd(&hist[bits >> 21], 1);
    }
    __syncthreads();
    if (t == 0) {
        int cum = 0, thr = 0;
        for (int b = 2047; b >= 0; b--) {
            cum += hist[b];
            if (cum >= TOPK) { thr = b; break; }
        }
        g_thrbin = thr;
    }
}
__global__ void k_compact() {
    int i = blockIdx.x * blockDim.x + threadIdx.x;
    if (i >= N_NODES) return;
    float d = g_dist[i];
    if ((int)(__float_as_uint(d) >> 21) >= g_thrbin) {
        int pos = atomicAdd(&g_selcnt, 1);
        if (pos < SELN) g_sel[pos] = d;
    }
}
__global__ void k_sortsel() {
    __shared__ float s[SELN];
    int t = threadIdx.x;
    for (int i = t; i < SELN; i += 1024) s[i] = g_sel[i];
    __syncthreads();
    for (int k = 2; k <= SELN; k <<= 1) {
        for (int j = k >> 1; j > 0; j >>= 1) {
            for (int i = t; i < SELN; i += 1024) {
                int ixj = i ^ j;
                if (ixj > i) {
                    bool dsc = (i & k) == 0;
                    float a = s[i], c = s[ixj];
                    bool sw = dsc ? (a < c) : (a > c);
                    if (sw) { s[i] = c; s[ixj] = a; }
                }
            }
            __syncthreads();
        }
    }
    for (int i = t; i < TOPK; i += 1024) g_top[i] = s[i];
}

// ---------------- head MLP ----------------
__global__ void k_mlp(const float* __restrict__ fc1w, const float* __restrict__ fc1b,
                      const float* __restrict__ ln1g, const float* __restrict__ ln1b,
                      const float* __restrict__ fc2w, const float* __restrict__ fc2b,
                      const float* __restrict__ ln2g, const float* __restrict__ ln2b,
                      const float* __restrict__ fc3w, const float* __restrict__ fc3b,
                      float* __restrict__ out) {
    __shared__ float vals[TOPK];
    __shared__ float h1[128];
    __shared__ float part[4][128];
    __shared__ float h2[512];
    __shared__ float red[512];
    int t = threadIdx.x;
    for (int i = t; i < TOPK; i += 512) vals[i] = g_top[i];
    __syncthreads();
    {
        int j = t & 127, c = t >> 7;
        float acc = 0.f;
        for (int i = c * 250; i < (c + 1) * 250; i++) acc += vals[i] * fc1w[i * 128 + j];
        part[c][j] = acc;
    }
    __syncthreads();
    if (t < 128) h1[t] = part[0][t] + part[1][t] + part[2][t] + part[3][t] + fc1b[t];
    __syncthreads();
    red[t] = (t < 128) ? h1[t] : 0.f;
    __syncthreads();
    for (int off = 256; off; off >>= 1) { if (t < off) red[t] += red[t + off]; __syncthreads(); }
    float mean1 = red[0] / 128.f;
    __syncthreads();
    red[t] = (t < 128) ? (h1[t] - mean1) * (h1[t] - mean1) : 0.f;
    __syncthreads();
    for (int off = 256; off; off >>= 1) { if (t < off) red[t] += red[t + off]; __syncthreads(); }
    float var1 = red[0] / 128.f;
    __syncthreads();
    if (t < 128) {
        float v = (h1[t] - mean1) * rsqrtf(var1 + 1e-5f) * ln1g[t] + ln1b[t];
        h1[t] = fmaxf(v, 0.f);
    }
    __syncthreads();
    {
        float acc = fc2b[t];
        for (int i = 0; i < 128; i++) acc += h1[i] * fc2w[i * 512 + t];
        h2[t] = acc;
    }
    __syncthreads();
    red[t] = h2[t];
    __syncthreads();
    for (int off = 256; off; off >>= 1) { if (t < off) red[t] += red[t + off]; __syncthreads(); }
    float mean2 = red[0] / 512.f;
    __syncthreads();
    red[t] = (h2[t] - mean2) * (h2[t] - mean2);
    __syncthreads();
    for (int off = 256; off; off >>= 1) { if (t < off) red[t] += red[t + off]; __syncthreads(); }
    float var2 = red[0] / 512.f;
    __syncthreads();
    float hr = fmaxf((h2[t] - mean2) * rsqrtf(var2 + 1e-5f) * ln2g[t] + ln2b[t], 0.f);
    red[t] = hr * fc3w[t];
    __syncthreads();
    for (int off = 256; off; off >>= 1) { if (t < off) red[t] += red[t + off]; __syncthreads(); }
    if (t == 0) out[0] = 1.f / (1.f + expf(-(red[0] + fc3b[0])));
}

// ---------------- launch ----------------
extern "C" void kernel_launch(void* const* d_in, const int* in_sizes, int n_in,
                              void* d_out, int out_size) {
    const float* x1   = (const float*)d_in[0];
    const int*   ei1  = (const int*)d_in[1];
    const float* x2   = (const float*)d_in[2];
    const int*   ei2  = (const int*)d_in[3];
    const float* w11  = (const float*)d_in[4];
    const float* b11  = (const float*)d_in[5];
    const float* w12  = (const float*)d_in[6];
    const float* b12  = (const float*)d_in[7];
    const float* w21  = (const float*)d_in[8];
    const float* b21  = (const float*)d_in[9];
    const float* w22  = (const float*)d_in[10];
    const float* b22  = (const float*)d_in[11];
    const float* w31  = (const float*)d_in[12];
    const float* b31  = (const float*)d_in[13];
    const float* w32  = (const float*)d_in[14];
    const float* b32  = (const float*)d_in[15];
    const float* linw = (const float*)d_in[16];
    const float* linb = (const float*)d_in[17];
    const float* fc1w = (const float*)d_in[18];
    const float* fc1b = (const float*)d_in[19];
    const float* ln1g = (const float*)d_in[20];
    const float* ln1b = (const float*)d_in[21];
    const float* fc2w = (const float*)d_in[22];
    const float* fc2b = (const float*)d_in[23];
    const float* ln2g = (const float*)d_in[24];
    const float* ln2b = (const float*)d_in[25];
    const float* fc3w = (const float*)d_in[26];
    const float* fc3b = (const float*)d_in[27];
    float* out = (float*)d_out;

    const int* src1 = ei1;
    const int* dst1 = ei1 + N_EDGES;
    const int* src2 = ei2;
    const int* dst2 = ei2 + N_EDGES;

    float *p_agg, *p_tmp, *p_act, *p_o;
    cudaGetSymbolAddress((void**)&p_agg, g_agg);
    cudaGetSymbolAddress((void**)&p_tmp, g_tmp);
    cudaGetSymbolAddress((void**)&p_act, g_act);
    cudaGetSymbolAddress((void**)&p_o, g_o);

    dim3 ggrid(HDIM / 128, MT2);
    const int E2B = (2 * N_EDGES + 255) / 256;
    const int N2B = (NTOT + 255) / 256;
    const int NB = (N_NODES + 255) / 256;

    // batched CSR for both graphs
    k_zero_cnt<<<N2B, 256>>>();
    k_hist2<<<E2B, 256>>>(dst1, dst2);
    k_scan2<<<2, 1024>>>();
    k_fill2<<<E2B, 256>>>(src1, dst1, src2, dst2);

    // layer 1 (FIN=256 -> H)
    k_agg2<FIN_DIM><<<(NTOT + 7) / 8, 512>>>(x1, x2, p_agg);
    k_gemm_mma<<<ggrid, 256>>>(p_agg, w11, b11, p_tmp, FIN_DIM);
    k_gemm_mma<<<ggrid, 256>>>(p_tmp, w12, b12, p_act, HDIM);
    // layer 2
    k_agg2<HDIM><<<(NTOT + 3) / 4, 512>>>(p_act, p_act + (size_t)N_NODES * HDIM, p_agg);
    k_gemm_mma<<<ggrid, 256>>>(p_agg, w21, b21, p_tmp, HDIM);
    k_gemm_mma<<<ggrid, 256>>>(p_tmp, w22, b22, p_act, HDIM);
    // layer 3
    k_agg2<HDIM><<<(NTOT + 3) / 4, 512>>>(p_act, p_act + (size_t)N_NODES * HDIM, p_agg);
    k_gemm_mma<<<ggrid, 256>>>(p_agg, w31, b31, p_tmp, HDIM);
    k_gemm_mma<<<ggrid, 256>>>(p_tmp, w32, b32, p_act, HDIM);
    // lin head -> [NTOT,2]
    k_lin<<<(NTOT * 32 + 255) / 256, 256>>>(p_act, linw, linb, p_o);

    k_dist<<<NB, 256>>>();
    k_selhist<<<1, 1024>>>();
    k_compact<<<NB, 256>>>();
    k_sortsel<<<1, 1024>>>();
    k_mlp<<<1, 512>>>(fc1w, fc1b, ln1g, ln1b, fc2w, fc2b, ln2g, ln2b, fc3w, fc3b, out);
}

// round 10
// speedup vs baseline: 1.3464x; 1.0256x over previous
#include <cuda_runtime.h>
#include <math.h>
#include <stdint.h>

#define N_NODES 20000
#define NTOT    40000
#define MPAD2   40192
#define MT2     314
#define N_EDGES 640000
#define FIN_DIM 256
#define HDIM 512
#define TOPK 1000
#define SELN 4096

// ---------------- scratch (static device memory; no allocations) ----------------
__device__ float g_agg[(size_t)MPAD2 * HDIM];
__device__ float g_tmp[(size_t)MPAD2 * HDIM];
__device__ float g_act[(size_t)MPAD2 * HDIM];
__device__ float g_part[8][MPAD2][2];
__device__ float g_o[NTOT * 2];
__device__ float g_dist[N_NODES];
__device__ float g_sel[SELN];
__device__ float g_top[TOPK];
__device__ int   g_selcnt;
__device__ int   g_thrbin;
__device__ int   g_cnt[NTOT];
__device__ int   g_rowptr[2 * (N_NODES + 1)];
__device__ int   g_cursor[NTOT];
__device__ int   g_esrc[2 * N_EDGES];

// ---------------- helpers ----------------
__device__ __forceinline__ uint32_t packbf(float lo_e, float hi_o) {
    uint32_t r;
    asm("cvt.rn.bf16x2.f32 %0, %1, %2;" : "=r"(r) : "f"(hi_o), "f"(lo_e));
    return r;
}
__device__ __forceinline__ void split2(float v0, float v1, uint32_t& h, uint32_t& l) {
    h = packbf(v0, v1);
    float h0 = __uint_as_float(h << 16);
    float h1 = __uint_as_float(h & 0xffff0000u);
    l = packbf(v0 - h0, v1 - h1);
}
__device__ __forceinline__ void mma_bf16(float* c, const uint32_t* a, const uint32_t* b) {
    asm volatile(
        "mma.sync.aligned.m16n8k16.row.col.f32.bf16.bf16.f32 "
        "{%0,%1,%2,%3}, {%4,%5,%6,%7}, {%8,%9}, {%0,%1,%2,%3};"
        : "+f"(c[0]), "+f"(c[1]), "+f"(c[2]), "+f"(c[3])
        : "r"(a[0]), "r"(a[1]), "r"(a[2]), "r"(a[3]), "r"(b[0]), "r"(b[1]));
}

// ---------------- CSR build (both graphs, batched) ----------------
__global__ void k_zero_cnt() {
    int i = blockIdx.x * blockDim.x + threadIdx.x;
    if (i < NTOT) g_cnt[i] = 0;
}
__global__ void k_hist2(const int* __restrict__ dst1, const int* __restrict__ dst2) {
    int e = blockIdx.x * blockDim.x + threadIdx.x;
    if (e >= 2 * N_EDGES) return;
    int gph = e >= N_EDGES;
    int le = e - gph * N_EDGES;
    int d = (gph ? dst2 : dst1)[le];
    atomicAdd(&g_cnt[gph * N_NODES + d], 1);
}
__global__ void k_scan2() {
    __shared__ int s[1024];
    __shared__ int carry;
    int t = threadIdx.x;
    int gph = blockIdx.x;
    const int cbase = gph * N_NODES;
    const int rbase = gph * (N_NODES + 1);
    if (t == 0) carry = 0;
    __syncthreads();
    for (int base = 0; base < N_NODES; base += 1024) {
        int v = (base + t < N_NODES) ? g_cnt[cbase + base + t] : 0;
        s[t] = v;
        __syncthreads();
        for (int off = 1; off < 1024; off <<= 1) {
            int a = (t >= off) ? s[t - off] : 0;
            __syncthreads();
            s[t] += a;
            __syncthreads();
        }
        int exc = s[t] - v + carry;
        if (base + t < N_NODES) {
            g_rowptr[rbase + base + t] = exc;
            g_cursor[cbase + base + t] = exc;
        }
        __syncthreads();
        if (t == 0) carry = carry + s[1023];
        __syncthreads();
    }
    if (t == 0) g_rowptr[rbase + N_NODES] = carry;
}
__global__ void k_fill2(const int* __restrict__ src1, const int* __restrict__ dst1,
                        const int* __restrict__ src2, const int* __restrict__ dst2) {
    int e = blockIdx.x * blockDim.x + threadIdx.x;
    if (e >= 2 * N_EDGES) return;
    int gph = e >= N_EDGES;
    int le = e - gph * N_EDGES;
    int d = (gph ? dst2 : dst1)[le];
    int sv = (gph ? src2 : src1)[le];
    int pos = atomicAdd(&g_cursor[gph * N_NODES + d], 1);
    g_esrc[gph * N_EDGES + pos] = sv;
}

// ---------------- aggregation: out[node] = x[node] + sum_j x[j] -------------
template <int F>
__global__ void k_agg2(const float* __restrict__ xa, const float* __restrict__ xb,
                       float* __restrict__ out) {
    const int FV = F / 4;
    const int NPB = 512 / FV;
    int t = threadIdx.x;
    int node = blockIdx.x * NPB + t / FV;
    int tf = t % FV;
    if (node >= NTOT) return;
    int gph = node >= N_NODES;
    int local = node - gph * N_NODES;
    const float4* x4 = (const float4*)(gph ? xb : xa);
    float4 acc = x4[(size_t)local * FV + tf];
    int beg = g_rowptr[gph * (N_NODES + 1) + local];
    int end = g_rowptr[gph * (N_NODES + 1) + local + 1];
    const int* ep = g_esrc + gph * N_EDGES;
    int e = beg;
    for (; e + 1 < end; e += 2) {
        int i0 = __ldg(&ep[e]);
        int i1 = __ldg(&ep[e + 1]);
        float4 v0 = x4[(size_t)i0 * FV + tf];
        float4 v1 = x4[(size_t)i1 * FV + tf];
        acc.x += v0.x + v1.x; acc.y += v0.y + v1.y;
        acc.z += v0.z + v1.z; acc.w += v0.w + v1.w;
    }
    if (e < end) {
        int i0 = __ldg(&ep[e]);
        float4 v0 = x4[(size_t)i0 * FV + tf];
        acc.x += v0.x; acc.y += v0.y; acc.z += v0.z; acc.w += v0.w;
    }
    ((float4*)out)[(size_t)node * FV + tf] = acc;
}

// ---------------- 3x-bf16 mma.sync GEMM: C[MPAD2,512] = relu(A @ W + b) ------
// (R9 config: 128x128x16, 256 thr, single barrier per stage.)
// If linw2 != nullptr: instead of storing C, contract relu(acc+bias) against
// linw2[512][2] and write partials to part[blockIdx.x*2+warp_n][row][2].
#define GSTRIDE 140
#define GMATW   (8 * GSTRIDE)

__global__ void __launch_bounds__(256)
k_gemm_mma(const float* __restrict__ A, const float* __restrict__ W,
           const float* __restrict__ bias, float* __restrict__ C, int K,
           const float* __restrict__ linw2, float* __restrict__ part) {
    __shared__ uint32_t S[2][4][GMATW];
    int t = threadIdx.x, lane = t & 31, wid = t >> 5;
    int warp_m = wid >> 1, warp_n = wid & 1;
    int rowBase = blockIdx.y * 128;
    int colBase = blockIdx.x * 128;

    float acc[2][8][4];
#pragma unroll
    for (int i = 0; i < 2; i++)
#pragma unroll
        for (int j = 0; j < 8; j++)
#pragma unroll
            for (int q = 0; q < 4; q++) acc[i][j][q] = 0.f;

    int a_row = t >> 1;
    int a_half = t & 1;
    int b_k2 = t >> 5;
    int b_n0 = lane * 4;

    const float* Ap = A + (size_t)(rowBase + a_row) * K + a_half * 8;
    const float* Bp0 = W + (size_t)(2 * b_k2) * HDIM + colBase + b_n0;
    const float* Bp1 = Bp0 + HDIM;

    const int nk = K >> 4;
    float4 ra0, ra1, rb0, rb1;

    ra0 = *(const float4*)(Ap);
    ra1 = *(const float4*)(Ap + 4);
    rb0 = *(const float4*)(Bp0);
    rb1 = *(const float4*)(Bp1);

    for (int s = 0; s < nk; s++) {
        int buf = s & 1;
        uint32_t* Ah = S[buf][0];
        uint32_t* Al = S[buf][1];
        uint32_t* Bh = S[buf][2];
        uint32_t* Bl = S[buf][3];
        {
            float av[8] = {ra0.x, ra0.y, ra0.z, ra0.w, ra1.x, ra1.y, ra1.z, ra1.w};
#pragma unroll
            for (int i = 0; i < 4; i++) {
                uint32_t h, l;
                split2(av[2 * i], av[2 * i + 1], h, l);
                int idx = (a_half * 4 + i) * GSTRIDE + a_row;
                Ah[idx] = h; Al[idx] = l;
            }
            uint4 hh, ll;
            split2(rb0.x, rb1.x, hh.x, ll.x);
            split2(rb0.y, rb1.y, hh.y, ll.y);
            split2(rb0.z, rb1.z, hh.z, ll.z);
            split2(rb0.w, rb1.w, hh.w, ll.w);
            *(uint4*)&Bh[b_k2 * GSTRIDE + b_n0] = hh;
            *(uint4*)&Bl[b_k2 * GSTRIDE + b_n0] = ll;
        }
        __syncthreads();   // the ONLY barrier per stage (double buffering)
        if (s + 1 < nk) {
            const float* Ap2 = Ap + (s + 1) * 16;
            const float* Bp2 = Bp0 + (size_t)(s + 1) * 16 * HDIM;
            ra0 = *(const float4*)(Ap2);
            ra1 = *(const float4*)(Ap2 + 4);
            rb0 = *(const float4*)(Bp2);
            rb1 = *(const float4*)(Bp2 + HDIM);
        }
        {
            int g = lane >> 2, q = lane & 3;
            uint32_t bhf[8][2], blf[8][2];
#pragma unroll
            for (int nt = 0; nt < 8; nt++) {
                int n = warp_n * 64 + nt * 8 + g;
                bhf[nt][0] = Bh[q * GSTRIDE + n];
                bhf[nt][1] = Bh[(q + 4) * GSTRIDE + n];
                blf[nt][0] = Bl[q * GSTRIDE + n];
                blf[nt][1] = Bl[(q + 4) * GSTRIDE + n];
            }
#pragma unroll
            for (int mt = 0; mt < 2; mt++) {
                int m = warp_m * 32 + mt * 16 + g;
                uint32_t ahf[4], alf[4];
                ahf[0] = Ah[q * GSTRIDE + m];
                ahf[1] = Ah[q * GSTRIDE + m + 8];
                ahf[2] = Ah[(q + 4) * GSTRIDE + m];
                ahf[3] = Ah[(q + 4) * GSTRIDE + m + 8];
                alf[0] = Al[q * GSTRIDE + m];
                alf[1] = Al[q * GSTRIDE + m + 8];
                alf[2] = Al[(q + 4) * GSTRIDE + m];
                alf[3] = Al[(q + 4) * GSTRIDE + m + 8];
#pragma unroll
                for (int nt = 0; nt < 8; nt++) {
                    mma_bf16(acc[mt][nt], ahf, bhf[nt]);
                    mma_bf16(acc[mt][nt], alf, bhf[nt]);
                    mma_bf16(acc[mt][nt], ahf, blf[nt]);
                }
            }
        }
    }

    int g = lane >> 2;
    int cq = (lane & 3) * 2;
    if (linw2 == nullptr) {
#pragma unroll
        for (int mt = 0; mt < 2; mt++) {
            int row = rowBase + warp_m * 32 + mt * 16 + g;
#pragma unroll
            for (int nt = 0; nt < 8; nt++) {
                int col = colBase + warp_n * 64 + nt * 8 + cq;
                float b0 = bias[col], b1 = bias[col + 1];
                float2 o0, o1;
                o0.x = fmaxf(acc[mt][nt][0] + b0, 0.f);
                o0.y = fmaxf(acc[mt][nt][1] + b1, 0.f);
                o1.x = fmaxf(acc[mt][nt][2] + b0, 0.f);
                o1.y = fmaxf(acc[mt][nt][3] + b1, 0.f);
                *(float2*)&C[(size_t)row * HDIM + col] = o0;
                *(float2*)&C[(size_t)(row + 8) * HDIM + col] = o1;
            }
        }
    } else {
        // fused final linear: partial dot of relu(acc+bias) with linw2 over this
        // warp's 16 columns; reduce across the 4 lanes sharing a row (lane&3).
        int slot = blockIdx.x * 2 + warp_n;
#pragma unroll
        for (int mt = 0; mt < 2; mt++) {
            float s00 = 0.f, s01 = 0.f;   // row = base+g
            float s10 = 0.f, s11 = 0.f;   // row = base+g+8
#pragma unroll
            for (int nt = 0; nt < 8; nt++) {
                int col = colBase + warp_n * 64 + nt * 8 + cq;
                float b0 = bias[col], b1 = bias[col + 1];
                float lw00 = linw2[col * 2],     lw01 = linw2[col * 2 + 1];
                float lw10 = linw2[col * 2 + 2], lw11 = linw2[col * 2 + 3];
                float v0 = fmaxf(acc[mt][nt][0] + b0, 0.f);
                float v1 = fmaxf(acc[mt][nt][1] + b1, 0.f);
                float v2 = fmaxf(acc[mt][nt][2] + b0, 0.f);
                float v3 = fmaxf(acc[mt][nt][3] + b1, 0.f);
                s00 += v0 * lw00 + v1 * lw10;
                s01 += v0 * lw01 + v1 * lw11;
                s10 += v2 * lw00 + v3 * lw10;
                s11 += v2 * lw01 + v3 * lw11;
            }
            // reduce over lane&3 (lanes 4g..4g+3 hold the same rows)
#pragma unroll
            for (int off = 1; off <= 2; off <<= 1) {
                s00 += __shfl_xor_sync(0xffffffffu, s00, off);
                s01 += __shfl_xor_sync(0xffffffffu, s01, off);
                s10 += __shfl_xor_sync(0xffffffffu, s10, off);
                s11 += __shfl_xor_sync(0xffffffffu, s11, off);
            }
            if ((lane & 3) == 0) {
                int row = rowBase + warp_m * 32 + mt * 16 + g;
                float* p0 = part + ((size_t)slot * MPAD2 + row) * 2;
                p0[0] = s00; p0[1] = s01;
                float* p1 = part + ((size_t)slot * MPAD2 + row + 8) * 2;
                p1[0] = s10; p1[1] = s11;
            }
        }
    }
}

// ---------------- reduce lin partials: o[i] = sum_slots part + bias ---------
__global__ void k_linred(const float* __restrict__ b, float* __restrict__ o) {
    int i = blockIdx.x * blockDim.x + threadIdx.x;
    if (i >= NTOT) return;
    float a0 = b[0], a1 = b[1];
#pragma unroll
    for (int s = 0; s < 8; s++) {
        a0 += g_part[s][i][0];
        a1 += g_part[s][i][1];
    }
    o[i * 2] = a0;
    o[i * 2 + 1] = a1;
}

// ---------------- pairwise distance ----------------
__global__ void k_dist() {
    int i = blockIdx.x * blockDim.x + threadIdx.x;
    if (i >= N_NODES) return;
    float dx = g_o[i * 2]     - g_o[(i + N_NODES) * 2]     + 1e-6f;
    float dy = g_o[i * 2 + 1] - g_o[(i + N_NODES) * 2 + 1] + 1e-6f;
    g_dist[i] = sqrtf(dx * dx + dy * dy);
}

// ---------------- top-k select: histogram threshold ----------------
__global__ void k_selhist() {
    __shared__ int hist[2048];
    int t = threadIdx.x;
    hist[t] = 0; hist[t + 1024] = 0;
    for (int i = t; i < SELN; i += 1024) g_sel[i] = -INFINITY;
    if (t == 0) g_selcnt = 0;
    __syncthreads();
    for (int i = t; i < N_NODES; i += 1024) {
        uint32_t bits = __float_as_uint(g_dist[i]);
        atomicAdd(&hist[bits >> 21], 1);
    }
    __syncthreads();
    if (t == 0) {
        int cum = 0, thr = 0;
        for (int b = 2047; b >= 0; b--) {
            cum += hist[b];
            if (cum >= TOPK) { thr = b; break; }
        }
        g_thrbin = thr;
    }
}
__global__ void k_compact() {
    int i = blockIdx.x * blockDim.x + threadIdx.x;
    if (i >= N_NODES) return;
    float d = g_dist[i];
    if ((int)(__float_as_uint(d) >> 21) >= g_thrbin) {
        int pos = atomicAdd(&g_selcnt, 1);
        if (pos < SELN) g_sel[pos] = d;
    }
}
__global__ void k_sortsel() {
    __shared__ float s[SELN];
    int t = threadIdx.x;
    for (int i = t; i < SELN; i += 1024) s[i] = g_sel[i];
    __syncthreads();
    for (int k = 2; k <= SELN; k <<= 1) {
        for (int j = k >> 1; j > 0; j >>= 1) {
            for (int i = t; i < SELN; i += 1024) {
                int ixj = i ^ j;
                if (ixj > i) {
                    bool dsc = (i & k) == 0;
                    float a = s[i], c = s[ixj];
                    bool sw = dsc ? (a < c) : (a > c);
                    if (sw) { s[i] = c; s[ixj] = a; }
                }
            }
            __syncthreads();
        }
    }
    for (int i = t; i < TOPK; i += 1024) g_top[i] = s[i];
}

// ---------------- head MLP ----------------
__global__ void k_mlp(const float* __restrict__ fc1w, const float* __restrict__ fc1b,
                      const float* __restrict__ ln1g, const float* __restrict__ ln1b,
                      const float* __restrict__ fc2w, const float* __restrict__ fc2b,
                      const float* __restrict__ ln2g, const float* __restrict__ ln2b,
                      const float* __restrict__ fc3w, const float* __restrict__ fc3b,
                      float* __restrict__ out) {
    __shared__ float vals[TOPK];
    __shared__ float h1[128];
    __shared__ float part[4][128];
    __shared__ float h2[512];
    __shared__ float red[512];
    int t = threadIdx.x;
    for (int i = t; i < TOPK; i += 512) vals[i] = g_top[i];
    __syncthreads();
    {
        int j = t & 127, c = t >> 7;
        float acc = 0.f;
        for (int i = c * 250; i < (c + 1) * 250; i++) acc += vals[i] * fc1w[i * 128 + j];
        part[c][j] = acc;
    }
    __syncthreads();
    if (t < 128) h1[t] = part[0][t] + part[1][t] + part[2][t] + part[3][t] + fc1b[t];
    __syncthreads();
    red[t] = (t < 128) ? h1[t] : 0.f;
    __syncthreads();
    for (int off = 256; off; off >>= 1) { if (t < off) red[t] += red[t + off]; __syncthreads(); }
    float mean1 = red[0] / 128.f;
    __syncthreads();
    red[t] = (t < 128) ? (h1[t] - mean1) * (h1[t] - mean1) : 0.f;
    __syncthreads();
    for (int off = 256; off; off >>= 1) { if (t < off) red[t] += red[t + off]; __syncthreads(); }
    float var1 = red[0] / 128.f;
    __syncthreads();
    if (t < 128) {
        float v = (h1[t] - mean1) * rsqrtf(var1 + 1e-5f) * ln1g[t] + ln1b[t];
        h1[t] = fmaxf(v, 0.f);
    }
    __syncthreads();
    {
        float acc = fc2b[t];
        for (int i = 0; i < 128; i++) acc += h1[i] * fc2w[i * 512 + t];
        h2[t] = acc;
    }
    __syncthreads();
    red[t] = h2[t];
    __syncthreads();
    for (int off = 256; off; off >>= 1) { if (t < off) red[t] += red[t + off]; __syncthreads(); }
    float mean2 = red[0] / 512.f;
    __syncthreads();
    red[t] = (h2[t] - mean2) * (h2[t] - mean2);
    __syncthreads();
    for (int off = 256; off; off >>= 1) { if (t < off) red[t] += red[t + off]; __syncthreads(); }
    float var2 = red[0] / 512.f;
    __syncthreads();
    float hr = fmaxf((h2[t] - mean2) * rsqrtf(var2 + 1e-5f) * ln2g[t] + ln2b[t], 0.f);
    red[t] = hr * fc3w[t];
    __syncthreads();
    for (int off = 256; off; off >>= 1) { if (t < off) red[t] += red[t + off]; __syncthreads(); }
    if (t == 0) out[0] = 1.f / (1.f + expf(-(red[0] + fc3b[0])));
}

// ---------------- launch ----------------
extern "C" void kernel_launch(void* const* d_in, const int* in_sizes, int n_in,
                              void* d_out, int out_size) {
    const float* x1   = (const float*)d_in[0];
    const int*   ei1  = (const int*)d_in[1];
    const float* x2   = (const float*)d_in[2];
    const int*   ei2  = (const int*)d_in[3];
    const float* w11  = (const float*)d_in[4];
    const float* b11  = (const float*)d_in[5];
    const float* w12  = (const float*)d_in[6];
    const float* b12  = (const float*)d_in[7];
    const float* w21  = (const float*)d_in[8];
    const float* b21  = (const float*)d_in[9];
    const float* w22  = (const float*)d_in[10];
    const float* b22  = (const float*)d_in[11];
    const float* w31  = (const float*)d_in[12];
    const float* b31  = (const float*)d_in[13];
    const float* w32  = (const float*)d_in[14];
    const float* b32  = (const float*)d_in[15];
    const float* linw = (const float*)d_in[16];
    const float* linb = (const float*)d_in[17];
    const float* fc1w = (const float*)d_in[18];
    const float* fc1b = (const float*)d_in[19];
    const float* ln1g = (const float*)d_in[20];
    const float* ln1b = (const float*)d_in[21];
    const float* fc2w = (const float*)d_in[22];
    const float* fc2b = (const float*)d_in[23];
    const float* ln2g = (const float*)d_in[24];
    const float* ln2b = (const float*)d_in[25];
    const float* fc3w = (const float*)d_in[26];
    const float* fc3b = (const float*)d_in[27];
    float* out = (float*)d_out;

    const int* src1 = ei1;
    const int* dst1 = ei1 + N_EDGES;
    const int* src2 = ei2;
    const int* dst2 = ei2 + N_EDGES;

    float *p_agg, *p_tmp, *p_act, *p_o, *p_part;
    cudaGetSymbolAddress((void**)&p_agg, g_agg);
    cudaGetSymbolAddress((void**)&p_tmp, g_tmp);
    cudaGetSymbolAddress((void**)&p_act, g_act);
    cudaGetSymbolAddress((void**)&p_o, g_o);
    cudaGetSymbolAddress((void**)&p_part, g_part);

    dim3 ggrid(HDIM / 128, MT2);
    const int E2B = (2 * N_EDGES + 255) / 256;
    const int N2B = (NTOT + 255) / 256;
    const int NB = (N_NODES + 255) / 256;

    // batched CSR for both graphs
    k_zero_cnt<<<N2B, 256>>>();
    k_hist2<<<E2B, 256>>>(dst1, dst2);
    k_scan2<<<2, 1024>>>();
    k_fill2<<<E2B, 256>>>(src1, dst1, src2, dst2);

    // layer 1 (FIN=256 -> H)
    k_agg2<FIN_DIM><<<(NTOT + 7) / 8, 512>>>(x1, x2, p_agg);
    k_gemm_mma<<<ggrid, 256>>>(p_agg, w11, b11, p_tmp, FIN_DIM, nullptr, nullptr);
    k_gemm_mma<<<ggrid, 256>>>(p_tmp, w12, b12, p_act, HDIM, nullptr, nullptr);
    // layer 2
    k_agg2<HDIM><<<(NTOT + 3) / 4, 512>>>(p_act, p_act + (size_t)N_NODES * HDIM, p_agg);
    k_gemm_mma<<<ggrid, 256>>>(p_agg, w21, b21, p_tmp, HDIM, nullptr, nullptr);
    k_gemm_mma<<<ggrid, 256>>>(p_tmp, w22, b22, p_act, HDIM, nullptr, nullptr);
    // layer 3
    k_agg2<HDIM><<<(NTOT + 3) / 4, 512>>>(p_act, p_act + (size_t)N_NODES * HDIM, p_agg);
    k_gemm_mma<<<ggrid, 256>>>(p_agg, w31, b31, p_tmp, HDIM, nullptr, nullptr);
    // last GEMM: fused final linear (no act store, no k_lin)
    k_gemm_mma<<<ggrid, 256>>>(p_tmp, w32, b32, nullptr, HDIM, linw, p_part);
    k_linred<<<N2B, 256>>>(linb, p_o);

    k_dist<<<NB, 256>>>();
    k_selhist<<<1, 1024>>>();
    k_compact<<<NB, 256>>>();
    k_sortsel<<<1, 1024>>>();
    k_mlp<<<1, 512>>>(fc1w, fc1b, ln1g, ln1b, fc2w, fc2b, ln2g, ln2b, fc3w, fc3b, out);
}

// round 11
// speedup vs baseline: 1.4405x; 1.0699x over previous
#include <cuda_runtime.h>
#include <cuda_fp16.h>
#include <math.h>
#include <stdint.h>

#define N_NODES 20000
#define NTOT    40000
#define MPAD2   40192
#define MT2     314
#define N_EDGES 640000
#define FIN_DIM 256
#define HDIM 512
#define TOPK 1000
#define SELN 4096

// ---------------- scratch (static device memory; no allocations) ----------------
__device__ __half g_aggh[(size_t)MPAD2 * HDIM];   // agg outputs (GEMM A operand)
__device__ __half g_acth[(size_t)MPAD2 * HDIM];   // layer outputs consumed by agg
__device__ float  g_tmp[(size_t)MPAD2 * HDIM];    // inter-GEMM fp32 intermediate
__device__ float  g_part[8][MPAD2][2];
__device__ float  g_o[NTOT * 2];
__device__ float  g_dist[N_NODES];
__device__ float  g_sel[SELN];
__device__ float  g_top[TOPK];
__device__ int    g_selcnt;
__device__ int    g_thrbin;
__device__ int    g_cnt[NTOT];
__device__ int    g_rowptr[2 * (N_NODES + 1)];
__device__ int    g_cursor[NTOT];
__device__ int    g_esrc[2 * N_EDGES];

// ---------------- helpers ----------------
__device__ __forceinline__ uint32_t packbf(float lo_e, float hi_o) {
    uint32_t r;
    asm("cvt.rn.bf16x2.f32 %0, %1, %2;" : "=r"(r) : "f"(hi_o), "f"(lo_e));
    return r;
}
__device__ __forceinline__ void split2(float v0, float v1, uint32_t& h, uint32_t& l) {
    h = packbf(v0, v1);
    float h0 = __uint_as_float(h << 16);
    float h1 = __uint_as_float(h & 0xffff0000u);
    l = packbf(v0 - h0, v1 - h1);
}
__device__ __forceinline__ void mma_bf16(float* c, const uint32_t* a, const uint32_t* b) {
    asm volatile(
        "mma.sync.aligned.m16n8k16.row.col.f32.bf16.bf16.f32 "
        "{%0,%1,%2,%3}, {%4,%5,%6,%7}, {%8,%9}, {%0,%1,%2,%3};"
        : "+f"(c[0]), "+f"(c[1]), "+f"(c[2]), "+f"(c[3])
        : "r"(a[0]), "r"(a[1]), "r"(a[2]), "r"(a[3]), "r"(b[0]), "r"(b[1]));
}

// ---------------- CSR build (both graphs, batched) ----------------
__global__ void k_zero_cnt() {
    int i = blockIdx.x * blockDim.x + threadIdx.x;
    if (i < NTOT) g_cnt[i] = 0;
}
__global__ void k_hist2(const int* __restrict__ dst1, const int* __restrict__ dst2) {
    int e = blockIdx.x * blockDim.x + threadIdx.x;
    if (e >= 2 * N_EDGES) return;
    int gph = e >= N_EDGES;
    int le = e - gph * N_EDGES;
    int d = (gph ? dst2 : dst1)[le];
    atomicAdd(&g_cnt[gph * N_NODES + d], 1);
}
__global__ void k_scan2() {
    __shared__ int s[1024];
    __shared__ int carry;
    int t = threadIdx.x;
    int gph = blockIdx.x;
    const int cbase = gph * N_NODES;
    const int rbase = gph * (N_NODES + 1);
    if (t == 0) carry = 0;
    __syncthreads();
    for (int base = 0; base < N_NODES; base += 1024) {
        int v = (base + t < N_NODES) ? g_cnt[cbase + base + t] : 0;
        s[t] = v;
        __syncthreads();
        for (int off = 1; off < 1024; off <<= 1) {
            int a = (t >= off) ? s[t - off] : 0;
            __syncthreads();
            s[t] += a;
            __syncthreads();
        }
        int exc = s[t] - v + carry;
        if (base + t < N_NODES) {
            g_rowptr[rbase + base + t] = exc;
            g_cursor[cbase + base + t] = exc;
        }
        __syncthreads();
        if (t == 0) carry = carry + s[1023];
        __syncthreads();
    }
    if (t == 0) g_rowptr[rbase + N_NODES] = carry;
}
__global__ void k_fill2(const int* __restrict__ src1, const int* __restrict__ dst1,
                        const int* __restrict__ src2, const int* __restrict__ dst2) {
    int e = blockIdx.x * blockDim.x + threadIdx.x;
    if (e >= 2 * N_EDGES) return;
    int gph = e >= N_EDGES;
    int le = e - gph * N_EDGES;
    int d = (gph ? dst2 : dst1)[le];
    int sv = (gph ? src2 : src1)[le];
    int pos = atomicAdd(&g_cursor[gph * N_NODES + d], 1);
    g_esrc[gph * N_EDGES + pos] = sv;
}

// ---------------- aggregation layer 1: fp32 in, fp16 out -------------------
// F=256 floats; 64 threads/node (float4), 8 nodes per 512-thread block.
__global__ void k_agg_f2h(const float* __restrict__ xa, const float* __restrict__ xb,
                          __half* __restrict__ out) {
    const int FV = FIN_DIM / 4;          // 64
    int t = threadIdx.x;
    int node = blockIdx.x * 8 + t / FV;
    int tf = t % FV;
    if (node >= NTOT) return;
    int gph = node >= N_NODES;
    int local = node - gph * N_NODES;
    const float4* x4 = (const float4*)(gph ? xb : xa);
    float4 acc = x4[(size_t)local * FV + tf];
    int beg = g_rowptr[gph * (N_NODES + 1) + local];
    int end = g_rowptr[gph * (N_NODES + 1) + local + 1];
    const int* ep = g_esrc + gph * N_EDGES;
    int e = beg;
    for (; e + 1 < end; e += 2) {
        int i0 = __ldg(&ep[e]);
        int i1 = __ldg(&ep[e + 1]);
        float4 v0 = x4[(size_t)i0 * FV + tf];
        float4 v1 = x4[(size_t)i1 * FV + tf];
        acc.x += v0.x + v1.x; acc.y += v0.y + v1.y;
        acc.z += v0.z + v1.z; acc.w += v0.w + v1.w;
    }
    if (e < end) {
        int i0 = __ldg(&ep[e]);
        float4 v0 = x4[(size_t)i0 * FV + tf];
        acc.x += v0.x; acc.y += v0.y; acc.z += v0.z; acc.w += v0.w;
    }
    __half2 ha = __floats2half2_rn(acc.x, acc.y);
    __half2 hb = __floats2half2_rn(acc.z, acc.w);
    uint2 u = make_uint2(*(uint32_t*)&ha, *(uint32_t*)&hb);
    *(uint2*)(out + (size_t)node * FIN_DIM + tf * 4) = u;
}

// ---------------- aggregation layers 2-3: fp16 in, fp16 out ----------------
// F=512 halves; 64 threads/node (uint4 = 8 halves), 8 nodes per block.
__global__ void k_agg_h2h(const __half* __restrict__ x, __half* __restrict__ out) {
    int t = threadIdx.x;
    int node = blockIdx.x * 8 + t / 64;
    int tf = t % 64;
    if (node >= NTOT) return;
    int gph = node >= N_NODES;
    int local = node - gph * N_NODES;
    const uint4* x4 = (const uint4*)x;   // one row = 64 uint4
    float acc[8];
    {
        uint4 v = x4[(size_t)node * 64 + tf];
        float2 f0 = __half22float2(*(__half2*)&v.x);
        float2 f1 = __half22float2(*(__half2*)&v.y);
        float2 f2 = __half22float2(*(__half2*)&v.z);
        float2 f3 = __half22float2(*(__half2*)&v.w);
        acc[0] = f0.x; acc[1] = f0.y; acc[2] = f1.x; acc[3] = f1.y;
        acc[4] = f2.x; acc[5] = f2.y; acc[6] = f3.x; acc[7] = f3.y;
    }
    int beg = g_rowptr[gph * (N_NODES + 1) + local];
    int end = g_rowptr[gph * (N_NODES + 1) + local + 1];
    const int* ep = g_esrc + gph * N_EDGES;
    const size_t gofs = (size_t)gph * N_NODES * 64;
    int e = beg;
    for (; e + 1 < end; e += 2) {
        int i0 = __ldg(&ep[e]);
        int i1 = __ldg(&ep[e + 1]);
        uint4 v0 = x4[gofs + (size_t)i0 * 64 + tf];
        uint4 v1 = x4[gofs + (size_t)i1 * 64 + tf];
        float2 a0 = __half22float2(*(__half2*)&v0.x), b0 = __half22float2(*(__half2*)&v1.x);
        float2 a1 = __half22float2(*(__half2*)&v0.y), b1 = __half22float2(*(__half2*)&v1.y);
        float2 a2 = __half22float2(*(__half2*)&v0.z), b2 = __half22float2(*(__half2*)&v1.z);
        float2 a3 = __half22float2(*(__half2*)&v0.w), b3 = __half22float2(*(__half2*)&v1.w);
        acc[0] += a0.x + b0.x; acc[1] += a0.y + b0.y;
        acc[2] += a1.x + b1.x; acc[3] += a1.y + b1.y;
        acc[4] += a2.x + b2.x; acc[5] += a2.y + b2.y;
        acc[6] += a3.x + b3.x; acc[7] += a3.y + b3.y;
    }
    if (e < end) {
        int i0 = __ldg(&ep[e]);
        uint4 v0 = x4[gofs + (size_t)i0 * 64 + tf];
        float2 a0 = __half22float2(*(__half2*)&v0.x);
        float2 a1 = __half22float2(*(__half2*)&v0.y);
        float2 a2 = __half22float2(*(__half2*)&v0.z);
        float2 a3 = __half22float2(*(__half2*)&v0.w);
        acc[0] += a0.x; acc[1] += a0.y; acc[2] += a1.x; acc[3] += a1.y;
        acc[4] += a2.x; acc[5] += a2.y; acc[6] += a3.x; acc[7] += a3.y;
    }
    __half2 h0 = __floats2half2_rn(acc[0], acc[1]);
    __half2 h1 = __floats2half2_rn(acc[2], acc[3]);
    __half2 h2 = __floats2half2_rn(acc[4], acc[5]);
    __half2 h3 = __floats2half2_rn(acc[6], acc[7]);
    uint4 u = make_uint4(*(uint32_t*)&h0, *(uint32_t*)&h1,
                         *(uint32_t*)&h2, *(uint32_t*)&h3);
    ((uint4*)out)[(size_t)node * 64 + tf] = u;
}

// ---------------- 3x-bf16 mma.sync GEMM (templated A/C types) --------------
// Block 128x128x16, 256 thr, single barrier per stage (R9 config).
// TA in {float, __half}; TC in {float, __half}. If linw2 != nullptr: fused
// final linear, partials to part[blockIdx.x*2+warp_n][row][2] (TC unused).
#define GSTRIDE 140
#define GMATW   (8 * GSTRIDE)

template <typename TA, typename TC>
__global__ void __launch_bounds__(256)
k_gemm_mma(const TA* __restrict__ A, const float* __restrict__ W,
           const float* __restrict__ bias, TC* __restrict__ C, int K,
           const float* __restrict__ linw2, float* __restrict__ part) {
    constexpr bool A_HALF = sizeof(TA) == 2;
    __shared__ uint32_t S[2][4][GMATW];
    int t = threadIdx.x, lane = t & 31, wid = t >> 5;
    int warp_m = wid >> 1, warp_n = wid & 1;
    int rowBase = blockIdx.y * 128;
    int colBase = blockIdx.x * 128;

    float acc[2][8][4];
#pragma unroll
    for (int i = 0; i < 2; i++)
#pragma unroll
        for (int j = 0; j < 8; j++)
#pragma unroll
            for (int q = 0; q < 4; q++) acc[i][j][q] = 0.f;

    int a_row = t >> 1;
    int a_half = t & 1;
    int b_k2 = t >> 5;
    int b_n0 = lane * 4;

    const TA* Ap = A + (size_t)(rowBase + a_row) * K + a_half * 8;
    const float* Bp0 = W + (size_t)(2 * b_k2) * HDIM + colBase + b_n0;
    const float* Bp1 = Bp0 + HDIM;

    const int nk = K >> 4;
    float4 ra0, ra1;
    uint4 rah;
    float4 rb0, rb1;

    if constexpr (A_HALF) {
        rah = *(const uint4*)(Ap);
    } else {
        ra0 = *(const float4*)(Ap);
        ra1 = *(const float4*)(Ap + 4);
    }
    rb0 = *(const float4*)(Bp0);
    rb1 = *(const float4*)(Bp1);

    for (int s = 0; s < nk; s++) {
        int buf = s & 1;
        uint32_t* Ah = S[buf][0];
        uint32_t* Al = S[buf][1];
        uint32_t* Bh = S[buf][2];
        uint32_t* Bl = S[buf][3];
        {
            if constexpr (A_HALF) {
                uint32_t words[4] = {rah.x, rah.y, rah.z, rah.w};
#pragma unroll
                for (int i = 0; i < 4; i++) {
                    float2 f = __half22float2(*(__half2*)&words[i]);
                    uint32_t h, l;
                    split2(f.x, f.y, h, l);
                    int idx = (a_half * 4 + i) * GSTRIDE + a_row;
                    Ah[idx] = h; Al[idx] = l;
                }
            } else {
                float av[8] = {ra0.x, ra0.y, ra0.z, ra0.w, ra1.x, ra1.y, ra1.z, ra1.w};
#pragma unroll
                for (int i = 0; i < 4; i++) {
                    uint32_t h, l;
                    split2(av[2 * i], av[2 * i + 1], h, l);
                    int idx = (a_half * 4 + i) * GSTRIDE + a_row;
                    Ah[idx] = h; Al[idx] = l;
                }
            }
            uint4 hh, ll;
            split2(rb0.x, rb1.x, hh.x, ll.x);
            split2(rb0.y, rb1.y, hh.y, ll.y);
            split2(rb0.z, rb1.z, hh.z, ll.z);
            split2(rb0.w, rb1.w, hh.w, ll.w);
            *(uint4*)&Bh[b_k2 * GSTRIDE + b_n0] = hh;
            *(uint4*)&Bl[b_k2 * GSTRIDE + b_n0] = ll;
        }
        __syncthreads();   // single barrier per stage (double buffering)
        if (s + 1 < nk) {
            if constexpr (A_HALF) {
                rah = *(const uint4*)(Ap + (s + 1) * 16);
            } else {
                const float* Ap2 = (const float*)Ap + (s + 1) * 16;
                ra0 = *(const float4*)(Ap2);
                ra1 = *(const float4*)(Ap2 + 4);
            }
            const float* Bp2 = Bp0 + (size_t)(s + 1) * 16 * HDIM;
            rb0 = *(const float4*)(Bp2);
            rb1 = *(const float4*)(Bp2 + HDIM);
        }
        {
            int g = lane >> 2, q = lane & 3;
            uint32_t bhf[8][2], blf[8][2];
#pragma unroll
            for (int nt = 0; nt < 8; nt++) {
                int n = warp_n * 64 + nt * 8 + g;
                bhf[nt][0] = Bh[q * GSTRIDE + n];
                bhf[nt][1] = Bh[(q + 4) * GSTRIDE + n];
                blf[nt][0] = Bl[q * GSTRIDE + n];
                blf[nt][1] = Bl[(q + 4) * GSTRIDE + n];
            }
#pragma unroll
            for (int mt = 0; mt < 2; mt++) {
                int m = warp_m * 32 + mt * 16 + g;
                uint32_t ahf[4], alf[4];
                ahf[0] = Ah[q * GSTRIDE + m];
                ahf[1] = Ah[q * GSTRIDE + m + 8];
                ahf[2] = Ah[(q + 4) * GSTRIDE + m];
                ahf[3] = Ah[(q + 4) * GSTRIDE + m + 8];
                alf[0] = Al[q * GSTRIDE + m];
                alf[1] = Al[q * GSTRIDE + m + 8];
                alf[2] = Al[(q + 4) * GSTRIDE + m];
                alf[3] = Al[(q + 4) * GSTRIDE + m + 8];
#pragma unroll
                for (int nt = 0; nt < 8; nt++) {
                    mma_bf16(acc[mt][nt], ahf, bhf[nt]);
                    mma_bf16(acc[mt][nt], alf, bhf[nt]);
                    mma_bf16(acc[mt][nt], ahf, blf[nt]);
                }
            }
        }
    }

    int g = lane >> 2;
    int cq = (lane & 3) * 2;
    if (linw2 == nullptr) {
#pragma unroll
        for (int mt = 0; mt < 2; mt++) {
            int row = rowBase + warp_m * 32 + mt * 16 + g;
#pragma unroll
            for (int nt = 0; nt < 8; nt++) {
                int col = colBase + warp_n * 64 + nt * 8 + cq;
                float b0 = bias[col], b1 = bias[col + 1];
                float o0x = fmaxf(acc[mt][nt][0] + b0, 0.f);
                float o0y = fmaxf(acc[mt][nt][1] + b1, 0.f);
                float o1x = fmaxf(acc[mt][nt][2] + b0, 0.f);
                float o1y = fmaxf(acc[mt][nt][3] + b1, 0.f);
                if constexpr (sizeof(TC) == 2) {
                    __half2 p0 = __floats2half2_rn(o0x, o0y);
                    __half2 p1 = __floats2half2_rn(o1x, o1y);
                    *(__half2*)((__half*)C + (size_t)row * HDIM + col) = p0;
                    *(__half2*)((__half*)C + (size_t)(row + 8) * HDIM + col) = p1;
                } else {
                    *(float2*)((float*)C + (size_t)row * HDIM + col) = make_float2(o0x, o0y);
                    *(float2*)((float*)C + (size_t)(row + 8) * HDIM + col) = make_float2(o1x, o1y);
                }
            }
        }
    } else {
        int slot = blockIdx.x * 2 + warp_n;
#pragma unroll
        for (int mt = 0; mt < 2; mt++) {
            float s00 = 0.f, s01 = 0.f;
            float s10 = 0.f, s11 = 0.f;
#pragma unroll
            for (int nt = 0; nt < 8; nt++) {
                int col = colBase + warp_n * 64 + nt * 8 + cq;
                float b0 = bias[col], b1 = bias[col + 1];
                float lw00 = linw2[col * 2],     lw01 = linw2[col * 2 + 1];
                float lw10 = linw2[col * 2 + 2], lw11 = linw2[col * 2 + 3];
                float v0 = fmaxf(acc[mt][nt][0] + b0, 0.f);
                float v1 = fmaxf(acc[mt][nt][1] + b1, 0.f);
                float v2 = fmaxf(acc[mt][nt][2] + b0, 0.f);
                float v3 = fmaxf(acc[mt][nt][3] + b1, 0.f);
                s00 += v0 * lw00 + v1 * lw10;
                s01 += v0 * lw01 + v1 * lw11;
                s10 += v2 * lw00 + v3 * lw10;
                s11 += v2 * lw01 + v3 * lw11;
            }
#pragma unroll
            for (int off = 1; off <= 2; off <<= 1) {
                s00 += __shfl_xor_sync(0xffffffffu, s00, off);
                s01 += __shfl_xor_sync(0xffffffffu, s01, off);
                s10 += __shfl_xor_sync(0xffffffffu, s10, off);
                s11 += __shfl_xor_sync(0xffffffffu, s11, off);
            }
            if ((lane & 3) == 0) {
                int row = rowBase + warp_m * 32 + mt * 16 + g;
                float* p0 = part + ((size_t)slot * MPAD2 + row) * 2;
                p0[0] = s00; p0[1] = s01;
                float* p1 = part + ((size_t)slot * MPAD2 + row + 8) * 2;
                p1[0] = s10; p1[1] = s11;
            }
        }
    }
}

// ---------------- reduce lin partials: o[i] = sum_slots part + bias ---------
__global__ void k_linred(const float* __restrict__ b, float* __restrict__ o) {
    int i = blockIdx.x * blockDim.x + threadIdx.x;
    if (i >= NTOT) return;
    float a0 = b[0], a1 = b[1];
#pragma unroll
    for (int s = 0; s < 8; s++) {
        a0 += g_part[s][i][0];
        a1 += g_part[s][i][1];
    }
    o[i * 2] = a0;
    o[i * 2 + 1] = a1;
}

// ---------------- pairwise distance ----------------
__global__ void k_dist() {
    int i = blockIdx.x * blockDim.x + threadIdx.x;
    if (i >= N_NODES) return;
    float dx = g_o[i * 2]     - g_o[(i + N_NODES) * 2]     + 1e-6f;
    float dy = g_o[i * 2 + 1] - g_o[(i + N_NODES) * 2 + 1] + 1e-6f;
    g_dist[i] = sqrtf(dx * dx + dy * dy);
}

// ---------------- top-k select: histogram threshold ----------------
__global__ void k_selhist() {
    __shared__ int hist[2048];
    int t = threadIdx.x;
    hist[t] = 0; hist[t + 1024] = 0;
    for (int i = t; i < SELN; i += 1024) g_sel[i] = -INFINITY;
    if (t == 0) g_selcnt = 0;
    __syncthreads();
    for (int i = t; i < N_NODES; i += 1024) {
        uint32_t bits = __float_as_uint(g_dist[i]);
        atomicAdd(&hist[bits >> 21], 1);
    }
    __syncthreads();
    if (t == 0) {
        int cum = 0, thr = 0;
        for (int b = 2047; b >= 0; b--) {
            cum += hist[b];
            if (cum >= TOPK) { thr = b; break; }
        }
        g_thrbin = thr;
    }
}
__global__ void k_compact() {
    int i = blockIdx.x * blockDim.x + threadIdx.x;
    if (i >= N_NODES) return;
    float d = g_dist[i];
    if ((int)(__float_as_uint(d) >> 21) >= g_thrbin) {
        int pos = atomicAdd(&g_selcnt, 1);
        if (pos < SELN) g_sel[pos] = d;
    }
}
__global__ void k_sortsel() {
    __shared__ float s[SELN];
    int t = threadIdx.x;
    for (int i = t; i < SELN; i += 1024) s[i] = g_sel[i];
    __syncthreads();
    for (int k = 2; k <= SELN; k <<= 1) {
        for (int j = k >> 1; j > 0; j >>= 1) {
            for (int i = t; i < SELN; i += 1024) {
                int ixj = i ^ j;
                if (ixj > i) {
                    bool dsc = (i & k) == 0;
                    float a = s[i], c = s[ixj];
                    bool sw = dsc ? (a < c) : (a > c);
                    if (sw) { s[i] = c; s[ixj] = a; }
                }
            }
            __syncthreads();
        }
    }
    for (int i = t; i < TOPK; i += 1024) g_top[i] = s[i];
}

// ---------------- head MLP ----------------
__global__ void k_mlp(const float* __restrict__ fc1w, const float* __restrict__ fc1b,
                      const float* __restrict__ ln1g, const float* __restrict__ ln1b,
                      const float* __restrict__ fc2w, const float* __restrict__ fc2b,
                      const float* __restrict__ ln2g, const float* __restrict__ ln2b,
                      const float* __restrict__ fc3w, const float* __restrict__ fc3b,
                      float* __restrict__ out) {
    __shared__ float vals[TOPK];
    __shared__ float h1[128];
    __shared__ float part[4][128];
    __shared__ float h2[512];
    __shared__ float red[512];
    int t = threadIdx.x;
    for (int i = t; i < TOPK; i += 512) vals[i] = g_top[i];
    __syncthreads();
    {
        int j = t & 127, c = t >> 7;
        float acc = 0.f;
        for (int i = c * 250; i < (c + 1) * 250; i++) acc += vals[i] * fc1w[i * 128 + j];
        part[c][j] = acc;
    }
    __syncthreads();
    if (t < 128) h1[t] = part[0][t] + part[1][t] + part[2][t] + part[3][t] + fc1b[t];
    __syncthreads();
    red[t] = (t < 128) ? h1[t] : 0.f;
    __syncthreads();
    for (int off = 256; off; off >>= 1) { if (t < off) red[t] += red[t + off]; __syncthreads(); }
    float mean1 = red[0] / 128.f;
    __syncthreads();
    red[t] = (t < 128) ? (h1[t] - mean1) * (h1[t] - mean1) : 0.f;
    __syncthreads();
    for (int off = 256; off; off >>= 1) { if (t < off) red[t] += red[t + off]; __syncthreads(); }
    float var1 = red[0] / 128.f;
    __syncthreads();
    if (t < 128) {
        float v = (h1[t] - mean1) * rsqrtf(var1 + 1e-5f) * ln1g[t] + ln1b[t];
        h1[t] = fmaxf(v, 0.f);
    }
    __syncthreads();
    {
        float acc = fc2b[t];
        for (int i = 0; i < 128; i++) acc += h1[i] * fc2w[i * 512 + t];
        h2[t] = acc;
    }
    __syncthreads();
    red[t] = h2[t];
    __syncthreads();
    for (int off = 256; off; off >>= 1) { if (t < off) red[t] += red[t + off]; __syncthreads(); }
    float mean2 = red[0] / 512.f;
    __syncthreads();
    red[t] = (h2[t] - mean2) * (h2[t] - mean2);
    __syncthreads();
    for (int off = 256; off; off >>= 1) { if (t < off) red[t] += red[t + off]; __syncthreads(); }
    float var2 = red[0] / 512.f;
    __syncthreads();
    float hr = fmaxf((h2[t] - mean2) * rsqrtf(var2 + 1e-5f) * ln2g[t] + ln2b[t], 0.f);
    red[t] = hr * fc3w[t];
    __syncthreads();
    for (int off = 256; off; off >>= 1) { if (t < off) red[t] += red[t + off]; __syncthreads(); }
    if (t == 0) out[0] = 1.f / (1.f + expf(-(red[0] + fc3b[0])));
}

// ---------------- launch ----------------
extern "C" void kernel_launch(void* const* d_in, const int* in_sizes, int n_in,
                              void* d_out, int out_size) {
    const float* x1   = (const float*)d_in[0];
    const int*   ei1  = (const int*)d_in[1];
    const float* x2   = (const float*)d_in[2];
    const int*   ei2  = (const int*)d_in[3];
    const float* w11  = (const float*)d_in[4];
    const float* b11  = (const float*)d_in[5];
    const float* w12  = (const float*)d_in[6];
    const float* b12  = (const float*)d_in[7];
    const float* w21  = (const float*)d_in[8];
    const float* b21  = (const float*)d_in[9];
    const float* w22  = (const float*)d_in[10];
    const float* b22  = (const float*)d_in[11];
    const float* w31  = (const float*)d_in[12];
    const float* b31  = (const float*)d_in[13];
    const float* w32  = (const float*)d_in[14];
    const float* b32  = (const float*)d_in[15];
    const float* linw = (const float*)d_in[16];
    const float* linb = (const float*)d_in[17];
    const float* fc1w = (const float*)d_in[18];
    const float* fc1b = (const float*)d_in[19];
    const float* ln1g = (const float*)d_in[20];
    const float* ln1b = (const float*)d_in[21];
    const float* fc2w = (const float*)d_in[22];
    const float* fc2b = (const float*)d_in[23];
    const float* ln2g = (const float*)d_in[24];
    const float* ln2b = (const float*)d_in[25];
    const float* fc3w = (const float*)d_in[26];
    const float* fc3b = (const float*)d_in[27];
    float* out = (float*)d_out;

    const int* src1 = ei1;
    const int* dst1 = ei1 + N_EDGES;
    const int* src2 = ei2;
    const int* dst2 = ei2 + N_EDGES;

    __half *p_aggh, *p_acth;
    float *p_tmp, *p_o, *p_part;
    cudaGetSymbolAddress((void**)&p_aggh, g_aggh);
    cudaGetSymbolAddress((void**)&p_acth, g_acth);
    cudaGetSymbolAddress((void**)&p_tmp, g_tmp);
    cudaGetSymbolAddress((void**)&p_o, g_o);
    cudaGetSymbolAddress((void**)&p_part, g_part);

    dim3 ggrid(HDIM / 128, MT2);
    const int E2B = (2 * N_EDGES + 255) / 256;
    const int N2B = (NTOT + 255) / 256;
    const int NB = (N_NODES + 255) / 256;
    const int AGB = (NTOT + 7) / 8;

    // batched CSR for both graphs
    k_zero_cnt<<<N2B, 256>>>();
    k_hist2<<<E2B, 256>>>(dst1, dst2);
    k_scan2<<<2, 1024>>>();
    k_fill2<<<E2B, 256>>>(src1, dst1, src2, dst2);

    // layer 1 (FIN=256 -> H): fp32 gather -> fp16 agg -> GEMMs
    k_agg_f2h<<<AGB, 512>>>(x1, x2, p_aggh);
    k_gemm_mma<__half, float><<<ggrid, 256>>>(p_aggh, w11, b11, p_tmp, FIN_DIM, nullptr, nullptr);
    k_gemm_mma<float, __half><<<ggrid, 256>>>(p_tmp, w12, b12, p_acth, HDIM, nullptr, nullptr);
    // layer 2
    k_agg_h2h<<<AGB, 512>>>(p_acth, p_aggh);
    k_gemm_mma<__half, float><<<ggrid, 256>>>(p_aggh, w21, b21, p_tmp, HDIM, nullptr, nullptr);
    k_gemm_mma<float, __half><<<ggrid, 256>>>(p_tmp, w22, b22, p_acth, HDIM, nullptr, nullptr);
    // layer 3
    k_agg_h2h<<<AGB, 512>>>(p_acth, p_aggh);
    k_gemm_mma<__half, float><<<ggrid, 256>>>(p_aggh, w31, b31, p_tmp, HDIM, nullptr, nullptr);
    // last GEMM: fused final linear
    k_gemm_mma<float, float><<<ggrid, 256>>>(p_tmp, w32, b32, (float*)nullptr, HDIM, linw, p_part);
    k_linred<<<N2B, 256>>>(linb, p_o);

    k_dist<<<NB, 256>>>();
    k_selhist<<<1, 1024>>>();
    k_compact<<<NB, 256>>>();
    k_sortsel<<<1, 1024>>>();
    k_mlp<<<1, 512>>>(fc1w, fc1b, ln1g, ln1b, fc2w, fc2b, ln2g, ln2b, fc3w, fc3b, out);
}

// round 12
// speedup vs baseline: 1.4557x; 1.0106x over previous
#include <cuda_runtime.h>
#include <cuda_fp16.h>
#include <math.h>
#include <stdint.h>

#define N_NODES 20000
#define NTOT    40000
#define MPAD2   40192
#define MT2     314
#define N_EDGES 640000
#define FIN_DIM 256
#define HDIM 512
#define TOPK 1000
#define SELN 4096

// ---------------- scratch (static device memory; no allocations) ----------------
__device__ __half g_xh[(size_t)NTOT * FIN_DIM];   // fp16 copy of inputs
__device__ __half g_aggh[(size_t)MPAD2 * HDIM];   // agg outputs (GEMM A operand)
__device__ __half g_acth[(size_t)MPAD2 * HDIM];   // layer outputs consumed by agg
__device__ __half g_tmph[(size_t)MPAD2 * HDIM];   // inter-GEMM fp16 intermediate
__device__ float  g_part[8][MPAD2][2];
__device__ float  g_o[NTOT * 2];
__device__ float  g_dist[N_NODES];
__device__ float  g_sel[SELN];
__device__ float  g_top[TOPK];
__device__ int    g_selcnt;
__device__ int    g_thrbin;
__device__ int    g_cnt[NTOT];
__device__ int    g_rowptr[2 * (N_NODES + 1)];
__device__ int    g_cursor[NTOT];
__device__ int    g_esrc[2 * N_EDGES];

// ---------------- helpers ----------------
__device__ __forceinline__ uint32_t packbf(float lo_e, float hi_o) {
    uint32_t r;
    asm("cvt.rn.bf16x2.f32 %0, %1, %2;" : "=r"(r) : "f"(hi_o), "f"(lo_e));
    return r;
}
__device__ __forceinline__ void split2(float v0, float v1, uint32_t& h, uint32_t& l) {
    h = packbf(v0, v1);
    float h0 = __uint_as_float(h << 16);
    float h1 = __uint_as_float(h & 0xffff0000u);
    l = packbf(v0 - h0, v1 - h1);
}
__device__ __forceinline__ void mma_bf16(float* c, const uint32_t* a, const uint32_t* b) {
    asm volatile(
        "mma.sync.aligned.m16n8k16.row.col.f32.bf16.bf16.f32 "
        "{%0,%1,%2,%3}, {%4,%5,%6,%7}, {%8,%9}, {%0,%1,%2,%3};"
        : "+f"(c[0]), "+f"(c[1]), "+f"(c[2]), "+f"(c[3])
        : "r"(a[0]), "r"(a[1]), "r"(a[2]), "r"(a[3]), "r"(b[0]), "r"(b[1]));
}

// ---------------- CSR build (both graphs, batched) ----------------
__global__ void k_zero_cnt() {
    int i = blockIdx.x * blockDim.x + threadIdx.x;
    if (i < NTOT) g_cnt[i] = 0;
}
__global__ void k_hist2(const int* __restrict__ dst1, const int* __restrict__ dst2) {
    int e = blockIdx.x * blockDim.x + threadIdx.x;
    if (e >= 2 * N_EDGES) return;
    int gph = e >= N_EDGES;
    int le = e - gph * N_EDGES;
    int d = (gph ? dst2 : dst1)[le];
    atomicAdd(&g_cnt[gph * N_NODES + d], 1);
}
__global__ void k_scan2() {
    __shared__ int s[1024];
    __shared__ int carry;
    int t = threadIdx.x;
    int gph = blockIdx.x;
    const int cbase = gph * N_NODES;
    const int rbase = gph * (N_NODES + 1);
    if (t == 0) carry = 0;
    __syncthreads();
    for (int base = 0; base < N_NODES; base += 1024) {
        int v = (base + t < N_NODES) ? g_cnt[cbase + base + t] : 0;
        s[t] = v;
        __syncthreads();
        for (int off = 1; off < 1024; off <<= 1) {
            int a = (t >= off) ? s[t - off] : 0;
            __syncthreads();
            s[t] += a;
            __syncthreads();
        }
        int exc = s[t] - v + carry;
        if (base + t < N_NODES) {
            g_rowptr[rbase + base + t] = exc;
            g_cursor[cbase + base + t] = exc;
        }
        __syncthreads();
        if (t == 0) carry = carry + s[1023];
        __syncthreads();
    }
    if (t == 0) g_rowptr[rbase + N_NODES] = carry;
}
__global__ void k_fill2(const int* __restrict__ src1, const int* __restrict__ dst1,
                        const int* __restrict__ src2, const int* __restrict__ dst2) {
    int e = blockIdx.x * blockDim.x + threadIdx.x;
    if (e >= 2 * N_EDGES) return;
    int gph = e >= N_EDGES;
    int le = e - gph * N_EDGES;
    int d = (gph ? dst2 : dst1)[le];
    int sv = (gph ? src2 : src1)[le];
    int pos = atomicAdd(&g_cursor[gph * N_NODES + d], 1);
    g_esrc[gph * N_EDGES + pos] = sv;
}

// ---------------- input conversion: fp32 x1|x2 -> fp16 g_xh ----------------
__global__ void k_x2h(const float* __restrict__ xa, const float* __restrict__ xb,
                      __half* __restrict__ out) {
    int n = blockIdx.x * blockDim.x + threadIdx.x;   // over NTOT*64 float4s
    if (n >= NTOT * (FIN_DIM / 4)) return;
    int gph = n >= N_NODES * (FIN_DIM / 4);
    int local = n - gph * N_NODES * (FIN_DIM / 4);
    float4 v = ((const float4*)(gph ? xb : xa))[local];
    __half2 h0 = __floats2half2_rn(v.x, v.y);
    __half2 h1 = __floats2half2_rn(v.z, v.w);
    ((uint2*)out)[n] = make_uint2(*(uint32_t*)&h0, *(uint32_t*)&h1);
}

// ---------------- aggregation (fp16 in, fp16 out), templated on F ----------
// TPN = F/8 threads per node (uint4 = 8 halves); 512/TPN nodes per block.
template <int F>
__global__ void k_aggh(const __half* __restrict__ x, __half* __restrict__ out) {
    const int TPN = F / 8;
    const int NPB = 512 / TPN;
    int t = threadIdx.x;
    int node = blockIdx.x * NPB + t / TPN;
    int tf = t % TPN;
    if (node >= NTOT) return;
    int gph = node >= N_NODES;
    int local = node - gph * N_NODES;
    const uint4* x4 = (const uint4*)x;
    float acc[8];
    {
        uint4 v = x4[(size_t)node * TPN + tf];
        float2 f0 = __half22float2(*(__half2*)&v.x);
        float2 f1 = __half22float2(*(__half2*)&v.y);
        float2 f2 = __half22float2(*(__half2*)&v.z);
        float2 f3 = __half22float2(*(__half2*)&v.w);
        acc[0] = f0.x; acc[1] = f0.y; acc[2] = f1.x; acc[3] = f1.y;
        acc[4] = f2.x; acc[5] = f2.y; acc[6] = f3.x; acc[7] = f3.y;
    }
    int beg = g_rowptr[gph * (N_NODES + 1) + local];
    int end = g_rowptr[gph * (N_NODES + 1) + local + 1];
    const int* ep = g_esrc + gph * N_EDGES;
    const size_t gofs = (size_t)gph * N_NODES * TPN;
    int e = beg;
    for (; e + 1 < end; e += 2) {
        int i0 = __ldg(&ep[e]);
        int i1 = __ldg(&ep[e + 1]);
        uint4 v0 = x4[gofs + (size_t)i0 * TPN + tf];
        uint4 v1 = x4[gofs + (size_t)i1 * TPN + tf];
        float2 a0 = __half22float2(*(__half2*)&v0.x), b0 = __half22float2(*(__half2*)&v1.x);
        float2 a1 = __half22float2(*(__half2*)&v0.y), b1 = __half22float2(*(__half2*)&v1.y);
        float2 a2 = __half22float2(*(__half2*)&v0.z), b2 = __half22float2(*(__half2*)&v1.z);
        float2 a3 = __half22float2(*(__half2*)&v0.w), b3 = __half22float2(*(__half2*)&v1.w);
        acc[0] += a0.x + b0.x; acc[1] += a0.y + b0.y;
        acc[2] += a1.x + b1.x; acc[3] += a1.y + b1.y;
        acc[4] += a2.x + b2.x; acc[5] += a2.y + b2.y;
        acc[6] += a3.x + b3.x; acc[7] += a3.y + b3.y;
    }
    if (e < end) {
        int i0 = __ldg(&ep[e]);
        uint4 v0 = x4[gofs + (size_t)i0 * TPN + tf];
        float2 a0 = __half22float2(*(__half2*)&v0.x);
        float2 a1 = __half22float2(*(__half2*)&v0.y);
        float2 a2 = __half22float2(*(__half2*)&v0.z);
        float2 a3 = __half22float2(*(__half2*)&v0.w);
        acc[0] += a0.x; acc[1] += a0.y; acc[2] += a1.x; acc[3] += a1.y;
        acc[4] += a2.x; acc[5] += a2.y; acc[6] += a3.x; acc[7] += a3.y;
    }
    __half2 h0 = __floats2half2_rn(acc[0], acc[1]);
    __half2 h1 = __floats2half2_rn(acc[2], acc[3]);
    __half2 h2 = __floats2half2_rn(acc[4], acc[5]);
    __half2 h3 = __floats2half2_rn(acc[6], acc[7]);
    uint4 u = make_uint4(*(uint32_t*)&h0, *(uint32_t*)&h1,
                         *(uint32_t*)&h2, *(uint32_t*)&h3);
    ((uint4*)out)[(size_t)node * TPN + tf] = u;
}

// ---------------- 3x-bf16 mma.sync GEMM (templated A/C types) --------------
#define GSTRIDE 140
#define GMATW   (8 * GSTRIDE)

template <typename TA, typename TC>
__global__ void __launch_bounds__(256)
k_gemm_mma(const TA* __restrict__ A, const float* __restrict__ W,
           const float* __restrict__ bias, TC* __restrict__ C, int K,
           const float* __restrict__ linw2, float* __restrict__ part) {
    constexpr bool A_HALF = sizeof(TA) == 2;
    __shared__ uint32_t S[2][4][GMATW];
    int t = threadIdx.x, lane = t & 31, wid = t >> 5;
    int warp_m = wid >> 1, warp_n = wid & 1;
    int rowBase = blockIdx.y * 128;
    int colBase = blockIdx.x * 128;

    float acc[2][8][4];
#pragma unroll
    for (int i = 0; i < 2; i++)
#pragma unroll
        for (int j = 0; j < 8; j++)
#pragma unroll
            for (int q = 0; q < 4; q++) acc[i][j][q] = 0.f;

    int a_row = t >> 1;
    int a_half = t & 1;
    int b_k2 = t >> 5;
    int b_n0 = lane * 4;

    const TA* Ap = A + (size_t)(rowBase + a_row) * K + a_half * 8;
    const float* Bp0 = W + (size_t)(2 * b_k2) * HDIM + colBase + b_n0;
    const float* Bp1 = Bp0 + HDIM;

    const int nk = K >> 4;
    float4 ra0, ra1;
    uint4 rah;
    float4 rb0, rb1;

    if constexpr (A_HALF) {
        rah = *(const uint4*)(Ap);
    } else {
        ra0 = *(const float4*)(Ap);
        ra1 = *(const float4*)(Ap + 4);
    }
    rb0 = *(const float4*)(Bp0);
    rb1 = *(const float4*)(Bp1);

    for (int s = 0; s < nk; s++) {
        int buf = s & 1;
        uint32_t* Ah = S[buf][0];
        uint32_t* Al = S[buf][1];
        uint32_t* Bh = S[buf][2];
        uint32_t* Bl = S[buf][3];
        {
            if constexpr (A_HALF) {
                uint32_t words[4] = {rah.x, rah.y, rah.z, rah.w};
#pragma unroll
                for (int i = 0; i < 4; i++) {
                    float2 f = __half22float2(*(__half2*)&words[i]);
                    uint32_t h, l;
                    split2(f.x, f.y, h, l);
                    int idx = (a_half * 4 + i) * GSTRIDE + a_row;
                    Ah[idx] = h; Al[idx] = l;
                }
            } else {
                float av[8] = {ra0.x, ra0.y, ra0.z, ra0.w, ra1.x, ra1.y, ra1.z, ra1.w};
#pragma unroll
                for (int i = 0; i < 4; i++) {
                    uint32_t h, l;
                    split2(av[2 * i], av[2 * i + 1], h, l);
                    int idx = (a_half * 4 + i) * GSTRIDE + a_row;
                    Ah[idx] = h; Al[idx] = l;
                }
            }
            uint4 hh, ll;
            split2(rb0.x, rb1.x, hh.x, ll.x);
            split2(rb0.y, rb1.y, hh.y, ll.y);
            split2(rb0.z, rb1.z, hh.z, ll.z);
            split2(rb0.w, rb1.w, hh.w, ll.w);
            *(uint4*)&Bh[b_k2 * GSTRIDE + b_n0] = hh;
            *(uint4*)&Bl[b_k2 * GSTRIDE + b_n0] = ll;
        }
        __syncthreads();   // single barrier per stage (double buffering)
        if (s + 1 < nk) {
            if constexpr (A_HALF) {
                rah = *(const uint4*)(Ap + (s + 1) * 16);
            } else {
                const float* Ap2 = (const float*)Ap + (s + 1) * 16;
                ra0 = *(const float4*)(Ap2);
                ra1 = *(const float4*)(Ap2 + 4);
            }
            const float* Bp2 = Bp0 + (size_t)(s + 1) * 16 * HDIM;
            rb0 = *(const float4*)(Bp2);
            rb1 = *(const float4*)(Bp2 + HDIM);
        }
        {
            int g = lane >> 2, q = lane & 3;
            uint32_t bhf[8][2], blf[8][2];
#pragma unroll
            for (int nt = 0; nt < 8; nt++) {
                int n = warp_n * 64 + nt * 8 + g;
                bhf[nt][0] = Bh[q * GSTRIDE + n];
                bhf[nt][1] = Bh[(q + 4) * GSTRIDE + n];
                blf[nt][0] = Bl[q * GSTRIDE + n];
                blf[nt][1] = Bl[(q + 4) * GSTRIDE + n];
            }
#pragma unroll
            for (int mt = 0; mt < 2; mt++) {
                int m = warp_m * 32 + mt * 16 + g;
                uint32_t ahf[4], alf[4];
                ahf[0] = Ah[q * GSTRIDE + m];
                ahf[1] = Ah[q * GSTRIDE + m + 8];
                ahf[2] = Ah[(q + 4) * GSTRIDE + m];
                ahf[3] = Ah[(q + 4) * GSTRIDE + m + 8];
                alf[0] = Al[q * GSTRIDE + m];
                alf[1] = Al[q * GSTRIDE + m + 8];
                alf[2] = Al[(q + 4) * GSTRIDE + m];
                alf[3] = Al[(q + 4) * GSTRIDE + m + 8];
#pragma unroll
                for (int nt = 0; nt < 8; nt++) {
                    mma_bf16(acc[mt][nt], ahf, bhf[nt]);
                    mma_bf16(acc[mt][nt], alf, bhf[nt]);
                    mma_bf16(acc[mt][nt], ahf, blf[nt]);
                }
            }
        }
    }

    int g = lane >> 2;
    int cq = (lane & 3) * 2;
    if (linw2 == nullptr) {
#pragma unroll
        for (int mt = 0; mt < 2; mt++) {
            int row = rowBase + warp_m * 32 + mt * 16 + g;
#pragma unroll
            for (int nt = 0; nt < 8; nt++) {
                int col = colBase + warp_n * 64 + nt * 8 + cq;
                float b0 = bias[col], b1 = bias[col + 1];
                float o0x = fmaxf(acc[mt][nt][0] + b0, 0.f);
                float o0y = fmaxf(acc[mt][nt][1] + b1, 0.f);
                float o1x = fmaxf(acc[mt][nt][2] + b0, 0.f);
                float o1y = fmaxf(acc[mt][nt][3] + b1, 0.f);
                if constexpr (sizeof(TC) == 2) {
                    __half2 p0 = __floats2half2_rn(o0x, o0y);
                    __half2 p1 = __floats2half2_rn(o1x, o1y);
                    *(__half2*)((__half*)C + (size_t)row * HDIM + col) = p0;
                    *(__half2*)((__half*)C + (size_t)(row + 8) * HDIM + col) = p1;
                } else {
                    *(float2*)((float*)C + (size_t)row * HDIM + col) = make_float2(o0x, o0y);
                    *(float2*)((float*)C + (size_t)(row + 8) * HDIM + col) = make_float2(o1x, o1y);
                }
            }
        }
    } else {
        int slot = blockIdx.x * 2 + warp_n;
#pragma unroll
        for (int mt = 0; mt < 2; mt++) {
            float s00 = 0.f, s01 = 0.f;
            float s10 = 0.f, s11 = 0.f;
#pragma unroll
            for (int nt = 0; nt < 8; nt++) {
                int col = colBase + warp_n * 64 + nt * 8 + cq;
                float b0 = bias[col], b1 = bias[col + 1];
                float lw00 = linw2[col * 2],     lw01 = linw2[col * 2 + 1];
                float lw10 = linw2[col * 2 + 2], lw11 = linw2[col * 2 + 3];
                float v0 = fmaxf(acc[mt][nt][0] + b0, 0.f);
                float v1 = fmaxf(acc[mt][nt][1] + b1, 0.f);
                float v2 = fmaxf(acc[mt][nt][2] + b0, 0.f);
                float v3 = fmaxf(acc[mt][nt][3] + b1, 0.f);
                s00 += v0 * lw00 + v1 * lw10;
                s01 += v0 * lw01 + v1 * lw11;
                s10 += v2 * lw00 + v3 * lw10;
                s11 += v2 * lw01 + v3 * lw11;
            }
#pragma unroll
            for (int off = 1; off <= 2; off <<= 1) {
                s00 += __shfl_xor_sync(0xffffffffu, s00, off);
                s01 += __shfl_xor_sync(0xffffffffu, s01, off);
                s10 += __shfl_xor_sync(0xffffffffu, s10, off);
                s11 += __shfl_xor_sync(0xffffffffu, s11, off);
            }
            if ((lane & 3) == 0) {
                int row = rowBase + warp_m * 32 + mt * 16 + g;
                float* p0 = part + ((size_t)slot * MPAD2 + row) * 2;
                p0[0] = s00; p0[1] = s01;
                float* p1 = part + ((size_t)slot * MPAD2 + row + 8) * 2;
                p1[0] = s10; p1[1] = s11;
            }
        }
    }
}

// ---------------- reduce lin partials: o[i] = sum_slots part + bias ---------
__global__ void k_linred(const float* __restrict__ b, float* __restrict__ o) {
    int i = blockIdx.x * blockDim.x + threadIdx.x;
    if (i >= NTOT) return;
    float a0 = b[0], a1 = b[1];
#pragma unroll
    for (int s = 0; s < 8; s++) {
        a0 += g_part[s][i][0];
        a1 += g_part[s][i][1];
    }
    o[i * 2] = a0;
    o[i * 2 + 1] = a1;
}

// ---------------- pairwise distance ----------------
__global__ void k_dist() {
    int i = blockIdx.x * blockDim.x + threadIdx.x;
    if (i >= N_NODES) return;
    float dx = g_o[i * 2]     - g_o[(i + N_NODES) * 2]     + 1e-6f;
    float dy = g_o[i * 2 + 1] - g_o[(i + N_NODES) * 2 + 1] + 1e-6f;
    g_dist[i] = sqrtf(dx * dx + dy * dy);
}

// ---------------- top-k select: histogram threshold ----------------
__global__ void k_selhist() {
    __shared__ int hist[2048];
    int t = threadIdx.x;
    hist[t] = 0; hist[t + 1024] = 0;
    for (int i = t; i < SELN; i += 1024) g_sel[i] = -INFINITY;
    if (t == 0) g_selcnt = 0;
    __syncthreads();
    for (int i = t; i < N_NODES; i += 1024) {
        uint32_t bits = __float_as_uint(g_dist[i]);
        atomicAdd(&hist[bits >> 21], 1);
    }
    __syncthreads();
    if (t == 0) {
        int cum = 0, thr = 0;
        for (int b = 2047; b >= 0; b--) {
            cum += hist[b];
            if (cum >= TOPK) { thr = b; break; }
        }
        g_thrbin = thr;
    }
}
__global__ void k_compact() {
    int i = blockIdx.x * blockDim.x + threadIdx.x;
    if (i >= N_NODES) return;
    float d = g_dist[i];
    if ((int)(__float_as_uint(d) >> 21) >= g_thrbin) {
        int pos = atomicAdd(&g_selcnt, 1);
        if (pos < SELN) g_sel[pos] = d;
    }
}
__global__ void k_sortsel() {
    __shared__ float s[SELN];
    int t = threadIdx.x;
    for (int i = t; i < SELN; i += 1024) s[i] = g_sel[i];
    __syncthreads();
    for (int k = 2; k <= SELN; k <<= 1) {
        for (int j = k >> 1; j > 0; j >>= 1) {
            for (int i = t; i < SELN; i += 1024) {
                int ixj = i ^ j;
                if (ixj > i) {
                    bool dsc = (i & k) == 0;
                    float a = s[i], c = s[ixj];
                    bool sw = dsc ? (a < c) : (a > c);
                    if (sw) { s[i] = c; s[ixj] = a; }
                }
            }
            __syncthreads();
        }
    }
    for (int i = t; i < TOPK; i += 1024) g_top[i] = s[i];
}

// ---------------- head MLP ----------------
__global__ void k_mlp(const float* __restrict__ fc1w, const float* __restrict__ fc1b,
                      const float* __restrict__ ln1g, const float* __restrict__ ln1b,
                      const float* __restrict__ fc2w, const float* __restrict__ fc2b,
                      const float* __restrict__ ln2g, const float* __restrict__ ln2b,
                      const float* __restrict__ fc3w, const float* __restrict__ fc3b,
                      float* __restrict__ out) {
    __shared__ float vals[TOPK];
    __shared__ float h1[128];
    __shared__ float part[4][128];
    __shared__ float h2[512];
    __shared__ float red[512];
    int t = threadIdx.x;
    for (int i = t; i < TOPK; i += 512) vals[i] = g_top[i];
    __syncthreads();
    {
        int j = t & 127, c = t >> 7;
        float acc = 0.f;
        for (int i = c * 250; i < (c + 1) * 250; i++) acc += vals[i] * fc1w[i * 128 + j];
        part[c][j] = acc;
    }
    __syncthreads();
    if (t < 128) h1[t] = part[0][t] + part[1][t] + part[2][t] + part[3][t] + fc1b[t];
    __syncthreads();
    red[t] = (t < 128) ? h1[t] : 0.f;
    __syncthreads();
    for (int off = 256; off; off >>= 1) { if (t < off) red[t] += red[t + off]; __syncthreads(); }
    float mean1 = red[0] / 128.f;
    __syncthreads();
    red[t] = (t < 128) ? (h1[t] - mean1) * (h1[t] - mean1) : 0.f;
    __syncthreads();
    for (int off = 256; off; off >>= 1) { if (t < off) red[t] += red[t + off]; __syncthreads(); }
    float var1 = red[0] / 128.f;
    __syncthreads();
    if (t < 128) {
        float v = (h1[t] - mean1) * rsqrtf(var1 + 1e-5f) * ln1g[t] + ln1b[t];
        h1[t] = fmaxf(v, 0.f);
    }
    __syncthreads();
    {
        float acc = fc2b[t];
        for (int i = 0; i < 128; i++) acc += h1[i] * fc2w[i * 512 + t];
        h2[t] = acc;
    }
    __syncthreads();
    red[t] = h2[t];
    __syncthreads();
    for (int off = 256; off; off >>= 1) { if (t < off) red[t] += red[t + off]; __syncthreads(); }
    float mean2 = red[0] / 512.f;
    __syncthreads();
    red[t] = (h2[t] - mean2) * (h2[t] - mean2);
    __syncthreads();
    for (int off = 256; off; off >>= 1) { if (t < off) red[t] += red[t + off]; __syncthreads(); }
    float var2 = red[0] / 512.f;
    __syncthreads();
    float hr = fmaxf((h2[t] - mean2) * rsqrtf(var2 + 1e-5f) * ln2g[t] + ln2b[t], 0.f);
    red[t] = hr * fc3w[t];
    __syncthreads();
    for (int off = 256; off; off >>= 1) { if (t < off) red[t] += red[t + off]; __syncthreads(); }
    if (t == 0) out[0] = 1.f / (1.f + expf(-(red[0] + fc3b[0])));
}

// ---------------- launch ----------------
extern "C" void kernel_launch(void* const* d_in, const int* in_sizes, int n_in,
                              void* d_out, int out_size) {
    const float* x1   = (const float*)d_in[0];
    const int*   ei1  = (const int*)d_in[1];
    const float* x2   = (const float*)d_in[2];
    const int*   ei2  = (const int*)d_in[3];
    const float* w11  = (const float*)d_in[4];
    const float* b11  = (const float*)d_in[5];
    const float* w12  = (const float*)d_in[6];
    const float* b12  = (const float*)d_in[7];
    const float* w21  = (const float*)d_in[8];
    const float* b21  = (const float*)d_in[9];
    const float* w22  = (const float*)d_in[10];
    const float* b22  = (const float*)d_in[11];
    const float* w31  = (const float*)d_in[12];
    const float* b31  = (const float*)d_in[13];
    const float* w32  = (const float*)d_in[14];
    const float* b32  = (const float*)d_in[15];
    const float* linw = (const float*)d_in[16];
    const float* linb = (const float*)d_in[17];
    const float* fc1w = (const float*)d_in[18];
    const float* fc1b = (const float*)d_in[19];
    const float* ln1g = (const float*)d_in[20];
    const float* ln1b = (const float*)d_in[21];
    const float* fc2w = (const float*)d_in[22];
    const float* fc2b = (const float*)d_in[23];
    const float* ln2g = (const float*)d_in[24];
    const float* ln2b = (const float*)d_in[25];
    const float* fc3w = (const float*)d_in[26];
    const float* fc3b = (const float*)d_in[27];
    float* out = (float*)d_out;

    const int* src1 = ei1;
    const int* dst1 = ei1 + N_EDGES;
    const int* src2 = ei2;
    const int* dst2 = ei2 + N_EDGES;

    __half *p_xh, *p_aggh, *p_acth, *p_tmph;
    float *p_o, *p_part;
    cudaGetSymbolAddress((void**)&p_xh, g_xh);
    cudaGetSymbolAddress((void**)&p_aggh, g_aggh);
    cudaGetSymbolAddress((void**)&p_acth, g_acth);
    cudaGetSymbolAddress((void**)&p_tmph, g_tmph);
    cudaGetSymbolAddress((void**)&p_o, g_o);
    cudaGetSymbolAddress((void**)&p_part, g_part);

    dim3 ggrid(HDIM / 128, MT2);
    const int E2B = (2 * N_EDGES + 255) / 256;
    const int N2B = (NTOT + 255) / 256;
    const int NB = (N_NODES + 255) / 256;
    const int AGB512 = (NTOT + 7) / 8;      // F=512: 8 nodes/block
    const int AGB256 = (NTOT + 15) / 16;    // F=256: 16 nodes/block
    const int XCB = (NTOT * (FIN_DIM / 4) + 255) / 256;

    // batched CSR for both graphs
    k_zero_cnt<<<N2B, 256>>>();
    k_hist2<<<E2B, 256>>>(dst1, dst2);
    k_scan2<<<2, 1024>>>();
    k_fill2<<<E2B, 256>>>(src1, dst1, src2, dst2);

    // convert inputs to fp16 (overlaps CSR build — independent)
    k_x2h<<<XCB, 256>>>(x1, x2, p_xh);

    // layer 1 (FIN=256 -> H)
    k_aggh<FIN_DIM><<<AGB256, 512>>>(p_xh, p_aggh);
    k_gemm_mma<__half, __half><<<ggrid, 256>>>(p_aggh, w11, b11, p_tmph, FIN_DIM, nullptr, nullptr);
    k_gemm_mma<__half, __half><<<ggrid, 256>>>(p_tmph, w12, b12, p_acth, HDIM, nullptr, nullptr);
    // layer 2
    k_aggh<HDIM><<<AGB512, 512>>>(p_acth, p_aggh);
    k_gemm_mma<__half, __half><<<ggrid, 256>>>(p_aggh, w21, b21, p_tmph, HDIM, nullptr, nullptr);
    k_gemm_mma<__half, __half><<<ggrid, 256>>>(p_tmph, w22, b22, p_acth, HDIM, nullptr, nullptr);
    // layer 3
    k_aggh<HDIM><<<AGB512, 512>>>(p_acth, p_aggh);
    k_gemm_mma<__half, __half><<<ggrid, 256>>>(p_aggh, w31, b31, p_tmph, HDIM, nullptr, nullptr);
    // last GEMM: fused final linear
    k_gemm_mma<__half, float><<<ggrid, 256>>>(p_tmph, w32, b32, (float*)nullptr, HDIM, linw, p_part);
    k_linred<<<N2B, 256>>>(linb, p_o);

    k_dist<<<NB, 256>>>();
    k_selhist<<<1, 1024>>>();
    k_compact<<<NB, 256>>>();
    k_sortsel<<<1, 1024>>>();
    k_mlp<<<1, 512>>>(fc1w, fc1b, ln1g, ln1b, fc2w, fc2b, ln2g, ln2b, fc3w, fc3b, out);
}

// round 13
// speedup vs baseline: 1.7221x; 1.1830x over previous
#include <cuda_runtime.h>
#include <cuda_fp16.h>
#include <math.h>
#include <stdint.h>

#define N_NODES 20000
#define NTOT    40000
#define MPAD2   40192
#define MT2     314
#define N_EDGES 640000
#define FIN_DIM 256
#define HDIM 512
#define TOPK 1000
#define SELN 4096

// ---------------- scratch (static device memory; no allocations) ----------------
__device__ __half g_xh[(size_t)NTOT * FIN_DIM];   // fp16 copy of inputs
__device__ __half g_aggh[(size_t)MPAD2 * HDIM];   // agg outputs (GEMM A operand)
__device__ __half g_acth[(size_t)MPAD2 * HDIM];   // layer outputs consumed by agg
__device__ __half g_tmph[(size_t)MPAD2 * HDIM];   // inter-GEMM fp16 intermediate
__device__ float  g_part[8][MPAD2][2];
__device__ float  g_o[NTOT * 2];
__device__ float  g_dist[N_NODES];
__device__ float  g_sel[SELN];
__device__ float  g_top[TOPK];
__device__ int    g_selcnt;
__device__ int    g_thrbin;
__device__ int    g_cnt[NTOT];
__device__ int    g_rowptr[2 * (N_NODES + 1)];
__device__ int    g_cursor[NTOT];
__device__ int    g_esrc[2 * N_EDGES];

// ---------------- helpers ----------------
// split a k-pair of fp32 (v0=k even, v1=k odd) into fp16 hi + fp16 lo words
__device__ __forceinline__ void split2h(float v0, float v1, uint32_t& h, uint32_t& l) {
    __half2 hh = __floats2half2_rn(v0, v1);
    h = *(uint32_t*)&hh;
    float2 hf = __half22float2(hh);
    __half2 ll = __floats2half2_rn(v0 - hf.x, v1 - hf.y);
    l = *(uint32_t*)&ll;
}
__device__ __forceinline__ void mma_f16(float* c, const uint32_t* a, const uint32_t* b) {
    asm volatile(
        "mma.sync.aligned.m16n8k16.row.col.f32.f16.f16.f32 "
        "{%0,%1,%2,%3}, {%4,%5,%6,%7}, {%8,%9}, {%0,%1,%2,%3};"
        : "+f"(c[0]), "+f"(c[1]), "+f"(c[2]), "+f"(c[3])
        : "r"(a[0]), "r"(a[1]), "r"(a[2]), "r"(a[3]), "r"(b[0]), "r"(b[1]));
}

// ---------------- CSR build (both graphs, batched) ----------------
__global__ void k_zero_cnt() {
    int i = blockIdx.x * blockDim.x + threadIdx.x;
    if (i < NTOT) g_cnt[i] = 0;
}
__global__ void k_hist2(const int* __restrict__ dst1, const int* __restrict__ dst2) {
    int e = blockIdx.x * blockDim.x + threadIdx.x;
    if (e >= 2 * N_EDGES) return;
    int gph = e >= N_EDGES;
    int le = e - gph * N_EDGES;
    int d = (gph ? dst2 : dst1)[le];
    atomicAdd(&g_cnt[gph * N_NODES + d], 1);
}
__global__ void k_scan2() {
    __shared__ int s[1024];
    __shared__ int carry;
    int t = threadIdx.x;
    int gph = blockIdx.x;
    const int cbase = gph * N_NODES;
    const int rbase = gph * (N_NODES + 1);
    if (t == 0) carry = 0;
    __syncthreads();
    for (int base = 0; base < N_NODES; base += 1024) {
        int v = (base + t < N_NODES) ? g_cnt[cbase + base + t] : 0;
        s[t] = v;
        __syncthreads();
        for (int off = 1; off < 1024; off <<= 1) {
            int a = (t >= off) ? s[t - off] : 0;
            __syncthreads();
            s[t] += a;
            __syncthreads();
        }
        int exc = s[t] - v + carry;
        if (base + t < N_NODES) {
            g_rowptr[rbase + base + t] = exc;
            g_cursor[cbase + base + t] = exc;
        }
        __syncthreads();
        if (t == 0) carry = carry + s[1023];
        __syncthreads();
    }
    if (t == 0) g_rowptr[rbase + N_NODES] = carry;
}
__global__ void k_fill2(const int* __restrict__ src1, const int* __restrict__ dst1,
                        const int* __restrict__ src2, const int* __restrict__ dst2) {
    int e = blockIdx.x * blockDim.x + threadIdx.x;
    if (e >= 2 * N_EDGES) return;
    int gph = e >= N_EDGES;
    int le = e - gph * N_EDGES;
    int d = (gph ? dst2 : dst1)[le];
    int sv = (gph ? src2 : src1)[le];
    int pos = atomicAdd(&g_cursor[gph * N_NODES + d], 1);
    g_esrc[gph * N_EDGES + pos] = sv;
}

// ---------------- input conversion: fp32 x1|x2 -> fp16 g_xh ----------------
__global__ void k_x2h(const float* __restrict__ xa, const float* __restrict__ xb,
                      __half* __restrict__ out) {
    int n = blockIdx.x * blockDim.x + threadIdx.x;
    if (n >= NTOT * (FIN_DIM / 4)) return;
    int gph = n >= N_NODES * (FIN_DIM / 4);
    int local = n - gph * N_NODES * (FIN_DIM / 4);
    float4 v = ((const float4*)(gph ? xb : xa))[local];
    __half2 h0 = __floats2half2_rn(v.x, v.y);
    __half2 h1 = __floats2half2_rn(v.z, v.w);
    ((uint2*)out)[n] = make_uint2(*(uint32_t*)&h0, *(uint32_t*)&h1);
}

// ---------------- aggregation (fp16 in, fp16 out), templated on F ----------
template <int F>
__global__ void k_aggh(const __half* __restrict__ x, __half* __restrict__ out) {
    const int TPN = F / 8;
    const int NPB = 512 / TPN;
    int t = threadIdx.x;
    int node = blockIdx.x * NPB + t / TPN;
    int tf = t % TPN;
    if (node >= NTOT) return;
    int gph = node >= N_NODES;
    int local = node - gph * N_NODES;
    const uint4* x4 = (const uint4*)x;
    float acc[8];
    {
        uint4 v = x4[(size_t)node * TPN + tf];
        float2 f0 = __half22float2(*(__half2*)&v.x);
        float2 f1 = __half22float2(*(__half2*)&v.y);
        float2 f2 = __half22float2(*(__half2*)&v.z);
        float2 f3 = __half22float2(*(__half2*)&v.w);
        acc[0] = f0.x; acc[1] = f0.y; acc[2] = f1.x; acc[3] = f1.y;
        acc[4] = f2.x; acc[5] = f2.y; acc[6] = f3.x; acc[7] = f3.y;
    }
    int beg = g_rowptr[gph * (N_NODES + 1) + local];
    int end = g_rowptr[gph * (N_NODES + 1) + local + 1];
    const int* ep = g_esrc + gph * N_EDGES;
    const size_t gofs = (size_t)gph * N_NODES * TPN;
    int e = beg;
    for (; e + 1 < end; e += 2) {
        int i0 = __ldg(&ep[e]);
        int i1 = __ldg(&ep[e + 1]);
        uint4 v0 = x4[gofs + (size_t)i0 * TPN + tf];
        uint4 v1 = x4[gofs + (size_t)i1 * TPN + tf];
        float2 a0 = __half22float2(*(__half2*)&v0.x), b0 = __half22float2(*(__half2*)&v1.x);
        float2 a1 = __half22float2(*(__half2*)&v0.y), b1 = __half22float2(*(__half2*)&v1.y);
        float2 a2 = __half22float2(*(__half2*)&v0.z), b2 = __half22float2(*(__half2*)&v1.z);
        float2 a3 = __half22float2(*(__half2*)&v0.w), b3 = __half22float2(*(__half2*)&v1.w);
        acc[0] += a0.x + b0.x; acc[1] += a0.y + b0.y;
        acc[2] += a1.x + b1.x; acc[3] += a1.y + b1.y;
        acc[4] += a2.x + b2.x; acc[5] += a2.y + b2.y;
        acc[6] += a3.x + b3.x; acc[7] += a3.y + b3.y;
    }
    if (e < end) {
        int i0 = __ldg(&ep[e]);
        uint4 v0 = x4[gofs + (size_t)i0 * TPN + tf];
        float2 a0 = __half22float2(*(__half2*)&v0.x);
        float2 a1 = __half22float2(*(__half2*)&v0.y);
        float2 a2 = __half22float2(*(__half2*)&v0.z);
        float2 a3 = __half22float2(*(__half2*)&v0.w);
        acc[0] += a0.x; acc[1] += a0.y; acc[2] += a1.x; acc[3] += a1.y;
        acc[4] += a2.x; acc[5] += a2.y; acc[6] += a3.x; acc[7] += a3.y;
    }
    __half2 h0 = __floats2half2_rn(acc[0], acc[1]);
    __half2 h1 = __floats2half2_rn(acc[2], acc[3]);
    __half2 h2 = __floats2half2_rn(acc[4], acc[5]);
    __half2 h3 = __floats2half2_rn(acc[6], acc[7]);
    uint4 u = make_uint4(*(uint32_t*)&h0, *(uint32_t*)&h1,
                         *(uint32_t*)&h2, *(uint32_t*)&h3);
    ((uint4*)out)[(size_t)node * TPN + tf] = u;
}

// ---------------- 2-pass fp16 mma.sync GEMM: C = relu(A @ W + b) -----------
// A fp16 (exact, single piece); B fp32 split to fp16 hi/lo (2 MMA passes).
// Block 128x128x16, 256 thr, single barrier per stage.
#define GSTRIDE 140
#define GMATW   (8 * GSTRIDE)

template <typename TC>
__global__ void __launch_bounds__(256)
k_gemm_mma(const __half* __restrict__ A, const float* __restrict__ W,
           const float* __restrict__ bias, TC* __restrict__ C, int K,
           const float* __restrict__ linw2, float* __restrict__ part) {
    __shared__ uint32_t S[2][3][GMATW];
    int t = threadIdx.x, lane = t & 31, wid = t >> 5;
    int warp_m = wid >> 1, warp_n = wid & 1;
    int rowBase = blockIdx.y * 128;
    int colBase = blockIdx.x * 128;

    float acc[2][8][4];
#pragma unroll
    for (int i = 0; i < 2; i++)
#pragma unroll
        for (int j = 0; j < 8; j++)
#pragma unroll
            for (int q = 0; q < 4; q++) acc[i][j][q] = 0.f;

    int a_row = t >> 1;
    int a_half = t & 1;
    int b_k2 = t >> 5;
    int b_n0 = lane * 4;

    const __half* Ap = A + (size_t)(rowBase + a_row) * K + a_half * 8;
    const float* Bp0 = W + (size_t)(2 * b_k2) * HDIM + colBase + b_n0;
    const float* Bp1 = Bp0 + HDIM;

    const int nk = K >> 4;
    uint4 rah;
    float4 rb0, rb1;

    rah = *(const uint4*)(Ap);
    rb0 = *(const float4*)(Bp0);
    rb1 = *(const float4*)(Bp1);

    for (int s = 0; s < nk; s++) {
        int buf = s & 1;
        uint32_t* Aw = S[buf][0];
        uint32_t* Bh = S[buf][1];
        uint32_t* Bl = S[buf][2];
        {
            // A: raw fp16 k-pairs, no conversion needed
            Aw[(a_half * 4 + 0) * GSTRIDE + a_row] = rah.x;
            Aw[(a_half * 4 + 1) * GSTRIDE + a_row] = rah.y;
            Aw[(a_half * 4 + 2) * GSTRIDE + a_row] = rah.z;
            Aw[(a_half * 4 + 3) * GSTRIDE + a_row] = rah.w;
            uint4 hh, ll;
            split2h(rb0.x, rb1.x, hh.x, ll.x);
            split2h(rb0.y, rb1.y, hh.y, ll.y);
            split2h(rb0.z, rb1.z, hh.z, ll.z);
            split2h(rb0.w, rb1.w, hh.w, ll.w);
            *(uint4*)&Bh[b_k2 * GSTRIDE + b_n0] = hh;
            *(uint4*)&Bl[b_k2 * GSTRIDE + b_n0] = ll;
        }
        __syncthreads();   // single barrier per stage (double buffering)
        if (s + 1 < nk) {
            rah = *(const uint4*)(Ap + (s + 1) * 16);
            const float* Bp2 = Bp0 + (size_t)(s + 1) * 16 * HDIM;
            rb0 = *(const float4*)(Bp2);
            rb1 = *(const float4*)(Bp2 + HDIM);
        }
        {
            int g = lane >> 2, q = lane & 3;
            uint32_t bhf[8][2], blf[8][2];
#pragma unroll
            for (int nt = 0; nt < 8; nt++) {
                int n = warp_n * 64 + nt * 8 + g;
                bhf[nt][0] = Bh[q * GSTRIDE + n];
                bhf[nt][1] = Bh[(q + 4) * GSTRIDE + n];
                blf[nt][0] = Bl[q * GSTRIDE + n];
                blf[nt][1] = Bl[(q + 4) * GSTRIDE + n];
            }
#pragma unroll
            for (int mt = 0; mt < 2; mt++) {
                int m = warp_m * 32 + mt * 16 + g;
                uint32_t ahf[4];
                ahf[0] = Aw[q * GSTRIDE + m];
                ahf[1] = Aw[q * GSTRIDE + m + 8];
                ahf[2] = Aw[(q + 4) * GSTRIDE + m];
                ahf[3] = Aw[(q + 4) * GSTRIDE + m + 8];
#pragma unroll
                for (int nt = 0; nt < 8; nt++) {
                    mma_f16(acc[mt][nt], ahf, bhf[nt]);
                    mma_f16(acc[mt][nt], ahf, blf[nt]);
                }
            }
        }
    }

    int g = lane >> 2;
    int cq = (lane & 3) * 2;
    if (linw2 == nullptr) {
#pragma unroll
        for (int mt = 0; mt < 2; mt++) {
            int row = rowBase + warp_m * 32 + mt * 16 + g;
#pragma unroll
            for (int nt = 0; nt < 8; nt++) {
                int col = colBase + warp_n * 64 + nt * 8 + cq;
                float b0 = bias[col], b1 = bias[col + 1];
                float o0x = fmaxf(acc[mt][nt][0] + b0, 0.f);
                float o0y = fmaxf(acc[mt][nt][1] + b1, 0.f);
                float o1x = fmaxf(acc[mt][nt][2] + b0, 0.f);
                float o1y = fmaxf(acc[mt][nt][3] + b1, 0.f);
                if constexpr (sizeof(TC) == 2) {
                    __half2 p0 = __floats2half2_rn(o0x, o0y);
                    __half2 p1 = __floats2half2_rn(o1x, o1y);
                    *(__half2*)((__half*)C + (size_t)row * HDIM + col) = p0;
                    *(__half2*)((__half*)C + (size_t)(row + 8) * HDIM + col) = p1;
                } else {
                    *(float2*)((float*)C + (size_t)row * HDIM + col) = make_float2(o0x, o0y);
                    *(float2*)((float*)C + (size_t)(row + 8) * HDIM + col) = make_float2(o1x, o1y);
                }
            }
        }
    } else {
        int slot = blockIdx.x * 2 + warp_n;
#pragma unroll
        for (int mt = 0; mt < 2; mt++) {
            float s00 = 0.f, s01 = 0.f;
            float s10 = 0.f, s11 = 0.f;
#pragma unroll
            for (int nt = 0; nt < 8; nt++) {
                int col = colBase + warp_n * 64 + nt * 8 + cq;
                float b0 = bias[col], b1 = bias[col + 1];
                float lw00 = linw2[col * 2],     lw01 = linw2[col * 2 + 1];
                float lw10 = linw2[col * 2 + 2], lw11 = linw2[col * 2 + 3];
                float v0 = fmaxf(acc[mt][nt][0] + b0, 0.f);
                float v1 = fmaxf(acc[mt][nt][1] + b1, 0.f);
                float v2 = fmaxf(acc[mt][nt][2] + b0, 0.f);
                float v3 = fmaxf(acc[mt][nt][3] + b1, 0.f);
                s00 += v0 * lw00 + v1 * lw10;
                s01 += v0 * lw01 + v1 * lw11;
                s10 += v2 * lw00 + v3 * lw10;
                s11 += v2 * lw01 + v3 * lw11;
            }
#pragma unroll
            for (int off = 1; off <= 2; off <<= 1) {
                s00 += __shfl_xor_sync(0xffffffffu, s00, off);
                s01 += __shfl_xor_sync(0xffffffffu, s01, off);
                s10 += __shfl_xor_sync(0xffffffffu, s10, off);
                s11 += __shfl_xor_sync(0xffffffffu, s11, off);
            }
            if ((lane & 3) == 0) {
                int row = rowBase + warp_m * 32 + mt * 16 + g;
                float* p0 = part + ((size_t)slot * MPAD2 + row) * 2;
                p0[0] = s00; p0[1] = s01;
                float* p1 = part + ((size_t)slot * MPAD2 + row + 8) * 2;
                p1[0] = s10; p1[1] = s11;
            }
        }
    }
}

// ---------------- reduce lin partials: o[i] = sum_slots part + bias ---------
__global__ void k_linred(const float* __restrict__ b, float* __restrict__ o) {
    int i = blockIdx.x * blockDim.x + threadIdx.x;
    if (i >= NTOT) return;
    float a0 = b[0], a1 = b[1];
#pragma unroll
    for (int s = 0; s < 8; s++) {
        a0 += g_part[s][i][0];
        a1 += g_part[s][i][1];
    }
    o[i * 2] = a0;
    o[i * 2 + 1] = a1;
}

// ---------------- pairwise distance ----------------
__global__ void k_dist() {
    int i = blockIdx.x * blockDim.x + threadIdx.x;
    if (i >= N_NODES) return;
    float dx = g_o[i * 2]     - g_o[(i + N_NODES) * 2]     + 1e-6f;
    float dy = g_o[i * 2 + 1] - g_o[(i + N_NODES) * 2 + 1] + 1e-6f;
    g_dist[i] = sqrtf(dx * dx + dy * dy);
}

// ---------------- top-k select: histogram threshold ----------------
__global__ void k_selhist() {
    __shared__ int hist[2048];
    int t = threadIdx.x;
    hist[t] = 0; hist[t + 1024] = 0;
    for (int i = t; i < SELN; i += 1024) g_sel[i] = -INFINITY;
    if (t == 0) g_selcnt = 0;
    __syncthreads();
    for (int i = t; i < N_NODES; i += 1024) {
        uint32_t bits = __float_as_uint(g_dist[i]);
        atomicAdd(&hist[bits >> 21], 1);
    }
    __syncthreads();
    if (t == 0) {
        int cum = 0, thr = 0;
        for (int b = 2047; b >= 0; b--) {
            cum += hist[b];
            if (cum >= TOPK) { thr = b; break; }
        }
        g_thrbin = thr;
    }
}
__global__ void k_compact() {
    int i = blockIdx.x * blockDim.x + threadIdx.x;
    if (i >= N_NODES) return;
    float d = g_dist[i];
    if ((int)(__float_as_uint(d) >> 21) >= g_thrbin) {
        int pos = atomicAdd(&g_selcnt, 1);
        if (pos < SELN) g_sel[pos] = d;
    }
}
__global__ void k_sortsel() {
    __shared__ float s[SELN];
    int t = threadIdx.x;
    for (int i = t; i < SELN; i += 1024) s[i] = g_sel[i];
    __syncthreads();
    for (int k = 2; k <= SELN; k <<= 1) {
        for (int j = k >> 1; j > 0; j >>= 1) {
            for (int i = t; i < SELN; i += 1024) {
                int ixj = i ^ j;
                if (ixj > i) {
                    bool dsc = (i & k) == 0;
                    float a = s[i], c = s[ixj];
                    bool sw = dsc ? (a < c) : (a > c);
                    if (sw) { s[i] = c; s[ixj] = a; }
                }
            }
            __syncthreads();
        }
    }
    for (int i = t; i < TOPK; i += 1024) g_top[i] = s[i];
}

// ---------------- head MLP ----------------
__global__ void k_mlp(const float* __restrict__ fc1w, const float* __restrict__ fc1b,
                      const float* __restrict__ ln1g, const float* __restrict__ ln1b,
                      const float* __restrict__ fc2w, const float* __restrict__ fc2b,
                      const float* __restrict__ ln2g, const float* __restrict__ ln2b,
                      const float* __restrict__ fc3w, const float* __restrict__ fc3b,
                      float* __restrict__ out) {
    __shared__ float vals[TOPK];
    __shared__ float h1[128];
    __shared__ float part[4][128];
    __shared__ float h2[512];
    __shared__ float red[512];
    int t = threadIdx.x;
    for (int i = t; i < TOPK; i += 512) vals[i] = g_top[i];
    __syncthreads();
    {
        int j = t & 127, c = t >> 7;
        float acc = 0.f;
        for (int i = c * 250; i < (c + 1) * 250; i++) acc += vals[i] * fc1w[i * 128 + j];
        part[c][j] = acc;
    }
    __syncthreads();
    if (t < 128) h1[t] = part[0][t] + part[1][t] + part[2][t] + part[3][t] + fc1b[t];
    __syncthreads();
    red[t] = (t < 128) ? h1[t] : 0.f;
    __syncthreads();
    for (int off = 256; off; off >>= 1) { if (t < off) red[t] += red[t + off]; __syncthreads(); }
    float mean1 = red[0] / 128.f;
    __syncthreads();
    red[t] = (t < 128) ? (h1[t] - mean1) * (h1[t] - mean1) : 0.f;
    __syncthreads();
    for (int off = 256; off; off >>= 1) { if (t < off) red[t] += red[t + off]; __syncthreads(); }
    float var1 = red[0] / 128.f;
    __syncthreads();
    if (t < 128) {
        float v = (h1[t] - mean1) * rsqrtf(var1 + 1e-5f) * ln1g[t] + ln1b[t];
        h1[t] = fmaxf(v, 0.f);
    }
    __syncthreads();
    {
        float acc = fc2b[t];
        for (int i = 0; i < 128; i++) acc += h1[i] * fc2w[i * 512 + t];
        h2[t] = acc;
    }
    __syncthreads();
    red[t] = h2[t];
    __syncthreads();
    for (int off = 256; off; off >>= 1) { if (t < off) red[t] += red[t + off]; __syncthreads(); }
    float mean2 = red[0] / 512.f;
    __syncthreads();
    red[t] = (h2[t] - mean2) * (h2[t] - mean2);
    __syncthreads();
    for (int off = 256; off; off >>= 1) { if (t < off) red[t] += red[t + off]; __syncthreads(); }
    float var2 = red[0] / 512.f;
    __syncthreads();
    float hr = fmaxf((h2[t] - mean2) * rsqrtf(var2 + 1e-5f) * ln2g[t] + ln2b[t], 0.f);
    red[t] = hr * fc3w[t];
    __syncthreads();
    for (int off = 256; off; off >>= 1) { if (t < off) red[t] += red[t + off]; __syncthreads(); }
    if (t == 0) out[0] = 1.f / (1.f + expf(-(red[0] + fc3b[0])));
}

// ---------------- launch ----------------
extern "C" void kernel_launch(void* const* d_in, const int* in_sizes, int n_in,
                              void* d_out, int out_size) {
    const float* x1   = (const float*)d_in[0];
    const int*   ei1  = (const int*)d_in[1];
    const float* x2   = (const float*)d_in[2];
    const int*   ei2  = (const int*)d_in[3];
    const float* w11  = (const float*)d_in[4];
    const float* b11  = (const float*)d_in[5];
    const float* w12  = (const float*)d_in[6];
    const float* b12  = (const float*)d_in[7];
    const float* w21  = (const float*)d_in[8];
    const float* b21  = (const float*)d_in[9];
    const float* w22  = (const float*)d_in[10];
    const float* b22  = (const float*)d_in[11];
    const float* w31  = (const float*)d_in[12];
    const float* b31  = (const float*)d_in[13];
    const float* w32  = (const float*)d_in[14];
    const float* b32  = (const float*)d_in[15];
    const float* linw = (const float*)d_in[16];
    const float* linb = (const float*)d_in[17];
    const float* fc1w = (const float*)d_in[18];
    const float* fc1b = (const float*)d_in[19];
    const float* ln1g = (const float*)d_in[20];
    const float* ln1b = (const float*)d_in[21];
    const float* fc2w = (const float*)d_in[22];
    const float* fc2b = (const float*)d_in[23];
    const float* ln2g = (const float*)d_in[24];
    const float* ln2b = (const float*)d_in[25];
    const float* fc3w = (const float*)d_in[26];
    const float* fc3b = (const float*)d_in[27];
    float* out = (float*)d_out;

    const int* src1 = ei1;
    const int* dst1 = ei1 + N_EDGES;
    const int* src2 = ei2;
    const int* dst2 = ei2 + N_EDGES;

    __half *p_xh, *p_aggh, *p_acth, *p_tmph;
    float *p_o, *p_part;
    cudaGetSymbolAddress((void**)&p_xh, g_xh);
    cudaGetSymbolAddress((void**)&p_aggh, g_aggh);
    cudaGetSymbolAddress((void**)&p_acth, g_acth);
    cudaGetSymbolAddress((void**)&p_tmph, g_tmph);
    cudaGetSymbolAddress((void**)&p_o, g_o);
    cudaGetSymbolAddress((void**)&p_part, g_part);

    dim3 ggrid(HDIM / 128, MT2);
    const int E2B = (2 * N_EDGES + 255) / 256;
    const int N2B = (NTOT + 255) / 256;
    const int NB = (N_NODES + 255) / 256;
    const int AGB512 = (NTOT + 7) / 8;
    const int AGB256 = (NTOT + 15) / 16;
    const int XCB = (NTOT * (FIN_DIM / 4) + 255) / 256;

    // batched CSR for both graphs
    k_zero_cnt<<<N2B, 256>>>();
    k_hist2<<<E2B, 256>>>(dst1, dst2);
    k_scan2<<<2, 1024>>>();
    k_fill2<<<E2B, 256>>>(src1, dst1, src2, dst2);

    // convert inputs to fp16 (independent of CSR build)
    k_x2h<<<XCB, 256>>>(x1, x2, p_xh);

    // layer 1 (FIN=256 -> H)
    k_aggh<FIN_DIM><<<AGB256, 512>>>(p_xh, p_aggh);
    k_gemm_mma<__half><<<ggrid, 256>>>(p_aggh, w11, b11, p_tmph, FIN_DIM, nullptr, nullptr);
    k_gemm_mma<__half><<<ggrid, 256>>>(p_tmph, w12, b12, p_acth, HDIM, nullptr, nullptr);
    // layer 2
    k_aggh<HDIM><<<AGB512, 512>>>(p_acth, p_aggh);
    k_gemm_mma<__half><<<ggrid, 256>>>(p_aggh, w21, b21, p_tmph, HDIM, nullptr, nullptr);
    k_gemm_mma<__half><<<ggrid, 256>>>(p_tmph, w22, b22, p_acth, HDIM, nullptr, nullptr);
    // layer 3
    k_aggh<HDIM><<<AGB512, 512>>>(p_acth, p_aggh);
    k_gemm_mma<__half><<<ggrid, 256>>>(p_aggh, w31, b31, p_tmph, HDIM, nullptr, nullptr);
    // last GEMM: fused final linear
    k_gemm_mma<float><<<ggrid, 256>>>(p_tmph, w32, b32, (float*)nullptr, HDIM, linw, p_part);
    k_linred<<<N2B, 256>>>(linb, p_o);

    k_dist<<<NB, 256>>>();
    k_selhist<<<1, 1024>>>();
    k_compact<<<NB, 256>>>();
    k_sortsel<<<1, 1024>>>();
    k_mlp<<<1, 512>>>(fc1w, fc1b, ln1g, ln1b, fc2w, fc2b, ln2g, ln2b, fc3w, fc3b, out);
}

// round 14
// speedup vs baseline: 2.1588x; 1.2536x over previous
#include <cuda_runtime.h>
#include <cuda_fp16.h>
#include <math.h>
#include <stdint.h>

#define N_NODES 20000
#define NTOT    40000
#define MPAD2   40192
#define MT2     314
#define N_EDGES 640000
#define FIN_DIM 256
#define HDIM 512
#define TOPK 1000
#define SELN 4096

// ---------------- scratch (static device memory; no allocations) ----------------
__device__ __half g_xh[(size_t)NTOT * FIN_DIM];
__device__ __half g_aggh[(size_t)MPAD2 * HDIM];
__device__ __half g_acth[(size_t)MPAD2 * HDIM];
__device__ __half g_tmph[(size_t)MPAD2 * HDIM];
__device__ float  g_part[8][MPAD2][2];
__device__ float  g_o[NTOT * 2];
__device__ float  g_dist[N_NODES];
__device__ float  g_sel[SELN];
__device__ float  g_top[TOPK];
__device__ int    g_selcnt;
__device__ int    g_thrbin;
__device__ int    g_cnt[NTOT];
__device__ int    g_rowptr[2 * (N_NODES + 1)];
__device__ int    g_cursor[NTOT];
__device__ int    g_esrc[2 * N_EDGES];

// ---------------- helpers ----------------
__device__ __forceinline__ void mma_f16(float* c, const uint32_t* a, const uint32_t* b) {
    asm volatile(
        "mma.sync.aligned.m16n8k16.row.col.f32.f16.f16.f32 "
        "{%0,%1,%2,%3}, {%4,%5,%6,%7}, {%8,%9}, {%0,%1,%2,%3};"
        : "+f"(c[0]), "+f"(c[1]), "+f"(c[2]), "+f"(c[3])
        : "r"(a[0]), "r"(a[1]), "r"(a[2]), "r"(a[3]), "r"(b[0]), "r"(b[1]));
}

// ---------------- CSR build (both graphs, batched) ----------------
__global__ void k_zero_cnt() {
    int i = blockIdx.x * blockDim.x + threadIdx.x;
    if (i < NTOT) g_cnt[i] = 0;
}
__global__ void k_hist2(const int* __restrict__ dst1, const int* __restrict__ dst2) {
    int e = blockIdx.x * blockDim.x + threadIdx.x;
    if (e >= 2 * N_EDGES) return;
    int gph = e >= N_EDGES;
    int le = e - gph * N_EDGES;
    int d = (gph ? dst2 : dst1)[le];
    atomicAdd(&g_cnt[gph * N_NODES + d], 1);
}
__global__ void k_scan2() {
    __shared__ int s[1024];
    __shared__ int carry;
    int t = threadIdx.x;
    int gph = blockIdx.x;
    const int cbase = gph * N_NODES;
    const int rbase = gph * (N_NODES + 1);
    if (t == 0) carry = 0;
    __syncthreads();
    for (int base = 0; base < N_NODES; base += 1024) {
        int v = (base + t < N_NODES) ? g_cnt[cbase + base + t] : 0;
        s[t] = v;
        __syncthreads();
        for (int off = 1; off < 1024; off <<= 1) {
            int a = (t >= off) ? s[t - off] : 0;
            __syncthreads();
            s[t] += a;
            __syncthreads();
        }
        int exc = s[t] - v + carry;
        if (base + t < N_NODES) {
            g_rowptr[rbase + base + t] = exc;
            g_cursor[cbase + base + t] = exc;
        }
        __syncthreads();
        if (t == 0) carry = carry + s[1023];
        __syncthreads();
    }
    if (t == 0) g_rowptr[rbase + N_NODES] = carry;
}
__global__ void k_fill2(const int* __restrict__ src1, const int* __restrict__ dst1,
                        const int* __restrict__ src2, const int* __restrict__ dst2) {
    int e = blockIdx.x * blockDim.x + threadIdx.x;
    if (e >= 2 * N_EDGES) return;
    int gph = e >= N_EDGES;
    int le = e - gph * N_EDGES;
    int d = (gph ? dst2 : dst1)[le];
    int sv = (gph ? src2 : src1)[le];
    int pos = atomicAdd(&g_cursor[gph * N_NODES + d], 1);
    g_esrc[gph * N_EDGES + pos] = sv;
}

// ---------------- input conversion: fp32 x1|x2 -> fp16 g_xh ----------------
__global__ void k_x2h(const float* __restrict__ xa, const float* __restrict__ xb,
                      __half* __restrict__ out) {
    int n = blockIdx.x * blockDim.x + threadIdx.x;
    if (n >= NTOT * (FIN_DIM / 4)) return;
    int gph = n >= N_NODES * (FIN_DIM / 4);
    int local = n - gph * N_NODES * (FIN_DIM / 4);
    float4 v = ((const float4*)(gph ? xb : xa))[local];
    __half2 h0 = __floats2half2_rn(v.x, v.y);
    __half2 h1 = __floats2half2_rn(v.z, v.w);
    ((uint2*)out)[n] = make_uint2(*(uint32_t*)&h0, *(uint32_t*)&h1);
}

// ---------------- aggregation (fp16 in, fp16 out), templated on F ----------
template <int F>
__global__ void k_aggh(const __half* __restrict__ x, __half* __restrict__ out) {
    const int TPN = F / 8;
    const int NPB = 512 / TPN;
    int t = threadIdx.x;
    int node = blockIdx.x * NPB + t / TPN;
    int tf = t % TPN;
    if (node >= NTOT) return;
    int gph = node >= N_NODES;
    int local = node - gph * N_NODES;
    const uint4* x4 = (const uint4*)x;
    float acc[8];
    {
        uint4 v = x4[(size_t)node * TPN + tf];
        float2 f0 = __half22float2(*(__half2*)&v.x);
        float2 f1 = __half22float2(*(__half2*)&v.y);
        float2 f2 = __half22float2(*(__half2*)&v.z);
        float2 f3 = __half22float2(*(__half2*)&v.w);
        acc[0] = f0.x; acc[1] = f0.y; acc[2] = f1.x; acc[3] = f1.y;
        acc[4] = f2.x; acc[5] = f2.y; acc[6] = f3.x; acc[7] = f3.y;
    }
    int beg = g_rowptr[gph * (N_NODES + 1) + local];
    int end = g_rowptr[gph * (N_NODES + 1) + local + 1];
    const int* ep = g_esrc + gph * N_EDGES;
    const size_t gofs = (size_t)gph * N_NODES * TPN;
    int e = beg;
    for (; e + 1 < end; e += 2) {
        int i0 = __ldg(&ep[e]);
        int i1 = __ldg(&ep[e + 1]);
        uint4 v0 = x4[gofs + (size_t)i0 * TPN + tf];
        uint4 v1 = x4[gofs + (size_t)i1 * TPN + tf];
        float2 a0 = __half22float2(*(__half2*)&v0.x), b0 = __half22float2(*(__half2*)&v1.x);
        float2 a1 = __half22float2(*(__half2*)&v0.y), b1 = __half22float2(*(__half2*)&v1.y);
        float2 a2 = __half22float2(*(__half2*)&v0.z), b2 = __half22float2(*(__half2*)&v1.z);
        float2 a3 = __half22float2(*(__half2*)&v0.w), b3 = __half22float2(*(__half2*)&v1.w);
        acc[0] += a0.x + b0.x; acc[1] += a0.y + b0.y;
        acc[2] += a1.x + b1.x; acc[3] += a1.y + b1.y;
        acc[4] += a2.x + b2.x; acc[5] += a2.y + b2.y;
        acc[6] += a3.x + b3.x; acc[7] += a3.y + b3.y;
    }
    if (e < end) {
        int i0 = __ldg(&ep[e]);
        uint4 v0 = x4[gofs + (size_t)i0 * TPN + tf];
        float2 a0 = __half22float2(*(__half2*)&v0.x);
        float2 a1 = __half22float2(*(__half2*)&v0.y);
        float2 a2 = __half22float2(*(__half2*)&v0.z);
        float2 a3 = __half22float2(*(__half2*)&v0.w);
        acc[0] += a0.x; acc[1] += a0.y; acc[2] += a1.x; acc[3] += a1.y;
        acc[4] += a2.x; acc[5] += a2.y; acc[6] += a3.x; acc[7] += a3.y;
    }
    __half2 h0 = __floats2half2_rn(acc[0], acc[1]);
    __half2 h1 = __floats2half2_rn(acc[2], acc[3]);
    __half2 h2 = __floats2half2_rn(acc[4], acc[5]);
    __half2 h3 = __floats2half2_rn(acc[6], acc[7]);
    uint4 u = make_uint4(*(uint32_t*)&h0, *(uint32_t*)&h1,
                         *(uint32_t*)&h2, *(uint32_t*)&h3);
    ((uint4*)out)[(size_t)node * TPN + tf] = u;
}

// ---------------- single-pass fp16 mma.sync GEMM: C = relu(A @ W + b) ------
// A fp16 exact; B fp32 rounded to fp16 (single piece).
// Block 128x128x16, 256 thr, single barrier per stage.
#define GSTRIDE 140
#define GMATW   (8 * GSTRIDE)

template <typename TC>
__global__ void __launch_bounds__(256)
k_gemm_mma(const __half* __restrict__ A, const float* __restrict__ W,
           const float* __restrict__ bias, TC* __restrict__ C, int K,
           const float* __restrict__ linw2, float* __restrict__ part) {
    __shared__ uint32_t S[2][2][GMATW];
    int t = threadIdx.x, lane = t & 31, wid = t >> 5;
    int warp_m = wid >> 1, warp_n = wid & 1;
    int rowBase = blockIdx.y * 128;
    int colBase = blockIdx.x * 128;

    float acc[2][8][4];
#pragma unroll
    for (int i = 0; i < 2; i++)
#pragma unroll
        for (int j = 0; j < 8; j++)
#pragma unroll
            for (int q = 0; q < 4; q++) acc[i][j][q] = 0.f;

    int a_row = t >> 1;
    int a_half = t & 1;
    int b_k2 = t >> 5;
    int b_n0 = lane * 4;

    const __half* Ap = A + (size_t)(rowBase + a_row) * K + a_half * 8;
    const float* Bp0 = W + (size_t)(2 * b_k2) * HDIM + colBase + b_n0;
    const float* Bp1 = Bp0 + HDIM;

    const int nk = K >> 4;
    uint4 rah;
    float4 rb0, rb1;

    rah = *(const uint4*)(Ap);
    rb0 = *(const float4*)(Bp0);
    rb1 = *(const float4*)(Bp1);

    for (int s = 0; s < nk; s++) {
        int buf = s & 1;
        uint32_t* Aw = S[buf][0];
        uint32_t* Bh = S[buf][1];
        {
            Aw[(a_half * 4 + 0) * GSTRIDE + a_row] = rah.x;
            Aw[(a_half * 4 + 1) * GSTRIDE + a_row] = rah.y;
            Aw[(a_half * 4 + 2) * GSTRIDE + a_row] = rah.z;
            Aw[(a_half * 4 + 3) * GSTRIDE + a_row] = rah.w;
            __half2 h0 = __floats2half2_rn(rb0.x, rb1.x);
            __half2 h1 = __floats2half2_rn(rb0.y, rb1.y);
            __half2 h2 = __floats2half2_rn(rb0.z, rb1.z);
            __half2 h3 = __floats2half2_rn(rb0.w, rb1.w);
            uint4 hh = make_uint4(*(uint32_t*)&h0, *(uint32_t*)&h1,
                                  *(uint32_t*)&h2, *(uint32_t*)&h3);
            *(uint4*)&Bh[b_k2 * GSTRIDE + b_n0] = hh;
        }
        __syncthreads();   // single barrier per stage (double buffering)
        if (s + 1 < nk) {
            rah = *(const uint4*)(Ap + (s + 1) * 16);
            const float* Bp2 = Bp0 + (size_t)(s + 1) * 16 * HDIM;
            rb0 = *(const float4*)(Bp2);
            rb1 = *(const float4*)(Bp2 + HDIM);
        }
        {
            int g = lane >> 2, q = lane & 3;
            uint32_t bhf[8][2];
#pragma unroll
            for (int nt = 0; nt < 8; nt++) {
                int n = warp_n * 64 + nt * 8 + g;
                bhf[nt][0] = Bh[q * GSTRIDE + n];
                bhf[nt][1] = Bh[(q + 4) * GSTRIDE + n];
            }
#pragma unroll
            for (int mt = 0; mt < 2; mt++) {
                int m = warp_m * 32 + mt * 16 + g;
                uint32_t ahf[4];
                ahf[0] = Aw[q * GSTRIDE + m];
                ahf[1] = Aw[q * GSTRIDE + m + 8];
                ahf[2] = Aw[(q + 4) * GSTRIDE + m];
                ahf[3] = Aw[(q + 4) * GSTRIDE + m + 8];
#pragma unroll
                for (int nt = 0; nt < 8; nt++) {
                    mma_f16(acc[mt][nt], ahf, bhf[nt]);
                }
            }
        }
    }

    int g = lane >> 2;
    int cq = (lane & 3) * 2;
    if (linw2 == nullptr) {
#pragma unroll
        for (int mt = 0; mt < 2; mt++) {
            int row = rowBase + warp_m * 32 + mt * 16 + g;
#pragma unroll
            for (int nt = 0; nt < 8; nt++) {
                int col = colBase + warp_n * 64 + nt * 8 + cq;
                float b0 = bias[col], b1 = bias[col + 1];
                float o0x = fmaxf(acc[mt][nt][0] + b0, 0.f);
                float o0y = fmaxf(acc[mt][nt][1] + b1, 0.f);
                float o1x = fmaxf(acc[mt][nt][2] + b0, 0.f);
                float o1y = fmaxf(acc[mt][nt][3] + b1, 0.f);
                if constexpr (sizeof(TC) == 2) {
                    __half2 p0 = __floats2half2_rn(o0x, o0y);
                    __half2 p1 = __floats2half2_rn(o1x, o1y);
                    *(__half2*)((__half*)C + (size_t)row * HDIM + col) = p0;
                    *(__half2*)((__half*)C + (size_t)(row + 8) * HDIM + col) = p1;
                } else {
                    *(float2*)((float*)C + (size_t)row * HDIM + col) = make_float2(o0x, o0y);
                    *(float2*)((float*)C + (size_t)(row + 8) * HDIM + col) = make_float2(o1x, o1y);
                }
            }
        }
    } else {
        int slot = blockIdx.x * 2 + warp_n;
#pragma unroll
        for (int mt = 0; mt < 2; mt++) {
            float s00 = 0.f, s01 = 0.f;
            float s10 = 0.f, s11 = 0.f;
#pragma unroll
            for (int nt = 0; nt < 8; nt++) {
                int col = colBase + warp_n * 64 + nt * 8 + cq;
                float b0 = bias[col], b1 = bias[col + 1];
                float lw00 = linw2[col * 2],     lw01 = linw2[col * 2 + 1];
                float lw10 = linw2[col * 2 + 2], lw11 = linw2[col * 2 + 3];
                float v0 = fmaxf(acc[mt][nt][0] + b0, 0.f);
                float v1 = fmaxf(acc[mt][nt][1] + b1, 0.f);
                float v2 = fmaxf(acc[mt][nt][2] + b0, 0.f);
                float v3 = fmaxf(acc[mt][nt][3] + b1, 0.f);
                s00 += v0 * lw00 + v1 * lw10;
                s01 += v0 * lw01 + v1 * lw11;
                s10 += v2 * lw00 + v3 * lw10;
                s11 += v2 * lw01 + v3 * lw11;
            }
#pragma unroll
            for (int off = 1; off <= 2; off <<= 1) {
                s00 += __shfl_xor_sync(0xffffffffu, s00, off);
                s01 += __shfl_xor_sync(0xffffffffu, s01, off);
                s10 += __shfl_xor_sync(0xffffffffu, s10, off);
                s11 += __shfl_xor_sync(0xffffffffu, s11, off);
            }
            if ((lane & 3) == 0) {
                int row = rowBase + warp_m * 32 + mt * 16 + g;
                float* p0 = part + ((size_t)slot * MPAD2 + row) * 2;
                p0[0] = s00; p0[1] = s01;
                float* p1 = part + ((size_t)slot * MPAD2 + row + 8) * 2;
                p1[0] = s10; p1[1] = s11;
            }
        }
    }
}

// ---------------- reduce lin partials ----------------
__global__ void k_linred(const float* __restrict__ b, float* __restrict__ o) {
    int i = blockIdx.x * blockDim.x + threadIdx.x;
    if (i >= NTOT) return;
    float a0 = b[0], a1 = b[1];
#pragma unroll
    for (int s = 0; s < 8; s++) {
        a0 += g_part[s][i][0];
        a1 += g_part[s][i][1];
    }
    o[i * 2] = a0;
    o[i * 2 + 1] = a1;
}

// ---------------- pairwise distance ----------------
__global__ void k_dist() {
    int i = blockIdx.x * blockDim.x + threadIdx.x;
    if (i >= N_NODES) return;
    float dx = g_o[i * 2]     - g_o[(i + N_NODES) * 2]     + 1e-6f;
    float dy = g_o[i * 2 + 1] - g_o[(i + N_NODES) * 2 + 1] + 1e-6f;
    g_dist[i] = sqrtf(dx * dx + dy * dy);
}

// ---------------- top-k select ----------------
__global__ void k_selhist() {
    __shared__ int hist[2048];
    int t = threadIdx.x;
    hist[t] = 0; hist[t + 1024] = 0;
    for (int i = t; i < SELN; i += 1024) g_sel[i] = -INFINITY;
    if (t == 0) g_selcnt = 0;
    __syncthreads();
    for (int i = t; i < N_NODES; i += 1024) {
        uint32_t bits = __float_as_uint(g_dist[i]);
        atomicAdd(&hist[bits >> 21], 1);
    }
    __syncthreads();
    if (t == 0) {
        int cum = 0, thr = 0;
        for (int b = 2047; b >= 0; b--) {
            cum += hist[b];
            if (cum >= TOPK) { thr = b; break; }
        }
        g_thrbin = thr;
    }
}
__global__ void k_compact() {
    int i = blockIdx.x * blockDim.x + threadIdx.x;
    if (i >= N_NODES) return;
    float d = g_dist[i];
    if ((int)(__float_as_uint(d) >> 21) >= g_thrbin) {
        int pos = atomicAdd(&g_selcnt, 1);
        if (pos < SELN) g_sel[pos] = d;
    }
}
__global__ void k_sortsel() {
    __shared__ float s[SELN];
    int t = threadIdx.x;
    for (int i = t; i < SELN; i += 1024) s[i] = g_sel[i];
    __syncthreads();
    for (int k = 2; k <= SELN; k <<= 1) {
        for (int j = k >> 1; j > 0; j >>= 1) {
            for (int i = t; i < SELN; i += 1024) {
                int ixj = i ^ j;
                if (ixj > i) {
                    bool dsc = (i & k) == 0;
                    float a = s[i], c = s[ixj];
                    bool sw = dsc ? (a < c) : (a > c);
                    if (sw) { s[i] = c; s[ixj] = a; }
                }
            }
            __syncthreads();
        }
    }
    for (int i = t; i < TOPK; i += 1024) g_top[i] = s[i];
}

// ---------------- head MLP ----------------
__global__ void k_mlp(const float* __restrict__ fc1w, const float* __restrict__ fc1b,
                      const float* __restrict__ ln1g, const float* __restrict__ ln1b,
                      const float* __restrict__ fc2w, const float* __restrict__ fc2b,
                      const float* __restrict__ ln2g, const float* __restrict__ ln2b,
                      const float* __restrict__ fc3w, const float* __restrict__ fc3b,
                      float* __restrict__ out) {
    __shared__ float vals[TOPK];
    __shared__ float h1[128];
    __shared__ float part[4][128];
    __shared__ float h2[512];
    __shared__ float red[512];
    int t = threadIdx.x;
    for (int i = t; i < TOPK; i += 512) vals[i] = g_top[i];
    __syncthreads();
    {
        int j = t & 127, c = t >> 7;
        float acc = 0.f;
        for (int i = c * 250; i < (c + 1) * 250; i++) acc += vals[i] * fc1w[i * 128 + j];
        part[c][j] = acc;
    }
    __syncthreads();
    if (t < 128) h1[t] = part[0][t] + part[1][t] + part[2][t] + part[3][t] + fc1b[t];
    __syncthreads();
    red[t] = (t < 128) ? h1[t] : 0.f;
    __syncthreads();
    for (int off = 256; off; off >>= 1) { if (t < off) red[t] += red[t + off]; __syncthreads(); }
    float mean1 = red[0] / 128.f;
    __syncthreads();
    red[t] = (t < 128) ? (h1[t] - mean1) * (h1[t] - mean1) : 0.f;
    __syncthreads();
    for (int off = 256; off; off >>= 1) { if (t < off) red[t] += red[t + off]; __syncthreads(); }
    float var1 = red[0] / 128.f;
    __syncthreads();
    if (t < 128) {
        float v = (h1[t] - mean1) * rsqrtf(var1 + 1e-5f) * ln1g[t] + ln1b[t];
        h1[t] = fmaxf(v, 0.f);
    }
    __syncthreads();
    {
        float acc = fc2b[t];
        for (int i = 0; i < 128; i++) acc += h1[i] * fc2w[i * 512 + t];
        h2[t] = acc;
    }
    __syncthreads();
    red[t] = h2[t];
    __syncthreads();
    for (int off = 256; off; off >>= 1) { if (t < off) red[t] += red[t + off]; __syncthreads(); }
    float mean2 = red[0] / 512.f;
    __syncthreads();
    red[t] = (h2[t] - mean2) * (h2[t] - mean2);
    __syncthreads();
    for (int off = 256; off; off >>= 1) { if (t < off) red[t] += red[t + off]; __syncthreads(); }
    float var2 = red[0] / 512.f;
    __syncthreads();
    float hr = fmaxf((h2[t] - mean2) * rsqrtf(var2 + 1e-5f) * ln2g[t] + ln2b[t], 0.f);
    red[t] = hr * fc3w[t];
    __syncthreads();
    for (int off = 256; off; off >>= 1) { if (t < off) red[t] += red[t + off]; __syncthreads(); }
    if (t == 0) out[0] = 1.f / (1.f + expf(-(red[0] + fc3b[0])));
}

// ---------------- launch ----------------
extern "C" void kernel_launch(void* const* d_in, const int* in_sizes, int n_in,
                              void* d_out, int out_size) {
    const float* x1   = (const float*)d_in[0];
    const int*   ei1  = (const int*)d_in[1];
    const float* x2   = (const float*)d_in[2];
    const int*   ei2  = (const int*)d_in[3];
    const float* w11  = (const float*)d_in[4];
    const float* b11  = (const float*)d_in[5];
    const float* w12  = (const float*)d_in[6];
    const float* b12  = (const float*)d_in[7];
    const float* w21  = (const float*)d_in[8];
    const float* b21  = (const float*)d_in[9];
    const float* w22  = (const float*)d_in[10];
    const float* b22  = (const float*)d_in[11];
    const float* w31  = (const float*)d_in[12];
    const float* b31  = (const float*)d_in[13];
    const float* w32  = (const float*)d_in[14];
    const float* b32  = (const float*)d_in[15];
    const float* linw = (const float*)d_in[16];
    const float* linb = (const float*)d_in[17];
    const float* fc1w = (const float*)d_in[18];
    const float* fc1b = (const float*)d_in[19];
    const float* ln1g = (const float*)d_in[20];
    const float* ln1b = (const float*)d_in[21];
    const float* fc2w = (const float*)d_in[22];
    const float* fc2b = (const float*)d_in[23];
    const float* ln2g = (const float*)d_in[24];
    const float* ln2b = (const float*)d_in[25];
    const float* fc3w = (const float*)d_in[26];
    const float* fc3b = (const float*)d_in[27];
    float* out = (float*)d_out;

    const int* src1 = ei1;
    const int* dst1 = ei1 + N_EDGES;
    const int* src2 = ei2;
    const int* dst2 = ei2 + N_EDGES;

    __half *p_xh, *p_aggh, *p_acth, *p_tmph;
    float *p_o, *p_part;
    cudaGetSymbolAddress((void**)&p_xh, g_xh);
    cudaGetSymbolAddress((void**)&p_aggh, g_aggh);
    cudaGetSymbolAddress((void**)&p_acth, g_acth);
    cudaGetSymbolAddress((void**)&p_tmph, g_tmph);
    cudaGetSymbolAddress((void**)&p_o, g_o);
    cudaGetSymbolAddress((void**)&p_part, g_part);

    dim3 ggrid(HDIM / 128, MT2);
    const int E2B = (2 * N_EDGES + 255) / 256;
    const int N2B = (NTOT + 255) / 256;
    const int NB = (N_NODES + 255) / 256;
    const int AGB512 = (NTOT + 7) / 8;
    const int AGB256 = (NTOT + 15) / 16;
    const int XCB = (NTOT * (FIN_DIM / 4) + 255) / 256;

    // batched CSR for both graphs
    k_zero_cnt<<<N2B, 256>>>();
    k_hist2<<<E2B, 256>>>(dst1, dst2);
    k_scan2<<<2, 1024>>>();
    k_fill2<<<E2B, 256>>>(src1, dst1, src2, dst2);

    // convert inputs to fp16 (independent of CSR build)
    k_x2h<<<XCB, 256>>>(x1, x2, p_xh);

    // layer 1 (FIN=256 -> H)
    k_aggh<FIN_DIM><<<AGB256, 512>>>(p_xh, p_aggh);
    k_gemm_mma<__half><<<ggrid, 256>>>(p_aggh, w11, b11, p_tmph, FIN_DIM, nullptr, nullptr);
    k_gemm_mma<__half><<<ggrid, 256>>>(p_tmph, w12, b12, p_acth, HDIM, nullptr, nullptr);
    // layer 2
    k_aggh<HDIM><<<AGB512, 512>>>(p_acth, p_aggh);
    k_gemm_mma<__half><<<ggrid, 256>>>(p_aggh, w21, b21, p_tmph, HDIM, nullptr, nullptr);
    k_gemm_mma<__half><<<ggrid, 256>>>(p_tmph, w22, b22, p_acth, HDIM, nullptr, nullptr);
    // layer 3
    k_aggh<HDIM><<<AGB512, 512>>>(p_acth, p_aggh);
    k_gemm_mma<__half><<<ggrid, 256>>>(p_aggh, w31, b31, p_tmph, HDIM, nullptr, nullptr);
    // last GEMM: fused final linear
    k_gemm_mma<float><<<ggrid, 256>>>(p_tmph, w32, b32, (float*)nullptr, HDIM, linw, p_part);
    k_linred<<<N2B, 256>>>(linb, p_o);

    k_dist<<<NB, 256>>>();
    k_selhist<<<1, 1024>>>();
    k_compact<<<NB, 256>>>();
    k_sortsel<<<1, 1024>>>();
    k_mlp<<<1, 512>>>(fc1w, fc1b, ln1g, ln1b, fc2w, fc2b, ln2g, ln2b, fc3w, fc3b, out);
}

// round 15
// speedup vs baseline: 2.1709x; 1.0056x over previous
#include <cuda_runtime.h>
#include <cuda_fp16.h>
#include <math.h>
#include <stdint.h>

#define N_NODES 20000
#define NTOT    40000
#define MPAD2   40192
#define MT2     314
#define N_EDGES 640000
#define FIN_DIM 256
#define HDIM 512
#define TOPK 1000
#define SELN 4096

// ---------------- scratch (static device memory; no allocations) ----------------
__device__ __half g_xh[(size_t)NTOT * FIN_DIM];
__device__ __half g_aggh[(size_t)MPAD2 * HDIM];
__device__ __half g_acth[(size_t)MPAD2 * HDIM];
__device__ __half g_tmph[(size_t)MPAD2 * HDIM];
__device__ float  g_part[8][MPAD2][2];
__device__ float  g_o[NTOT * 2];
__device__ float  g_top[TOPK];
__device__ int    g_cnt[NTOT];
__device__ int    g_rowptr[2 * (N_NODES + 1)];
__device__ int    g_cursor[NTOT];
__device__ int    g_esrc[2 * N_EDGES];

// ---------------- helpers ----------------
__device__ __forceinline__ void mma_f16(float* c, const uint32_t* a, const uint32_t* b) {
    asm volatile(
        "mma.sync.aligned.m16n8k16.row.col.f32.f16.f16.f32 "
        "{%0,%1,%2,%3}, {%4,%5,%6,%7}, {%8,%9}, {%0,%1,%2,%3};"
        : "+f"(c[0]), "+f"(c[1]), "+f"(c[2]), "+f"(c[3])
        : "r"(a[0]), "r"(a[1]), "r"(a[2]), "r"(a[3]), "r"(b[0]), "r"(b[1]));
}

// ---------------- CSR build (both graphs, batched) ----------------
__global__ void k_zero_cnt() {
    int i = blockIdx.x * blockDim.x + threadIdx.x;
    if (i < NTOT) g_cnt[i] = 0;
}
__global__ void k_hist2(const int* __restrict__ dst1, const int* __restrict__ dst2) {
    int e = blockIdx.x * blockDim.x + threadIdx.x;
    if (e >= 2 * N_EDGES) return;
    int gph = e >= N_EDGES;
    int le = e - gph * N_EDGES;
    int d = (gph ? dst2 : dst1)[le];
    atomicAdd(&g_cnt[gph * N_NODES + d], 1);
}
// single-pass scan: 1024 thr x 20 elems, warp-shuffle + cross-warp
__global__ void k_scan2() {
    const int PER = 20;                       // 1024*20 = 20480 >= 20000
    int gph = blockIdx.x;
    int t = threadIdx.x, lane = t & 31, wid = t >> 5;
    const int cbase = gph * N_NODES;
    const int rbase = gph * (N_NODES + 1);
    int base = t * PER;
    int v[PER];
    int sum = 0;
#pragma unroll
    for (int i = 0; i < PER; i++) {
        int idx = base + i;
        v[i] = (idx < N_NODES) ? g_cnt[cbase + idx] : 0;
        sum += v[i];
    }
    // inclusive warp scan of per-thread sums
    int s = sum;
#pragma unroll
    for (int off = 1; off < 32; off <<= 1) {
        int n = __shfl_up_sync(0xffffffffu, s, off);
        if (lane >= off) s += n;
    }
    __shared__ int wsum[32];
    if (lane == 31) wsum[wid] = s;
    __syncthreads();
    if (wid == 0) {
        int ws = wsum[lane];
#pragma unroll
        for (int off = 1; off < 32; off <<= 1) {
            int n = __shfl_up_sync(0xffffffffu, ws, off);
            if (lane >= off) ws += n;
        }
        wsum[lane] = ws;
    }
    __syncthreads();
    int excl = s - sum + (wid > 0 ? wsum[wid - 1] : 0);
    int run = excl;
#pragma unroll
    for (int i = 0; i < PER; i++) {
        int idx = base + i;
        if (idx < N_NODES) {
            g_rowptr[rbase + idx] = run;
            g_cursor[cbase + idx] = run;
        }
        run += v[i];
    }
    if (t == 1023) g_rowptr[rbase + N_NODES] = run;
}
__global__ void k_fill2(const int* __restrict__ src1, const int* __restrict__ dst1,
                        const int* __restrict__ src2, const int* __restrict__ dst2) {
    int e = blockIdx.x * blockDim.x + threadIdx.x;
    if (e >= 2 * N_EDGES) return;
    int gph = e >= N_EDGES;
    int le = e - gph * N_EDGES;
    int d = (gph ? dst2 : dst1)[le];
    int sv = (gph ? src2 : src1)[le];
    int pos = atomicAdd(&g_cursor[gph * N_NODES + d], 1);
    g_esrc[gph * N_EDGES + pos] = sv;
}

// ---------------- input conversion: fp32 x1|x2 -> fp16 g_xh ----------------
__global__ void k_x2h(const float* __restrict__ xa, const float* __restrict__ xb,
                      __half* __restrict__ out) {
    int n = blockIdx.x * blockDim.x + threadIdx.x;
    if (n >= NTOT * (FIN_DIM / 4)) return;
    int gph = n >= N_NODES * (FIN_DIM / 4);
    int local = n - gph * N_NODES * (FIN_DIM / 4);
    float4 v = ((const float4*)(gph ? xb : xa))[local];
    __half2 h0 = __floats2half2_rn(v.x, v.y);
    __half2 h1 = __floats2half2_rn(v.z, v.w);
    ((uint2*)out)[n] = make_uint2(*(uint32_t*)&h0, *(uint32_t*)&h1);
}

// ---------------- aggregation (fp16 in, fp16 out), templated on F ----------
template <int F>
__global__ void k_aggh(const __half* __restrict__ x, __half* __restrict__ out) {
    const int TPN = F / 8;
    const int NPB = 512 / TPN;
    int t = threadIdx.x;
    int node = blockIdx.x * NPB + t / TPN;
    int tf = t % TPN;
    if (node >= NTOT) return;
    int gph = node >= N_NODES;
    int local = node - gph * N_NODES;
    const uint4* x4 = (const uint4*)x;
    float acc[8];
    {
        uint4 v = x4[(size_t)node * TPN + tf];
        float2 f0 = __half22float2(*(__half2*)&v.x);
        float2 f1 = __half22float2(*(__half2*)&v.y);
        float2 f2 = __half22float2(*(__half2*)&v.z);
        float2 f3 = __half22float2(*(__half2*)&v.w);
        acc[0] = f0.x; acc[1] = f0.y; acc[2] = f1.x; acc[3] = f1.y;
        acc[4] = f2.x; acc[5] = f2.y; acc[6] = f3.x; acc[7] = f3.y;
    }
    int beg = g_rowptr[gph * (N_NODES + 1) + local];
    int end = g_rowptr[gph * (N_NODES + 1) + local + 1];
    const int* ep = g_esrc + gph * N_EDGES;
    const size_t gofs = (size_t)gph * N_NODES * TPN;
    int e = beg;
    for (; e + 1 < end; e += 2) {
        int i0 = __ldg(&ep[e]);
        int i1 = __ldg(&ep[e + 1]);
        uint4 v0 = x4[gofs + (size_t)i0 * TPN + tf];
        uint4 v1 = x4[gofs + (size_t)i1 * TPN + tf];
        float2 a0 = __half22float2(*(__half2*)&v0.x), b0 = __half22float2(*(__half2*)&v1.x);
        float2 a1 = __half22float2(*(__half2*)&v0.y), b1 = __half22float2(*(__half2*)&v1.y);
        float2 a2 = __half22float2(*(__half2*)&v0.z), b2 = __half22float2(*(__half2*)&v1.z);
        float2 a3 = __half22float2(*(__half2*)&v0.w), b3 = __half22float2(*(__half2*)&v1.w);
        acc[0] += a0.x + b0.x; acc[1] += a0.y + b0.y;
        acc[2] += a1.x + b1.x; acc[3] += a1.y + b1.y;
        acc[4] += a2.x + b2.x; acc[5] += a2.y + b2.y;
        acc[6] += a3.x + b3.x; acc[7] += a3.y + b3.y;
    }
    if (e < end) {
        int i0 = __ldg(&ep[e]);
        uint4 v0 = x4[gofs + (size_t)i0 * TPN + tf];
        float2 a0 = __half22float2(*(__half2*)&v0.x);
        float2 a1 = __half22float2(*(__half2*)&v0.y);
        float2 a2 = __half22float2(*(__half2*)&v0.z);
        float2 a3 = __half22float2(*(__half2*)&v0.w);
        acc[0] += a0.x; acc[1] += a0.y; acc[2] += a1.x; acc[3] += a1.y;
        acc[4] += a2.x; acc[5] += a2.y; acc[6] += a3.x; acc[7] += a3.y;
    }
    __half2 h0 = __floats2half2_rn(acc[0], acc[1]);
    __half2 h1 = __floats2half2_rn(acc[2], acc[3]);
    __half2 h2 = __floats2half2_rn(acc[4], acc[5]);
    __half2 h3 = __floats2half2_rn(acc[6], acc[7]);
    uint4 u = make_uint4(*(uint32_t*)&h0, *(uint32_t*)&h1,
                         *(uint32_t*)&h2, *(uint32_t*)&h3);
    ((uint4*)out)[(size_t)node * TPN + tf] = u;
}

// ---------------- single-pass fp16 mma.sync GEMM: C = relu(A @ W + b) ------
#define GSTRIDE 140
#define GMATW   (8 * GSTRIDE)

template <typename TC>
__global__ void __launch_bounds__(256)
k_gemm_mma(const __half* __restrict__ A, const float* __restrict__ W,
           const float* __restrict__ bias, TC* __restrict__ C, int K,
           const float* __restrict__ linw2, float* __restrict__ part) {
    __shared__ uint32_t S[2][2][GMATW];
    int t = threadIdx.x, lane = t & 31, wid = t >> 5;
    int warp_m = wid >> 1, warp_n = wid & 1;
    int rowBase = blockIdx.y * 128;
    int colBase = blockIdx.x * 128;

    float acc[2][8][4];
#pragma unroll
    for (int i = 0; i < 2; i++)
#pragma unroll
        for (int j = 0; j < 8; j++)
#pragma unroll
            for (int q = 0; q < 4; q++) acc[i][j][q] = 0.f;

    int a_row = t >> 1;
    int a_half = t & 1;
    int b_k2 = t >> 5;
    int b_n0 = lane * 4;

    const __half* Ap = A + (size_t)(rowBase + a_row) * K + a_half * 8;
    const float* Bp0 = W + (size_t)(2 * b_k2) * HDIM + colBase + b_n0;
    const float* Bp1 = Bp0 + HDIM;

    const int nk = K >> 4;
    uint4 rah;
    float4 rb0, rb1;

    rah = *(const uint4*)(Ap);
    rb0 = *(const float4*)(Bp0);
    rb1 = *(const float4*)(Bp1);

    for (int s = 0; s < nk; s++) {
        int buf = s & 1;
        uint32_t* Aw = S[buf][0];
        uint32_t* Bh = S[buf][1];
        {
            Aw[(a_half * 4 + 0) * GSTRIDE + a_row] = rah.x;
            Aw[(a_half * 4 + 1) * GSTRIDE + a_row] = rah.y;
            Aw[(a_half * 4 + 2) * GSTRIDE + a_row] = rah.z;
            Aw[(a_half * 4 + 3) * GSTRIDE + a_row] = rah.w;
            __half2 h0 = __floats2half2_rn(rb0.x, rb1.x);
            __half2 h1 = __floats2half2_rn(rb0.y, rb1.y);
            __half2 h2 = __floats2half2_rn(rb0.z, rb1.z);
            __half2 h3 = __floats2half2_rn(rb0.w, rb1.w);
            uint4 hh = make_uint4(*(uint32_t*)&h0, *(uint32_t*)&h1,
                                  *(uint32_t*)&h2, *(uint32_t*)&h3);
            *(uint4*)&Bh[b_k2 * GSTRIDE + b_n0] = hh;
        }
        __syncthreads();
        if (s + 1 < nk) {
            rah = *(const uint4*)(Ap + (s + 1) * 16);
            const float* Bp2 = Bp0 + (size_t)(s + 1) * 16 * HDIM;
            rb0 = *(const float4*)(Bp2);
            rb1 = *(const float4*)(Bp2 + HDIM);
        }
        {
            int g = lane >> 2, q = lane & 3;
            uint32_t bhf[8][2];
#pragma unroll
            for (int nt = 0; nt < 8; nt++) {
                int n = warp_n * 64 + nt * 8 + g;
                bhf[nt][0] = Bh[q * GSTRIDE + n];
                bhf[nt][1] = Bh[(q + 4) * GSTRIDE + n];
            }
#pragma unroll
            for (int mt = 0; mt < 2; mt++) {
                int m = warp_m * 32 + mt * 16 + g;
                uint32_t ahf[4];
                ahf[0] = Aw[q * GSTRIDE + m];
                ahf[1] = Aw[q * GSTRIDE + m + 8];
                ahf[2] = Aw[(q + 4) * GSTRIDE + m];
                ahf[3] = Aw[(q + 4) * GSTRIDE + m + 8];
#pragma unroll
                for (int nt = 0; nt < 8; nt++) {
                    mma_f16(acc[mt][nt], ahf, bhf[nt]);
                }
            }
        }
    }

    int g = lane >> 2;
    int cq = (lane & 3) * 2;
    if (linw2 == nullptr) {
#pragma unroll
        for (int mt = 0; mt < 2; mt++) {
            int row = rowBase + warp_m * 32 + mt * 16 + g;
#pragma unroll
            for (int nt = 0; nt < 8; nt++) {
                int col = colBase + warp_n * 64 + nt * 8 + cq;
                float b0 = bias[col], b1 = bias[col + 1];
                float o0x = fmaxf(acc[mt][nt][0] + b0, 0.f);
                float o0y = fmaxf(acc[mt][nt][1] + b1, 0.f);
                float o1x = fmaxf(acc[mt][nt][2] + b0, 0.f);
                float o1y = fmaxf(acc[mt][nt][3] + b1, 0.f);
                if constexpr (sizeof(TC) == 2) {
                    __half2 p0 = __floats2half2_rn(o0x, o0y);
                    __half2 p1 = __floats2half2_rn(o1x, o1y);
                    *(__half2*)((__half*)C + (size_t)row * HDIM + col) = p0;
                    *(__half2*)((__half*)C + (size_t)(row + 8) * HDIM + col) = p1;
                } else {
                    *(float2*)((float*)C + (size_t)row * HDIM + col) = make_float2(o0x, o0y);
                    *(float2*)((float*)C + (size_t)(row + 8) * HDIM + col) = make_float2(o1x, o1y);
                }
            }
        }
    } else {
        int slot = blockIdx.x * 2 + warp_n;
#pragma unroll
        for (int mt = 0; mt < 2; mt++) {
            float s00 = 0.f, s01 = 0.f;
            float s10 = 0.f, s11 = 0.f;
#pragma unroll
            for (int nt = 0; nt < 8; nt++) {
                int col = colBase + warp_n * 64 + nt * 8 + cq;
                float b0 = bias[col], b1 = bias[col + 1];
                float lw00 = linw2[col * 2],     lw01 = linw2[col * 2 + 1];
                float lw10 = linw2[col * 2 + 2], lw11 = linw2[col * 2 + 3];
                float v0 = fmaxf(acc[mt][nt][0] + b0, 0.f);
                float v1 = fmaxf(acc[mt][nt][1] + b1, 0.f);
                float v2 = fmaxf(acc[mt][nt][2] + b0, 0.f);
                float v3 = fmaxf(acc[mt][nt][3] + b1, 0.f);
                s00 += v0 * lw00 + v1 * lw10;
                s01 += v0 * lw01 + v1 * lw11;
                s10 += v2 * lw00 + v3 * lw10;
                s11 += v2 * lw01 + v3 * lw11;
            }
#pragma unroll
            for (int off = 1; off <= 2; off <<= 1) {
                s00 += __shfl_xor_sync(0xffffffffu, s00, off);
                s01 += __shfl_xor_sync(0xffffffffu, s01, off);
                s10 += __shfl_xor_sync(0xffffffffu, s10, off);
                s11 += __shfl_xor_sync(0xffffffffu, s11, off);
            }
            if ((lane & 3) == 0) {
                int row = rowBase + warp_m * 32 + mt * 16 + g;
                float* p0 = part + ((size_t)slot * MPAD2 + row) * 2;
                p0[0] = s00; p0[1] = s01;
                float* p1 = part + ((size_t)slot * MPAD2 + row + 8) * 2;
                p1[0] = s10; p1[1] = s11;
            }
        }
    }
}

// ---------------- reduce lin partials ----------------
__global__ void k_linred(const float* __restrict__ b, float* __restrict__ o) {
    int i = blockIdx.x * blockDim.x + threadIdx.x;
    if (i >= NTOT) return;
    float a0 = b[0], a1 = b[1];
#pragma unroll
    for (int s = 0; s < 8; s++) {
        a0 += g_part[s][i][0];
        a1 += g_part[s][i][1];
    }
    o[i * 2] = a0;
    o[i * 2 + 1] = a1;
}

// ---------------- fused top-k: dist + histogram + compact + sort -----------
__device__ __forceinline__ float sel_dist(int i) {
    float dx = g_o[i * 2]     - g_o[(i + N_NODES) * 2]     + 1e-6f;
    float dy = g_o[i * 2 + 1] - g_o[(i + N_NODES) * 2 + 1] + 1e-6f;
    return sqrtf(dx * dx + dy * dy);
}
__global__ void k_select() {
    __shared__ int hist[2048];
    __shared__ float sel[SELN];
    __shared__ int cnt;
    __shared__ int thr;
    int t = threadIdx.x;  // 1024
    hist[t] = 0; hist[t + 1024] = 0;
    if (t == 0) cnt = 0;
    __syncthreads();
    // pass 1: histogram of top-11-bits
    for (int i = t; i < N_NODES; i += 1024) {
        float d = sel_dist(i);
        atomicAdd(&hist[__float_as_uint(d) >> 21], 1);
    }
    __syncthreads();
    if (t == 0) {
        int cum = 0, b;
        for (b = 2047; b >= 0; b--) {
            cum += hist[b];
            if (cum >= TOPK) break;
        }
        thr = b;
    }
    for (int i = t; i < SELN; i += 1024) sel[i] = -INFINITY;
    __syncthreads();
    // pass 2: compact (recompute dist — deterministic identical values)
    int thrb = thr;
    for (int i = t; i < N_NODES; i += 1024) {
        float d = sel_dist(i);
        if ((int)(__float_as_uint(d) >> 21) >= thrb) {
            int pos = atomicAdd(&cnt, 1);
            if (pos < SELN) sel[pos] = d;
        }
    }
    __syncthreads();
    // bitonic sort 4096 descending
    for (int k = 2; k <= SELN; k <<= 1) {
        for (int j = k >> 1; j > 0; j >>= 1) {
            for (int i = t; i < SELN; i += 1024) {
                int ixj = i ^ j;
                if (ixj > i) {
                    bool dsc = (i & k) == 0;
                    float a = sel[i], c = sel[ixj];
                    bool sw = dsc ? (a < c) : (a > c);
                    if (sw) { sel[i] = c; sel[ixj] = a; }
                }
            }
            __syncthreads();
        }
    }
    if (t < TOPK) g_top[t] = sel[t];
}

// ---------------- head MLP ----------------
__global__ void k_mlp(const float* __restrict__ fc1w, const float* __restrict__ fc1b,
                      const float* __restrict__ ln1g, const float* __restrict__ ln1b,
                      const float* __restrict__ fc2w, const float* __restrict__ fc2b,
                      const float* __restrict__ ln2g, const float* __restrict__ ln2b,
                      const float* __restrict__ fc3w, const float* __restrict__ fc3b,
                      float* __restrict__ out) {
    __shared__ float vals[TOPK];
    __shared__ float h1[128];
    __shared__ float part[4][128];
    __shared__ float h2[512];
    __shared__ float red[512];
    int t = threadIdx.x;
    for (int i = t; i < TOPK; i += 512) vals[i] = g_top[i];
    __syncthreads();
    {
        int j = t & 127, c = t >> 7;
        float acc = 0.f;
        for (int i = c * 250; i < (c + 1) * 250; i++) acc += vals[i] * fc1w[i * 128 + j];
        part[c][j] = acc;
    }
    __syncthreads();
    if (t < 128) h1[t] = part[0][t] + part[1][t] + part[2][t] + part[3][t] + fc1b[t];
    __syncthreads();
    red[t] = (t < 128) ? h1[t] : 0.f;
    __syncthreads();
    for (int off = 256; off; off >>= 1) { if (t < off) red[t] += red[t + off]; __syncthreads(); }
    float mean1 = red[0] / 128.f;
    __syncthreads();
    red[t] = (t < 128) ? (h1[t] - mean1) * (h1[t] - mean1) : 0.f;
    __syncthreads();
    for (int off = 256; off; off >>= 1) { if (t < off) red[t] += red[t + off]; __syncthreads(); }
    float var1 = red[0] / 128.f;
    __syncthreads();
    if (t < 128) {
        float v = (h1[t] - mean1) * rsqrtf(var1 + 1e-5f) * ln1g[t] + ln1b[t];
        h1[t] = fmaxf(v, 0.f);
    }
    __syncthreads();
    {
        float acc = fc2b[t];
        for (int i = 0; i < 128; i++) acc += h1[i] * fc2w[i * 512 + t];
        h2[t] = acc;
    }
    __syncthreads();
    red[t] = h2[t];
    __syncthreads();
    for (int off = 256; off; off >>= 1) { if (t < off) red[t] += red[t + off]; __syncthreads(); }
    float mean2 = red[0] / 512.f;
    __syncthreads();
    red[t] = (h2[t] - mean2) * (h2[t] - mean2);
    __syncthreads();
    for (int off = 256; off; off >>= 1) { if (t < off) red[t] += red[t + off]; __syncthreads(); }
    float var2 = red[0] / 512.f;
    __syncthreads();
    float hr = fmaxf((h2[t] - mean2) * rsqrtf(var2 + 1e-5f) * ln2g[t] + ln2b[t], 0.f);
    red[t] = hr * fc3w[t];
    __syncthreads();
    for (int off = 256; off; off >>= 1) { if (t < off) red[t] += red[t + off]; __syncthreads(); }
    if (t == 0) out[0] = 1.f / (1.f + expf(-(red[0] + fc3b[0])));
}

// ---------------- launch ----------------
extern "C" void kernel_launch(void* const* d_in, const int* in_sizes, int n_in,
                              void* d_out, int out_size) {
    const float* x1   = (const float*)d_in[0];
    const int*   ei1  = (const int*)d_in[1];
    const float* x2   = (const float*)d_in[2];
    const int*   ei2  = (const int*)d_in[3];
    const float* w11  = (const float*)d_in[4];
    const float* b11  = (const float*)d_in[5];
    const float* w12  = (const float*)d_in[6];
    const float* b12  = (const float*)d_in[7];
    const float* w21  = (const float*)d_in[8];
    const float* b21  = (const float*)d_in[9];
    const float* w22  = (const float*)d_in[10];
    const float* b22  = (const float*)d_in[11];
    const float* w31  = (const float*)d_in[12];
    const float* b31  = (const float*)d_in[13];
    const float* w32  = (const float*)d_in[14];
    const float* b32  = (const float*)d_in[15];
    const float* linw = (const float*)d_in[16];
    const float* linb = (const float*)d_in[17];
    const float* fc1w = (const float*)d_in[18];
    const float* fc1b = (const float*)d_in[19];
    const float* ln1g = (const float*)d_in[20];
    const float* ln1b = (const float*)d_in[21];
    const float* fc2w = (const float*)d_in[22];
    const float* fc2b = (const float*)d_in[23];
    const float* ln2g = (const float*)d_in[24];
    const float* ln2b = (const float*)d_in[25];
    const float* fc3w = (const float*)d_in[26];
    const float* fc3b = (const float*)d_in[27];
    float* out = (float*)d_out;

    const int* src1 = ei1;
    const int* dst1 = ei1 + N_EDGES;
    const int* src2 = ei2;
    const int* dst2 = ei2 + N_EDGES;

    __half *p_xh, *p_aggh, *p_acth, *p_tmph;
    float *p_o, *p_part;
    cudaGetSymbolAddress((void**)&p_xh, g_xh);
    cudaGetSymbolAddress((void**)&p_aggh, g_aggh);
    cudaGetSymbolAddress((void**)&p_acth, g_acth);
    cudaGetSymbolAddress((void**)&p_tmph, g_tmph);
    cudaGetSymbolAddress((void**)&p_o, g_o);
    cudaGetSymbolAddress((void**)&p_part, g_part);

    dim3 ggrid(HDIM / 128, MT2);
    const int E2B = (2 * N_EDGES + 255) / 256;
    const int N2B = (NTOT + 255) / 256;
    const int AGB512 = (NTOT + 7) / 8;
    const int AGB256 = (NTOT + 15) / 16;
    const int XCB = (NTOT * (FIN_DIM / 4) + 255) / 256;

    // batched CSR for both graphs
    k_zero_cnt<<<N2B, 256>>>();
    k_hist2<<<E2B, 256>>>(dst1, dst2);
    k_scan2<<<2, 1024>>>();
    k_fill2<<<E2B, 256>>>(src1, dst1, src2, dst2);

    // convert inputs to fp16
    k_x2h<<<XCB, 256>>>(x1, x2, p_xh);

    // layer 1 (FIN=256 -> H)
    k_aggh<FIN_DIM><<<AGB256, 512>>>(p_xh, p_aggh);
    k_gemm_mma<__half><<<ggrid, 256>>>(p_aggh, w11, b11, p_tmph, FIN_DIM, nullptr, nullptr);
    k_gemm_mma<__half><<<ggrid, 256>>>(p_tmph, w12, b12, p_acth, HDIM, nullptr, nullptr);
    // layer 2
    k_aggh<HDIM><<<AGB512, 512>>>(p_acth, p_aggh);
    k_gemm_mma<__half><<<ggrid, 256>>>(p_aggh, w21, b21, p_tmph, HDIM, nullptr, nullptr);
    k_gemm_mma<__half><<<ggrid, 256>>>(p_tmph, w22, b22, p_acth, HDIM, nullptr, nullptr);
    // layer 3
    k_aggh<HDIM><<<AGB512, 512>>>(p_acth, p_aggh);
    k_gemm_mma<__half><<<ggrid, 256>>>(p_aggh, w31, b31, p_tmph, HDIM, nullptr, nullptr);
    // last GEMM: fused final linear
    k_gemm_mma<float><<<ggrid, 256>>>(p_tmph, w32, b32, (float*)nullptr, HDIM, linw, p_part);
    k_linred<<<N2B, 256>>>(linb, p_o);

    // fused dist + select + sort, then head MLP
    k_select<<<1, 1024>>>();
    k_mlp<<<1, 512>>>(fc1w, fc1b, ln1g, ln1b, fc2w, fc2b, ln2g, ln2b, fc3w, fc3b, out);
}

// round 16
// speedup vs baseline: 2.2071x; 1.0167x over previous
#include <cuda_runtime.h>
#include <cuda_fp16.h>
#include <math.h>
#include <stdint.h>

#define N_NODES 20000
#define NTOT    40000
#define MPAD2   40192
#define MT2     314
#define N_EDGES 640000
#define FIN_DIM 256
#define HDIM 512
#define TOPK 1000
#define SELN 4096
#define WSLOT 131072        // 256 k2-rows x 512 n words per weight slot

// ---------------- scratch (static device memory; no allocations) ----------------
__device__ __half   g_xh[(size_t)NTOT * FIN_DIM];
__device__ __half   g_aggh[(size_t)MPAD2 * HDIM];
__device__ __half   g_acth[(size_t)MPAD2 * HDIM];
__device__ __half   g_tmph[(size_t)MPAD2 * HDIM];
__device__ uint32_t g_wh[6 * WSLOT];          // packed fp16 k-pair weights
__device__ float    g_part[8][MPAD2][2];
__device__ float    g_o[NTOT * 2];
__device__ float    g_top[TOPK];
__device__ int      g_cnt[NTOT];
__device__ int      g_rowptr[2 * (N_NODES + 1)];
__device__ int      g_cursor[NTOT];
__device__ int      g_esrc[2 * N_EDGES];

// ---------------- helpers ----------------
__device__ __forceinline__ void mma_f16(float* c, const uint32_t* a, const uint32_t* b) {
    asm volatile(
        "mma.sync.aligned.m16n8k16.row.col.f32.f16.f16.f32 "
        "{%0,%1,%2,%3}, {%4,%5,%6,%7}, {%8,%9}, {%0,%1,%2,%3};"
        : "+f"(c[0]), "+f"(c[1]), "+f"(c[2]), "+f"(c[3])
        : "r"(a[0]), "r"(a[1]), "r"(a[2]), "r"(a[3]), "r"(b[0]), "r"(b[1]));
}

// ---------------- weight pre-pack: fp32 [K][512] -> half2 k-pair words ------
__global__ void k_w2h(const float* __restrict__ w11, const float* __restrict__ w12,
                      const float* __restrict__ w21, const float* __restrict__ w22,
                      const float* __restrict__ w31, const float* __restrict__ w32) {
    const int S0 = (FIN_DIM / 2) * HDIM;      // 65536 words for w11
    const int SN = (HDIM / 2) * HDIM;         // 131072 words for the rest
    int i = blockIdx.x * blockDim.x + threadIdx.x;
    int slot, local;
    if (i < S0) { slot = 0; local = i; }
    else {
        int j = i - S0;
        slot = 1 + j / SN;
        if (slot > 5) return;
        local = j - (slot - 1) * SN;
    }
    const float* W;
    switch (slot) {
        case 0: W = w11; break;
        case 1: W = w12; break;
        case 2: W = w21; break;
        case 3: W = w22; break;
        case 4: W = w31; break;
        default: W = w32; break;
    }
    int k2 = local / HDIM;
    int n = local - k2 * HDIM;
    __half2 h = __floats2half2_rn(W[(size_t)(2 * k2) * HDIM + n],
                                  W[(size_t)(2 * k2 + 1) * HDIM + n]);
    g_wh[slot * WSLOT + local] = *(uint32_t*)&h;
}

// ---------------- CSR build (both graphs, batched) ----------------
__global__ void k_zero_cnt() {
    int i = blockIdx.x * blockDim.x + threadIdx.x;
    if (i < NTOT) g_cnt[i] = 0;
}
__global__ void k_hist2(const int* __restrict__ dst1, const int* __restrict__ dst2) {
    int e = blockIdx.x * blockDim.x + threadIdx.x;
    if (e >= 2 * N_EDGES) return;
    int gph = e >= N_EDGES;
    int le = e - gph * N_EDGES;
    int d = (gph ? dst2 : dst1)[le];
    atomicAdd(&g_cnt[gph * N_NODES + d], 1);
}
__global__ void k_scan2() {
    const int PER = 20;
    int gph = blockIdx.x;
    int t = threadIdx.x, lane = t & 31, wid = t >> 5;
    const int cbase = gph * N_NODES;
    const int rbase = gph * (N_NODES + 1);
    int base = t * PER;
    int v[PER];
    int sum = 0;
#pragma unroll
    for (int i = 0; i < PER; i++) {
        int idx = base + i;
        v[i] = (idx < N_NODES) ? g_cnt[cbase + idx] : 0;
        sum += v[i];
    }
    int s = sum;
#pragma unroll
    for (int off = 1; off < 32; off <<= 1) {
        int n = __shfl_up_sync(0xffffffffu, s, off);
        if (lane >= off) s += n;
    }
    __shared__ int wsum[32];
    if (lane == 31) wsum[wid] = s;
    __syncthreads();
    if (wid == 0) {
        int ws = wsum[lane];
#pragma unroll
        for (int off = 1; off < 32; off <<= 1) {
            int n = __shfl_up_sync(0xffffffffu, ws, off);
            if (lane >= off) ws += n;
        }
        wsum[lane] = ws;
    }
    __syncthreads();
    int excl = s - sum + (wid > 0 ? wsum[wid - 1] : 0);
    int run = excl;
#pragma unroll
    for (int i = 0; i < PER; i++) {
        int idx = base + i;
        if (idx < N_NODES) {
            g_rowptr[rbase + idx] = run;
            g_cursor[cbase + idx] = run;
        }
        run += v[i];
    }
    if (t == 1023) g_rowptr[rbase + N_NODES] = run;
}
__global__ void k_fill2(const int* __restrict__ src1, const int* __restrict__ dst1,
                        const int* __restrict__ src2, const int* __restrict__ dst2) {
    int e = blockIdx.x * blockDim.x + threadIdx.x;
    if (e >= 2 * N_EDGES) return;
    int gph = e >= N_EDGES;
    int le = e - gph * N_EDGES;
    int d = (gph ? dst2 : dst1)[le];
    int sv = (gph ? src2 : src1)[le];
    int pos = atomicAdd(&g_cursor[gph * N_NODES + d], 1);
    g_esrc[gph * N_EDGES + pos] = sv;
}

// ---------------- input conversion: fp32 x1|x2 -> fp16 g_xh ----------------
__global__ void k_x2h(const float* __restrict__ xa, const float* __restrict__ xb,
                      __half* __restrict__ out) {
    int n = blockIdx.x * blockDim.x + threadIdx.x;
    if (n >= NTOT * (FIN_DIM / 4)) return;
    int gph = n >= N_NODES * (FIN_DIM / 4);
    int local = n - gph * N_NODES * (FIN_DIM / 4);
    float4 v = ((const float4*)(gph ? xb : xa))[local];
    __half2 h0 = __floats2half2_rn(v.x, v.y);
    __half2 h1 = __floats2half2_rn(v.z, v.w);
    ((uint2*)out)[n] = make_uint2(*(uint32_t*)&h0, *(uint32_t*)&h1);
}

// ---------------- aggregation (fp16 in, fp16 out), templated on F ----------
template <int F>
__global__ void k_aggh(const __half* __restrict__ x, __half* __restrict__ out) {
    const int TPN = F / 8;
    const int NPB = 512 / TPN;
    int t = threadIdx.x;
    int node = blockIdx.x * NPB + t / TPN;
    int tf = t % TPN;
    if (node >= NTOT) return;
    int gph = node >= N_NODES;
    int local = node - gph * N_NODES;
    const uint4* x4 = (const uint4*)x;
    float acc[8];
    {
        uint4 v = x4[(size_t)node * TPN + tf];
        float2 f0 = __half22float2(*(__half2*)&v.x);
        float2 f1 = __half22float2(*(__half2*)&v.y);
        float2 f2 = __half22float2(*(__half2*)&v.z);
        float2 f3 = __half22float2(*(__half2*)&v.w);
        acc[0] = f0.x; acc[1] = f0.y; acc[2] = f1.x; acc[3] = f1.y;
        acc[4] = f2.x; acc[5] = f2.y; acc[6] = f3.x; acc[7] = f3.y;
    }
    int beg = g_rowptr[gph * (N_NODES + 1) + local];
    int end = g_rowptr[gph * (N_NODES + 1) + local + 1];
    const int* ep = g_esrc + gph * N_EDGES;
    const size_t gofs = (size_t)gph * N_NODES * TPN;
    int e = beg;
    for (; e + 1 < end; e += 2) {
        int i0 = __ldg(&ep[e]);
        int i1 = __ldg(&ep[e + 1]);
        uint4 v0 = x4[gofs + (size_t)i0 * TPN + tf];
        uint4 v1 = x4[gofs + (size_t)i1 * TPN + tf];
        float2 a0 = __half22float2(*(__half2*)&v0.x), b0 = __half22float2(*(__half2*)&v1.x);
        float2 a1 = __half22float2(*(__half2*)&v0.y), b1 = __half22float2(*(__half2*)&v1.y);
        float2 a2 = __half22float2(*(__half2*)&v0.z), b2 = __half22float2(*(__half2*)&v1.z);
        float2 a3 = __half22float2(*(__half2*)&v0.w), b3 = __half22float2(*(__half2*)&v1.w);
        acc[0] += a0.x + b0.x; acc[1] += a0.y + b0.y;
        acc[2] += a1.x + b1.x; acc[3] += a1.y + b1.y;
        acc[4] += a2.x + b2.x; acc[5] += a2.y + b2.y;
        acc[6] += a3.x + b3.x; acc[7] += a3.y + b3.y;
    }
    if (e < end) {
        int i0 = __ldg(&ep[e]);
        uint4 v0 = x4[gofs + (size_t)i0 * TPN + tf];
        float2 a0 = __half22float2(*(__half2*)&v0.x);
        float2 a1 = __half22float2(*(__half2*)&v0.y);
        float2 a2 = __half22float2(*(__half2*)&v0.z);
        float2 a3 = __half22float2(*(__half2*)&v0.w);
        acc[0] += a0.x; acc[1] += a0.y; acc[2] += a1.x; acc[3] += a1.y;
        acc[4] += a2.x; acc[5] += a2.y; acc[6] += a3.x; acc[7] += a3.y;
    }
    __half2 h0 = __floats2half2_rn(acc[0], acc[1]);
    __half2 h1 = __floats2half2_rn(acc[2], acc[3]);
    __half2 h2 = __floats2half2_rn(acc[4], acc[5]);
    __half2 h3 = __floats2half2_rn(acc[6], acc[7]);
    uint4 u = make_uint4(*(uint32_t*)&h0, *(uint32_t*)&h1,
                         *(uint32_t*)&h2, *(uint32_t*)&h3);
    ((uint4*)out)[(size_t)node * TPN + tf] = u;
}

// ---------------- single-pass fp16 mma.sync GEMM with pre-packed W ---------
// A fp16; W2 = packed half2 k-pair words [k2][512]. Producer phase: raw copies.
#define GSTRIDE 140
#define GMATW   (8 * GSTRIDE)

template <typename TC>
__global__ void __launch_bounds__(256)
k_gemm_mma(const __half* __restrict__ A, const uint32_t* __restrict__ W2,
           const float* __restrict__ bias, TC* __restrict__ C, int K,
           const float* __restrict__ linw2, float* __restrict__ part) {
    __shared__ uint32_t S[2][2][GMATW];
    int t = threadIdx.x, lane = t & 31, wid = t >> 5;
    int warp_m = wid >> 1, warp_n = wid & 1;
    int rowBase = blockIdx.y * 128;
    int colBase = blockIdx.x * 128;

    float acc[2][8][4];
#pragma unroll
    for (int i = 0; i < 2; i++)
#pragma unroll
        for (int j = 0; j < 8; j++)
#pragma unroll
            for (int q = 0; q < 4; q++) acc[i][j][q] = 0.f;

    int a_row = t >> 1;
    int a_half = t & 1;
    int b_k2 = t >> 5;
    int b_n0 = lane * 4;

    const __half* Ap = A + (size_t)(rowBase + a_row) * K + a_half * 8;
    const uint32_t* Bp = W2 + (size_t)b_k2 * HDIM + colBase + b_n0;

    const int nk = K >> 4;
    uint4 rah, rbw;

    rah = *(const uint4*)(Ap);
    rbw = *(const uint4*)(Bp);

    for (int s = 0; s < nk; s++) {
        int buf = s & 1;
        uint32_t* Aw = S[buf][0];
        uint32_t* Bh = S[buf][1];
        {
            Aw[(a_half * 4 + 0) * GSTRIDE + a_row] = rah.x;
            Aw[(a_half * 4 + 1) * GSTRIDE + a_row] = rah.y;
            Aw[(a_half * 4 + 2) * GSTRIDE + a_row] = rah.z;
            Aw[(a_half * 4 + 3) * GSTRIDE + a_row] = rah.w;
            *(uint4*)&Bh[b_k2 * GSTRIDE + b_n0] = rbw;
        }
        __syncthreads();   // single barrier per stage (double buffering)
        if (s + 1 < nk) {
            rah = *(const uint4*)(Ap + (s + 1) * 16);
            rbw = *(const uint4*)(Bp + (size_t)(s + 1) * 8 * HDIM);
        }
        {
            int g = lane >> 2, q = lane & 3;
            uint32_t bhf[8][2];
#pragma unroll
            for (int nt = 0; nt < 8; nt++) {
                int n = warp_n * 64 + nt * 8 + g;
                bhf[nt][0] = Bh[q * GSTRIDE + n];
                bhf[nt][1] = Bh[(q + 4) * GSTRIDE + n];
            }
#pragma unroll
            for (int mt = 0; mt < 2; mt++) {
                int m = warp_m * 32 + mt * 16 + g;
                uint32_t ahf[4];
                ahf[0] = Aw[q * GSTRIDE + m];
                ahf[1] = Aw[q * GSTRIDE + m + 8];
                ahf[2] = Aw[(q + 4) * GSTRIDE + m];
                ahf[3] = Aw[(q + 4) * GSTRIDE + m + 8];
#pragma unroll
                for (int nt = 0; nt < 8; nt++) {
                    mma_f16(acc[mt][nt], ahf, bhf[nt]);
                }
            }
        }
    }

    int g = lane >> 2;
    int cq = (lane & 3) * 2;
    if (linw2 == nullptr) {
#pragma unroll
        for (int mt = 0; mt < 2; mt++) {
            int row = rowBase + warp_m * 32 + mt * 16 + g;
#pragma unroll
            for (int nt = 0; nt < 8; nt++) {
                int col = colBase + warp_n * 64 + nt * 8 + cq;
                float b0 = bias[col], b1 = bias[col + 1];
                float o0x = fmaxf(acc[mt][nt][0] + b0, 0.f);
                float o0y = fmaxf(acc[mt][nt][1] + b1, 0.f);
                float o1x = fmaxf(acc[mt][nt][2] + b0, 0.f);
                float o1y = fmaxf(acc[mt][nt][3] + b1, 0.f);
                if constexpr (sizeof(TC) == 2) {
                    __half2 p0 = __floats2half2_rn(o0x, o0y);
                    __half2 p1 = __floats2half2_rn(o1x, o1y);
                    *(__half2*)((__half*)C + (size_t)row * HDIM + col) = p0;
                    *(__half2*)((__half*)C + (size_t)(row + 8) * HDIM + col) = p1;
                } else {
                    *(float2*)((float*)C + (size_t)row * HDIM + col) = make_float2(o0x, o0y);
                    *(float2*)((float*)C + (size_t)(row + 8) * HDIM + col) = make_float2(o1x, o1y);
                }
            }
        }
    } else {
        int slot = blockIdx.x * 2 + warp_n;
#pragma unroll
        for (int mt = 0; mt < 2; mt++) {
            float s00 = 0.f, s01 = 0.f;
            float s10 = 0.f, s11 = 0.f;
#pragma unroll
            for (int nt = 0; nt < 8; nt++) {
                int col = colBase + warp_n * 64 + nt * 8 + cq;
                float b0 = bias[col], b1 = bias[col + 1];
                float lw00 = linw2[col * 2],     lw01 = linw2[col * 2 + 1];
                float lw10 = linw2[col * 2 + 2], lw11 = linw2[col * 2 + 3];
                float v0 = fmaxf(acc[mt][nt][0] + b0, 0.f);
                float v1 = fmaxf(acc[mt][nt][1] + b1, 0.f);
                float v2 = fmaxf(acc[mt][nt][2] + b0, 0.f);
                float v3 = fmaxf(acc[mt][nt][3] + b1, 0.f);
                s00 += v0 * lw00 + v1 * lw10;
                s01 += v0 * lw01 + v1 * lw11;
                s10 += v2 * lw00 + v3 * lw10;
                s11 += v2 * lw01 + v3 * lw11;
            }
#pragma unroll
            for (int off = 1; off <= 2; off <<= 1) {
                s00 += __shfl_xor_sync(0xffffffffu, s00, off);
                s01 += __shfl_xor_sync(0xffffffffu, s01, off);
                s10 += __shfl_xor_sync(0xffffffffu, s10, off);
                s11 += __shfl_xor_sync(0xffffffffu, s11, off);
            }
            if ((lane & 3) == 0) {
                int row = rowBase + warp_m * 32 + mt * 16 + g;
                float* p0 = part + ((size_t)slot * MPAD2 + row) * 2;
                p0[0] = s00; p0[1] = s01;
                float* p1 = part + ((size_t)slot * MPAD2 + row + 8) * 2;
                p1[0] = s10; p1[1] = s11;
            }
        }
    }
}

// ---------------- reduce lin partials ----------------
__global__ void k_linred(const float* __restrict__ b, float* __restrict__ o) {
    int i = blockIdx.x * blockDim.x + threadIdx.x;
    if (i >= NTOT) return;
    float a0 = b[0], a1 = b[1];
#pragma unroll
    for (int s = 0; s < 8; s++) {
        a0 += g_part[s][i][0];
        a1 += g_part[s][i][1];
    }
    o[i * 2] = a0;
    o[i * 2 + 1] = a1;
}

// ---------------- fused top-k: dist + histogram + compact + sort -----------
__device__ __forceinline__ float sel_dist(int i) {
    float dx = g_o[i * 2]     - g_o[(i + N_NODES) * 2]     + 1e-6f;
    float dy = g_o[i * 2 + 1] - g_o[(i + N_NODES) * 2 + 1] + 1e-6f;
    return sqrtf(dx * dx + dy * dy);
}
__global__ void k_select() {
    __shared__ int hist[2048];
    __shared__ float sel[SELN];
    __shared__ int cnt;
    __shared__ int thr;
    int t = threadIdx.x;
    hist[t] = 0; hist[t + 1024] = 0;
    if (t == 0) cnt = 0;
    __syncthreads();
    for (int i = t; i < N_NODES; i += 1024) {
        float d = sel_dist(i);
        atomicAdd(&hist[__float_as_uint(d) >> 21], 1);
    }
    __syncthreads();
    if (t == 0) {
        int cum = 0, b;
        for (b = 2047; b >= 0; b--) {
            cum += hist[b];
            if (cum >= TOPK) break;
        }
        thr = b;
    }
    for (int i = t; i < SELN; i += 1024) sel[i] = -INFINITY;
    __syncthreads();
    int thrb = thr;
    for (int i = t; i < N_NODES; i += 1024) {
        float d = sel_dist(i);
        if ((int)(__float_as_uint(d) >> 21) >= thrb) {
            int pos = atomicAdd(&cnt, 1);
            if (pos < SELN) sel[pos] = d;
        }
    }
    __syncthreads();
    for (int k = 2; k <= SELN; k <<= 1) {
        for (int j = k >> 1; j > 0; j >>= 1) {
            for (int i = t; i < SELN; i += 1024) {
                int ixj = i ^ j;
                if (ixj > i) {
                    bool dsc = (i & k) == 0;
                    float a = sel[i], c = sel[ixj];
                    bool sw = dsc ? (a < c) : (a > c);
                    if (sw) { sel[i] = c; sel[ixj] = a; }
                }
            }
            __syncthreads();
        }
    }
    if (t < TOPK) g_top[t] = sel[t];
}

// ---------------- head MLP ----------------
__global__ void k_mlp(const float* __restrict__ fc1w, const float* __restrict__ fc1b,
                      const float* __restrict__ ln1g, const float* __restrict__ ln1b,
                      const float* __restrict__ fc2w, const float* __restrict__ fc2b,
                      const float* __restrict__ ln2g, const float* __restrict__ ln2b,
                      const float* __restrict__ fc3w, const float* __restrict__ fc3b,
                      float* __restrict__ out) {
    __shared__ float vals[TOPK];
    __shared__ float h1[128];
    __shared__ float part[4][128];
    __shared__ float h2[512];
    __shared__ float red[512];
    int t = threadIdx.x;
    for (int i = t; i < TOPK; i += 512) vals[i] = g_top[i];
    __syncthreads();
    {
        int j = t & 127, c = t >> 7;
        float acc = 0.f;
        for (int i = c * 250; i < (c + 1) * 250; i++) acc += vals[i] * fc1w[i * 128 + j];
        part[c][j] = acc;
    }
    __syncthreads();
    if (t < 128) h1[t] = part[0][t] + part[1][t] + part[2][t] + part[3][t] + fc1b[t];
    __syncthreads();
    red[t] = (t < 128) ? h1[t] : 0.f;
    __syncthreads();
    for (int off = 256; off; off >>= 1) { if (t < off) red[t] += red[t + off]; __syncthreads(); }
    float mean1 = red[0] / 128.f;
    __syncthreads();
    red[t] = (t < 128) ? (h1[t] - mean1) * (h1[t] - mean1) : 0.f;
    __syncthreads();
    for (int off = 256; off; off >>= 1) { if (t < off) red[t] += red[t + off]; __syncthreads(); }
    float var1 = red[0] / 128.f;
    __syncthreads();
    if (t < 128) {
        float v = (h1[t] - mean1) * rsqrtf(var1 + 1e-5f) * ln1g[t] + ln1b[t];
        h1[t] = fmaxf(v, 0.f);
    }
    __syncthreads();
    {
        float acc = fc2b[t];
        for (int i = 0; i < 128; i++) acc += h1[i] * fc2w[i * 512 + t];
        h2[t] = acc;
    }
    __syncthreads();
    red[t] = h2[t];
    __syncthreads();
    for (int off = 256; off; off >>= 1) { if (t < off) red[t] += red[t + off]; __syncthreads(); }
    float mean2 = red[0] / 512.f;
    __syncthreads();
    red[t] = (h2[t] - mean2) * (h2[t] - mean2);
    __syncthreads();
    for (int off = 256; off; off >>= 1) { if (t < off) red[t] += red[t + off]; __syncthreads(); }
    float var2 = red[0] / 512.f;
    __syncthreads();
    float hr = fmaxf((h2[t] - mean2) * rsqrtf(var2 + 1e-5f) * ln2g[t] + ln2b[t], 0.f);
    red[t] = hr * fc3w[t];
    __syncthreads();
    for (int off = 256; off; off >>= 1) { if (t < off) red[t] += red[t + off]; __syncthreads(); }
    if (t == 0) out[0] = 1.f / (1.f + expf(-(red[0] + fc3b[0])));
}

// ---------------- launch ----------------
extern "C" void kernel_launch(void* const* d_in, const int* in_sizes, int n_in,
                              void* d_out, int out_size) {
    const float* x1   = (const float*)d_in[0];
    const int*   ei1  = (const int*)d_in[1];
    const float* x2   = (const float*)d_in[2];
    const int*   ei2  = (const int*)d_in[3];
    const float* w11  = (const float*)d_in[4];
    const float* b11  = (const float*)d_in[5];
    const float* w12  = (const float*)d_in[6];
    const float* b12  = (const float*)d_in[7];
    const float* w21  = (const float*)d_in[8];
    const float* b21  = (const float*)d_in[9];
    const float* w22  = (const float*)d_in[10];
    const float* b22  = (const float*)d_in[11];
    const float* w31  = (const float*)d_in[12];
    const float* b31  = (const float*)d_in[13];
    const float* w32  = (const float*)d_in[14];
    const float* b32  = (const float*)d_in[15];
    const float* linw = (const float*)d_in[16];
    const float* linb = (const float*)d_in[17];
    const float* fc1w = (const float*)d_in[18];
    const float* fc1b = (const float*)d_in[19];
    const float* ln1g = (const float*)d_in[20];
    const float* ln1b = (const float*)d_in[21];
    const float* fc2w = (const float*)d_in[22];
    const float* fc2b = (const float*)d_in[23];
    const float* ln2g = (const float*)d_in[24];
    const float* ln2b = (const float*)d_in[25];
    const float* fc3w = (const float*)d_in[26];
    const float* fc3b = (const float*)d_in[27];
    float* out = (float*)d_out;

    const int* src1 = ei1;
    const int* dst1 = ei1 + N_EDGES;
    const int* src2 = ei2;
    const int* dst2 = ei2 + N_EDGES;

    __half *p_xh, *p_aggh, *p_acth, *p_tmph;
    uint32_t* p_wh;
    float *p_o, *p_part;
    cudaGetSymbolAddress((void**)&p_xh, g_xh);
    cudaGetSymbolAddress((void**)&p_aggh, g_aggh);
    cudaGetSymbolAddress((void**)&p_acth, g_acth);
    cudaGetSymbolAddress((void**)&p_tmph, g_tmph);
    cudaGetSymbolAddress((void**)&p_wh, g_wh);
    cudaGetSymbolAddress((void**)&p_o, g_o);
    cudaGetSymbolAddress((void**)&p_part, g_part);

    dim3 ggrid(HDIM / 128, MT2);
    const int E2B = (2 * N_EDGES + 255) / 256;
    const int N2B = (NTOT + 255) / 256;
    const int AGB512 = (NTOT + 7) / 8;
    const int AGB256 = (NTOT + 15) / 16;
    const int XCB = (NTOT * (FIN_DIM / 4) + 255) / 256;
    const int WPB = ((FIN_DIM / 2 + 5 * (HDIM / 2)) * HDIM + 255) / 256;

    // batched CSR for both graphs
    k_zero_cnt<<<N2B, 256>>>();
    k_hist2<<<E2B, 256>>>(dst1, dst2);
    k_scan2<<<2, 1024>>>();
    k_fill2<<<E2B, 256>>>(src1, dst1, src2, dst2);

    // one-time conversions (independent of CSR build)
    k_x2h<<<XCB, 256>>>(x1, x2, p_xh);
    k_w2h<<<WPB, 256>>>(w11, w12, w21, w22, w31, w32);

    // layer 1 (FIN=256 -> H)
    k_aggh<FIN_DIM><<<AGB256, 512>>>(p_xh, p_aggh);
    k_gemm_mma<__half><<<ggrid, 256>>>(p_aggh, p_wh + 0 * WSLOT, b11, p_tmph, FIN_DIM, nullptr, nullptr);
    k_gemm_mma<__half><<<ggrid, 256>>>(p_tmph, p_wh + 1 * WSLOT, b12, p_acth, HDIM, nullptr, nullptr);
    // layer 2
    k_aggh<HDIM><<<AGB512, 512>>>(p_acth, p_aggh);
    k_gemm_mma<__half><<<ggrid, 256>>>(p_aggh, p_wh + 2 * WSLOT, b21, p_tmph, HDIM, nullptr, nullptr);
    k_gemm_mma<__half><<<ggrid, 256>>>(p_tmph, p_wh + 3 * WSLOT, b22, p_acth, HDIM, nullptr, nullptr);
    // layer 3
    k_aggh<HDIM><<<AGB512, 512>>>(p_acth, p_aggh);
    k_gemm_mma<__half><<<ggrid, 256>>>(p_aggh, p_wh + 4 * WSLOT, b31, p_tmph, HDIM, nullptr, nullptr);
    // last GEMM: fused final linear
    k_gemm_mma<float><<<ggrid, 256>>>(p_tmph, p_wh + 5 * WSLOT, b32, (float*)nullptr, HDIM, linw, p_part);
    k_linred<<<N2B, 256>>>(linb, p_o);

    // fused dist + select + sort, then head MLP
    k_select<<<1, 1024>>>();
    k_mlp<<<1, 512>>>(fc1w, fc1b, ln1g, ln1b, fc2w, fc2b, ln2g, ln2b, fc3w, fc3b, out);
}